// round 2
// baseline (speedup 1.0000x reference)
#include <cuda_runtime.h>
#include <math.h>

// Problem constants
// B=2, S=4096, H=2048, NH=32, NKV=8, HD=64, BL=256, nb=16, rep=4
// M = B*S = 8192 rows

#define M_ROWS 8192
#define S_LEN  4096

// Scratch (static __device__ arrays; no allocation allowed)
__device__ float g_q[(size_t)M_ROWS * 2048];   // Q after proj (+RoPE)   64 MB
__device__ float g_k[(size_t)M_ROWS * 512];    // K after proj (+RoPE)   16 MB
__device__ float g_v[(size_t)M_ROWS * 512];    // V after proj           16 MB
__device__ float g_att[(size_t)M_ROWS * 2048]; // attention out pre-Wo   64 MB

// ---------------------------------------------------------------------------
// Warp reductions
// ---------------------------------------------------------------------------
__device__ __forceinline__ float warp_max32(float v) {
#pragma unroll
    for (int o = 16; o > 0; o >>= 1) v = fmaxf(v, __shfl_xor_sync(0xffffffffu, v, o));
    return v;
}
__device__ __forceinline__ float warp_sum32(float v) {
#pragma unroll
    for (int o = 16; o > 0; o >>= 1) v += __shfl_xor_sync(0xffffffffu, v, o);
    return v;
}

// ---------------------------------------------------------------------------
// SGEMM (NT): C[m][n] = sum_k A[m][k] * W[n][k]
// A row-major MxK, W row-major NxK, C row-major MxN.
// 128x128 block tile, 16-wide K tile, 8x8 per-thread micro tile, 256 threads.
// Double-buffered smem with register prefetch: one __syncthreads per K tile.
// M, N multiples of 128; K multiple of 16.
// ---------------------------------------------------------------------------
__global__ __launch_bounds__(256) void sgemm_nt(
    const float* __restrict__ A, const float* __restrict__ W,
    float* __restrict__ C, int M, int N, int K) {
    __shared__ float As[2][16][128];
    __shared__ float Ws[2][16][128];
    const int tid = threadIdx.x;
    const int m0 = blockIdx.y << 7;
    const int n0 = blockIdx.x << 7;
    const int tx = tid & 15;
    const int ty = tid >> 4;

    float acc[8][8];
#pragma unroll
    for (int i = 0; i < 8; i++)
#pragma unroll
        for (int j = 0; j < 8; j++) acc[i][j] = 0.f;

    const int lrow = tid >> 2;       // 0..63
    const int lk   = (tid & 3) << 2; // 0,4,8,12

    float4 pa[2], pw[2];
    // Prefetch first tile into registers
#pragma unroll
    for (int tld = 0; tld < 2; tld++) {
        const int row = lrow + tld * 64;
        pa[tld] = *(const float4*)(A + (size_t)(m0 + row) * K + lk);
        pw[tld] = *(const float4*)(W + (size_t)(n0 + row) * K + lk);
    }
    // Store tile 0 to smem buffer 0
#pragma unroll
    for (int tld = 0; tld < 2; tld++) {
        const int row = lrow + tld * 64;
        As[0][lk + 0][row] = pa[tld].x; As[0][lk + 1][row] = pa[tld].y;
        As[0][lk + 2][row] = pa[tld].z; As[0][lk + 3][row] = pa[tld].w;
        Ws[0][lk + 0][row] = pw[tld].x; Ws[0][lk + 1][row] = pw[tld].y;
        Ws[0][lk + 2][row] = pw[tld].z; Ws[0][lk + 3][row] = pw[tld].w;
    }
    __syncthreads();

    int buf = 0;
    for (int k0 = 0; k0 < K; k0 += 16) {
        const int knext = k0 + 16;
        // Prefetch next tile into registers (overlaps with compute below)
        if (knext < K) {
#pragma unroll
            for (int tld = 0; tld < 2; tld++) {
                const int row = lrow + tld * 64;
                pa[tld] = *(const float4*)(A + (size_t)(m0 + row) * K + knext + lk);
                pw[tld] = *(const float4*)(W + (size_t)(n0 + row) * K + knext + lk);
            }
        }
        // Compute on current buffer
#pragma unroll
        for (int kk = 0; kk < 16; kk++) {
            float a[8], bb[8];
#pragma unroll
            for (int i = 0; i < 8; i++) a[i] = As[buf][kk][ty * 8 + i];
#pragma unroll
            for (int j = 0; j < 8; j++) bb[j] = Ws[buf][kk][tx * 8 + j];
#pragma unroll
            for (int i = 0; i < 8; i++)
#pragma unroll
                for (int j = 0; j < 8; j++) acc[i][j] += a[i] * bb[j];
        }
        // Commit next tile to the other buffer; single barrier per iteration
        if (knext < K) {
            const int nb_ = buf ^ 1;
#pragma unroll
            for (int tld = 0; tld < 2; tld++) {
                const int row = lrow + tld * 64;
                As[nb_][lk + 0][row] = pa[tld].x; As[nb_][lk + 1][row] = pa[tld].y;
                As[nb_][lk + 2][row] = pa[tld].z; As[nb_][lk + 3][row] = pa[tld].w;
                Ws[nb_][lk + 0][row] = pw[tld].x; Ws[nb_][lk + 1][row] = pw[tld].y;
                Ws[nb_][lk + 2][row] = pw[tld].z; Ws[nb_][lk + 3][row] = pw[tld].w;
            }
            __syncthreads();
            buf = nb_;
        }
    }
#pragma unroll
    for (int i = 0; i < 8; i++) {
        float4* dst = (float4*)(C + (size_t)(m0 + ty * 8 + i) * N + n0 + tx * 8);
        dst[0] = make_float4(acc[i][0], acc[i][1], acc[i][2], acc[i][3]);
        dst[1] = make_float4(acc[i][4], acc[i][5], acc[i][6], acc[i][7]);
    }
}

// ---------------------------------------------------------------------------
// RoPE applied in-place to Q (32 heads) and K (8 heads).
// For pair index p in [0,32): out[p]    = x[p]*cos - x[p+32]*sin
//                             out[p+32] = x[p+32]*cos + x[p]*sin
// inv_p = theta^{-(2p/64)} = exp2(-p/32 * log2(10000)); angle = s * inv_p,
// computed fp32 (mirrors the fp32 reference).
// ---------------------------------------------------------------------------
__global__ void rope_kernel(float* __restrict__ q, float* __restrict__ k) {
    const int idx = blockIdx.x * 256 + threadIdx.x;
    const int total = M_ROWS * 40 * 32; // (NH+NKV)=40 heads, 32 pairs each
    if (idx >= total) return;
    const int p = idx & 31;
    const int rest = idx >> 5;
    const int head = rest % 40;
    const int m = rest / 40;
    const int s = m & (S_LEN - 1);

    // log2(10000)/32 = 0.41524101186092027
    const float invf = exp2f(-(float)p * 0.41524101186092027f);
    const float ang = (float)s * invf;
    float sn, c;
    sincosf(ang, &sn, &c);

    float* base = (head < 32) ? (q + (size_t)m * 2048 + head * 64)
                              : (k + (size_t)m * 512 + (head - 32) * 64);
    const float x1 = base[p];
    const float x2 = base[p + 32];
    base[p]      = x1 * c - x2 * sn;
    base[p + 32] = x2 * c + x1 * sn;
}

// ---------------------------------------------------------------------------
// Windowed attention.
// grid = (4 qtiles, NH=32 heads, B*nb=32); 256 threads = 8 warps.
// Each block: one (b, block n, head h, 64-row q tile).
// Key context for block n is rows j in [0,512): global position (n-1)*256 + j.
// Valid: j >= i && j <= i+256, where i in [0,256) is the q row within the
// block; for n==0 also j >= 256 (handled by chunk skipping).
// Streaming (flash) softmax over 32-key chunks.
// warp w owns q rows i_row..i_row+7; lane = key column (scores) / out dim (PV).
// ---------------------------------------------------------------------------
__global__ __launch_bounds__(256) void attn_kernel(
    const float* __restrict__ q, const float* __restrict__ k,
    const float* __restrict__ v, float* __restrict__ o) {
    __shared__ float Qs[64][68];     // pitch 68 -> 16B-aligned rows, no conflicts
    __shared__ float Ks[32][68];
    __shared__ float Vs[32][68];
    __shared__ float Ps[8][8][32];   // per-warp probs [warp][row][key]

    const int tid  = threadIdx.x;
    const int lane = tid & 31;
    const int w    = tid >> 5;
    const int t = blockIdx.x;        // q tile 0..3
    const int h = blockIdx.y;        // head
    const int z = blockIdx.z;
    const int b = z >> 4;
    const int n = z & 15;
    const int kvh = h >> 2;          // GQA: 4 query heads per kv head

    // Load and pre-scale Q tile (scale = 1/sqrt(64) = 0.125 exact)
    {
        const size_t qbase = (size_t)(b * S_LEN + n * 256 + t * 64) * 2048 + h * 64;
        for (int idx = tid; idx < 64 * 64; idx += 256) {
            const int r = idx >> 6, d = idx & 63;
            Qs[r][d] = q[qbase + (size_t)r * 2048 + d] * 0.125f;
        }
    }

    float acc0[8], acc1[8], mrow[8], lrow[8];
#pragma unroll
    for (int r = 0; r < 8; r++) { acc0[r] = 0.f; acc1[r] = 0.f; mrow[r] = -1e30f; lrow[r] = 0.f; }

    int c_lo = 2 * t;                 // first chunk with any j >= i_min
    if (n == 0 && c_lo < 8) c_lo = 8; // block 0: previous block is all-masked
    int c_hi = 2 * t + 9;             // last chunk with any j <= i_max+256
    if (c_hi > 15) c_hi = 15;
    const int i_row = t * 64 + w * 8;

    for (int c = c_lo; c <= c_hi; c++) {
        __syncthreads();
        {
            const int srow0 = b * S_LEN + (n - 1) * 256 + c * 32; // >=0 for visited chunks
            for (int idx = tid; idx < 32 * 64; idx += 256) {
                const int r = idx >> 6, d = idx & 63;
                const size_t off = (size_t)(srow0 + r) * 512 + kvh * 64 + d;
                Ks[r][d] = k[off];
                Vs[r][d] = v[off];
            }
        }
        __syncthreads();

        // Scores: lane -> key j = c*32+lane, 8 rows per warp.
        float sc[8];
#pragma unroll
        for (int r = 0; r < 8; r++) sc[r] = 0.f;
        const float4* krow = (const float4*)(&Ks[lane][0]);
#pragma unroll
        for (int d4 = 0; d4 < 16; d4++) {
            const float4 kv = krow[d4];
#pragma unroll
            for (int r = 0; r < 8; r++) {
                const float4 qv = *(const float4*)(&Qs[w * 8 + r][d4 * 4]);
                sc[r] += qv.x * kv.x + qv.y * kv.y + qv.z * kv.z + qv.w * kv.w;
            }
        }

        const int j = c * 32 + lane;
        float alpha[8];
#pragma unroll
        for (int r = 0; r < 8; r++) {
            const int i = i_row + r;
            const bool valid = (j >= i) && (j <= i + 256);
            const float s = valid ? sc[r] : -1e30f;
            const float cm = warp_max32(s);
            const float mnew = fmaxf(mrow[r], cm);
            const float p = valid ? __expf(s - mnew) : 0.f;
            const float a = __expf(mrow[r] - mnew); // ==1 when both still -1e30
            lrow[r] = lrow[r] * a + warp_sum32(p);
            mrow[r] = mnew;
            alpha[r] = a;
            Ps[w][r][lane] = p;
        }
        __syncwarp();
#pragma unroll
        for (int r = 0; r < 8; r++) { acc0[r] *= alpha[r]; acc1[r] *= alpha[r]; }

        // PV: lane -> out dims d=lane and d=lane+32.
#pragma unroll
        for (int jj4 = 0; jj4 < 8; jj4++) {
            float va[4], vb[4];
#pragma unroll
            for (int u = 0; u < 4; u++) {
                va[u] = Vs[jj4 * 4 + u][lane];
                vb[u] = Vs[jj4 * 4 + u][lane + 32];
            }
#pragma unroll
            for (int r = 0; r < 8; r++) {
                const float4 p4 = *(const float4*)(&Ps[w][r][jj4 * 4]);
                acc0[r] += p4.x * va[0] + p4.y * va[1] + p4.z * va[2] + p4.w * va[3];
                acc1[r] += p4.x * vb[0] + p4.y * vb[1] + p4.z * vb[2] + p4.w * vb[3];
            }
        }
    }

    const size_t obase = (size_t)(b * S_LEN + n * 256 + i_row) * 2048 + h * 64;
#pragma unroll
    for (int r = 0; r < 8; r++) {
        const float invl = 1.f / lrow[r]; // lrow>0: self key (j=i+256) always valid
        o[obase + (size_t)r * 2048 + lane]      = acc0[r] * invl;
        o[obase + (size_t)r * 2048 + lane + 32] = acc1[r] * invl;
    }
}

// ---------------------------------------------------------------------------
// Launch: QKV projections -> RoPE -> attention -> output projection
// ---------------------------------------------------------------------------
extern "C" void kernel_launch(void* const* d_in, const int* in_sizes, int n_in,
                              void* d_out, int out_size) {
    const float* hs = (const float*)d_in[0];
    const float* Wq = (const float*)d_in[1];
    const float* Wk = (const float*)d_in[2];
    const float* Wv = (const float*)d_in[3];
    const float* Wo = (const float*)d_in[4];
    float* out = (float*)d_out;

    float *q, *k, *v, *att;
    cudaGetSymbolAddress((void**)&q,   g_q);
    cudaGetSymbolAddress((void**)&k,   g_k);
    cudaGetSymbolAddress((void**)&v,   g_v);
    cudaGetSymbolAddress((void**)&att, g_att);

    // Q/K/V projections (NT GEMMs)
    sgemm_nt<<<dim3(2048 / 128, M_ROWS / 128), 256>>>(hs, Wq, q, M_ROWS, 2048, 2048);
    sgemm_nt<<<dim3(512 / 128,  M_ROWS / 128), 256>>>(hs, Wk, k, M_ROWS, 512, 2048);
    sgemm_nt<<<dim3(512 / 128,  M_ROWS / 128), 256>>>(hs, Wv, v, M_ROWS, 512, 2048);

    // RoPE on Q and K in-place
    {
        const int total = M_ROWS * 40 * 32;
        rope_kernel<<<(total + 255) / 256, 256>>>(q, k);
    }

    // Windowed attention
    attn_kernel<<<dim3(4, 32, 32), 256>>>(q, k, v, att);

    // Output projection
    sgemm_nt<<<dim3(2048 / 128, M_ROWS / 128), 256>>>(att, Wo, out, M_ROWS, 2048, 2048);
}

// round 3
// speedup vs baseline: 1.9816x; 1.9816x over previous
#include <cuda_runtime.h>
#include <cuda_bf16.h>
#include <math.h>

// Problem constants
// B=2, S=4096, H=2048, NH=32, NKV=8, HD=64, BL=256, nb=16, rep=4
#define M_ROWS 8192
#define S_LEN  4096

// ---------------------------------------------------------------------------
// Scratch (__device__ globals; no runtime allocation allowed)
// ---------------------------------------------------------------------------
__device__ float g_q[(size_t)M_ROWS * 2048];   // Q after proj (+RoPE)
__device__ float g_k[(size_t)M_ROWS * 512];    // K after proj (+RoPE)
__device__ float g_v[(size_t)M_ROWS * 512];    // V after proj

__device__ __nv_bfloat16 g_hs_hi[(size_t)M_ROWS * 2048];
__device__ __nv_bfloat16 g_hs_lo[(size_t)M_ROWS * 2048];
__device__ __nv_bfloat16 g_wq_hi[(size_t)2048 * 2048];
__device__ __nv_bfloat16 g_wq_lo[(size_t)2048 * 2048];
__device__ __nv_bfloat16 g_wk_hi[(size_t)512 * 2048];
__device__ __nv_bfloat16 g_wk_lo[(size_t)512 * 2048];
__device__ __nv_bfloat16 g_wv_hi[(size_t)512 * 2048];
__device__ __nv_bfloat16 g_wv_lo[(size_t)512 * 2048];
__device__ __nv_bfloat16 g_wo_hi[(size_t)2048 * 2048];
__device__ __nv_bfloat16 g_wo_lo[(size_t)2048 * 2048];
__device__ __nv_bfloat16 g_att_hi[(size_t)M_ROWS * 2048];
__device__ __nv_bfloat16 g_att_lo[(size_t)M_ROWS * 2048];

// ---------------------------------------------------------------------------
// Helpers
// ---------------------------------------------------------------------------
__device__ __forceinline__ unsigned smem_u32(const void* p) {
    unsigned r;
    asm("{ .reg .u64 t; cvta.to.shared.u64 t, %1; cvt.u32.u64 %0, t; }"
        : "=r"(r) : "l"(p));
    return r;
}
__device__ __forceinline__ void cp16(unsigned dst, const void* src) {
    asm volatile("cp.async.cg.shared.global [%0], [%1], 16;\n"
                 :: "r"(dst), "l"(src) : "memory");
}
__device__ __forceinline__ void ldsm4(unsigned* r, unsigned addr) {
    asm volatile("ldmatrix.sync.aligned.m8n8.x4.shared.b16 {%0,%1,%2,%3}, [%4];"
                 : "=r"(r[0]), "=r"(r[1]), "=r"(r[2]), "=r"(r[3]) : "r"(addr));
}
__device__ __forceinline__ void mma16816(float* d, const unsigned* a, const unsigned* b) {
    asm volatile(
        "mma.sync.aligned.m16n8k16.row.col.f32.bf16.bf16.f32 "
        "{%0,%1,%2,%3}, {%4,%5,%6,%7}, {%8,%9}, {%0,%1,%2,%3};"
        : "+f"(d[0]), "+f"(d[1]), "+f"(d[2]), "+f"(d[3])
        : "r"(a[0]), "r"(a[1]), "r"(a[2]), "r"(a[3]), "r"(b[0]), "r"(b[1]));
}

__device__ __forceinline__ float warp_max32(float v) {
#pragma unroll
    for (int o = 16; o > 0; o >>= 1) v = fmaxf(v, __shfl_xor_sync(0xffffffffu, v, o));
    return v;
}
__device__ __forceinline__ float warp_sum32(float v) {
#pragma unroll
    for (int o = 16; o > 0; o >>= 1) v += __shfl_xor_sync(0xffffffffu, v, o);
    return v;
}

// ---------------------------------------------------------------------------
// split: fp32 x -> (hi = bf16(x), lo = bf16(x - hi)) ; n4 = elems/4
// ---------------------------------------------------------------------------
__global__ void split_kernel(const float* __restrict__ x,
                             __nv_bfloat16* __restrict__ hi,
                             __nv_bfloat16* __restrict__ lo, int n4) {
    const int i = blockIdx.x * 256 + threadIdx.x;
    if (i >= n4) return;
    const float4 vv = ((const float4*)x)[i];
    float f[4] = {vv.x, vv.y, vv.z, vv.w};
    __nv_bfloat16 h[4], l[4];
#pragma unroll
    for (int j = 0; j < 4; j++) {
        h[j] = __float2bfloat16(f[j]);
        l[j] = __float2bfloat16(f[j] - __bfloat162float(h[j]));
    }
    __nv_bfloat162* H = (__nv_bfloat162*)hi;
    __nv_bfloat162* L = (__nv_bfloat162*)lo;
    __nv_bfloat162 t;
    t.x = h[0]; t.y = h[1]; H[2 * i]     = t;
    t.x = h[2]; t.y = h[3]; H[2 * i + 1] = t;
    t.x = l[0]; t.y = l[1]; L[2 * i]     = t;
    t.x = l[2]; t.y = l[3]; L[2 * i + 1] = t;
}

// ---------------------------------------------------------------------------
// bf16x3 tensor-core GEMM (NT): C[m][n] = sum_k A[m][k] * W[n][k], fp32 out.
// A ~ Ahi+Alo, W ~ Whi+Wlo; D += Ahi*Whi + Ahi*Wlo + Alo*Whi.
// CTA tile 128x128, K-tile 32, 256 threads (8 warps, 2x4; warp tile 64x32).
// Smem: 2 buffers x 4 planes (Ahi,Alo,Whi,Wlo), each 128 rows x 64B,
// XOR-swizzled 16B chunks -> conflict-free ldmatrix. cp.async double buffer.
// Requires M%128==0, N%128==0, K%32==0.
// ---------------------------------------------------------------------------
__global__ __launch_bounds__(256, 1) void gemm_bf16x3(
    const __nv_bfloat16* __restrict__ Ahi, const __nv_bfloat16* __restrict__ Alo,
    const __nv_bfloat16* __restrict__ Whi, const __nv_bfloat16* __restrict__ Wlo,
    float* __restrict__ C, int M, int N, int K) {
    extern __shared__ __align__(16) unsigned char smraw[];
    const unsigned sbase = smem_u32(smraw);

    const int tid = threadIdx.x;
    const int wid = tid >> 5, lane = tid & 31;
    const int warp_m = wid >> 2;  // 0..1
    const int warp_n = wid & 3;   // 0..3
    const int m0 = blockIdx.y << 7;
    const int n0 = blockIdx.x << 7;

    const __nv_bfloat16* srcs[4] = {
        Ahi + (size_t)m0 * K, Alo + (size_t)m0 * K,
        Whi + (size_t)n0 * K, Wlo + (size_t)n0 * K};

    float acc[4][4][4];
#pragma unroll
    for (int i = 0; i < 4; i++)
#pragma unroll
        for (int j = 0; j < 4; j++)
#pragma unroll
            for (int u = 0; u < 4; u++) acc[i][j][u] = 0.f;

    // gmem->smem: thread t loads row r=t/2, 16B chunks c = 2*(t&1), 2*(t&1)+1
    const int ldr = tid >> 1;
    const int ldc = (tid & 1) * 2;

    auto prefetch = [&](int it, int bufi) {
        const int k0 = it * 32;
        const unsigned bufbase = sbase + bufi * 32768u;
#pragma unroll
        for (int p = 0; p < 4; p++) {
            const __nv_bfloat16* src = srcs[p] + (size_t)ldr * K + k0 + ldc * 8;
            const unsigned splane = bufbase + p * 8192u;
#pragma unroll
            for (int cc = 0; cc < 2; cc++) {
                const int c = ldc + cc;
                const unsigned dst =
                    splane + ldr * 64u + (unsigned)((c ^ ((ldr >> 1) & 3)) << 4);
                cp16(dst, src + cc * 8);
            }
        }
    };

    auto compute = [&](int bufi) {
        const unsigned base = sbase + bufi * 32768u;
        const int arow = (lane & 7) + ((lane >> 3) & 1) * 8;
        const int khalf = (lane >> 4) & 1;
#pragma unroll
        for (int ks = 0; ks < 2; ks++) {
            const int c = ks * 2 + khalf;
            unsigned ahi[4][4], alo[4][4];
#pragma unroll
            for (int fm = 0; fm < 4; fm++) {
                const int row = warp_m * 64 + fm * 16 + arow;
                const unsigned off =
                    row * 64u + (unsigned)((c ^ ((row >> 1) & 3)) << 4);
                ldsm4(ahi[fm], base + off);
                ldsm4(alo[fm], base + 8192u + off);
            }
            unsigned bhi[4][2], blo[4][2];
#pragma unroll
            for (int half = 0; half < 2; half++) {
                const int row = warp_n * 32 + half * 16 + arow;
                const unsigned off =
                    row * 64u + (unsigned)((c ^ ((row >> 1) & 3)) << 4);
                unsigned t[4];
                ldsm4(t, base + 16384u + off);
                bhi[half * 2 + 0][0] = t[0]; bhi[half * 2 + 0][1] = t[2];
                bhi[half * 2 + 1][0] = t[1]; bhi[half * 2 + 1][1] = t[3];
                ldsm4(t, base + 24576u + off);
                blo[half * 2 + 0][0] = t[0]; blo[half * 2 + 0][1] = t[2];
                blo[half * 2 + 1][0] = t[1]; blo[half * 2 + 1][1] = t[3];
            }
#pragma unroll
            for (int i = 0; i < 4; i++)
#pragma unroll
                for (int j = 0; j < 4; j++) {
                    mma16816(acc[i][j], ahi[i], bhi[j]);
                    mma16816(acc[i][j], ahi[i], blo[j]);
                    mma16816(acc[i][j], alo[i], bhi[j]);
                }
        }
    };

    const int NIT = K >> 5;
    prefetch(0, 0);
    asm volatile("cp.async.commit_group;\n" ::: "memory");
    int buf = 0;
    for (int it = 0; it < NIT; it++) {
        if (it + 1 < NIT) {
            prefetch(it + 1, buf ^ 1);
            asm volatile("cp.async.commit_group;\n" ::: "memory");
            asm volatile("cp.async.wait_group 1;\n" ::: "memory");
        } else {
            asm volatile("cp.async.wait_group 0;\n" ::: "memory");
        }
        __syncthreads();
        compute(buf);
        __syncthreads();
        buf ^= 1;
    }

    // Epilogue: write fp32 C
#pragma unroll
    for (int i = 0; i < 4; i++)
#pragma unroll
        for (int j = 0; j < 4; j++) {
            const int r0 = m0 + warp_m * 64 + i * 16 + (lane >> 2);
            const int cc = n0 + warp_n * 32 + j * 8 + (lane & 3) * 2;
            float2 u;
            u.x = acc[i][j][0]; u.y = acc[i][j][1];
            *(float2*)(C + (size_t)r0 * N + cc) = u;
            u.x = acc[i][j][2]; u.y = acc[i][j][3];
            *(float2*)(C + (size_t)(r0 + 8) * N + cc) = u;
        }
}

// ---------------------------------------------------------------------------
// RoPE in-place on Q (32 heads) and K (8 heads).
// ---------------------------------------------------------------------------
__global__ void rope_kernel(float* __restrict__ q, float* __restrict__ k) {
    const int idx = blockIdx.x * 256 + threadIdx.x;
    const int total = M_ROWS * 40 * 32;
    if (idx >= total) return;
    const int p = idx & 31;
    const int rest = idx >> 5;
    const int head = rest % 40;
    const int m = rest / 40;
    const int s = m & (S_LEN - 1);

    // log2(10000)/32
    const float invf = exp2f(-(float)p * 0.41524101186092027f);
    const float ang = (float)s * invf;
    float sn, c;
    sincosf(ang, &sn, &c);

    float* base = (head < 32) ? (q + (size_t)m * 2048 + head * 64)
                              : (k + (size_t)m * 512 + (head - 32) * 64);
    const float x1 = base[p];
    const float x2 = base[p + 32];
    base[p]      = x1 * c - x2 * sn;
    base[p + 32] = x2 * c + x1 * sn;
}

// ---------------------------------------------------------------------------
// Windowed attention (flash, fp32). Emits hi/lo bf16 split of the output so
// the O-projection GEMM can consume it directly.
// ---------------------------------------------------------------------------
__global__ __launch_bounds__(256) void attn_kernel(
    const float* __restrict__ q, const float* __restrict__ k,
    const float* __restrict__ v,
    __nv_bfloat16* __restrict__ ohi, __nv_bfloat16* __restrict__ olo) {
    __shared__ float Qs[64][68];
    __shared__ float Ks[32][68];
    __shared__ float Vs[32][68];
    __shared__ float Ps[8][8][32];

    const int tid  = threadIdx.x;
    const int lane = tid & 31;
    const int w    = tid >> 5;
    const int t = blockIdx.x;
    const int h = blockIdx.y;
    const int z = blockIdx.z;
    const int b = z >> 4;
    const int n = z & 15;
    const int kvh = h >> 2;

    {
        const size_t qbase = (size_t)(b * S_LEN + n * 256 + t * 64) * 2048 + h * 64;
        for (int idx = tid; idx < 64 * 64; idx += 256) {
            const int r = idx >> 6, d = idx & 63;
            Qs[r][d] = q[qbase + (size_t)r * 2048 + d] * 0.125f;
        }
    }

    float acc0[8], acc1[8], mrow[8], lrow[8];
#pragma unroll
    for (int r = 0; r < 8; r++) { acc0[r] = 0.f; acc1[r] = 0.f; mrow[r] = -1e30f; lrow[r] = 0.f; }

    int c_lo = 2 * t;
    if (n == 0 && c_lo < 8) c_lo = 8;
    int c_hi = 2 * t + 9;
    if (c_hi > 15) c_hi = 15;
    const int i_row = t * 64 + w * 8;

    for (int c = c_lo; c <= c_hi; c++) {
        __syncthreads();
        {
            const int srow0 = b * S_LEN + (n - 1) * 256 + c * 32;
            for (int idx = tid; idx < 32 * 64; idx += 256) {
                const int r = idx >> 6, d = idx & 63;
                const size_t off = (size_t)(srow0 + r) * 512 + kvh * 64 + d;
                Ks[r][d] = k[off];
                Vs[r][d] = v[off];
            }
        }
        __syncthreads();

        float sc[8];
#pragma unroll
        for (int r = 0; r < 8; r++) sc[r] = 0.f;
        const float4* krow = (const float4*)(&Ks[lane][0]);
#pragma unroll
        for (int d4 = 0; d4 < 16; d4++) {
            const float4 kv = krow[d4];
#pragma unroll
            for (int r = 0; r < 8; r++) {
                const float4 qv = *(const float4*)(&Qs[w * 8 + r][d4 * 4]);
                sc[r] += qv.x * kv.x + qv.y * kv.y + qv.z * kv.z + qv.w * kv.w;
            }
        }

        const int j = c * 32 + lane;
        float alpha[8];
#pragma unroll
        for (int r = 0; r < 8; r++) {
            const int i = i_row + r;
            const bool valid = (j >= i) && (j <= i + 256);
            const float s = valid ? sc[r] : -1e30f;
            const float cm = warp_max32(s);
            const float mnew = fmaxf(mrow[r], cm);
            const float p = valid ? __expf(s - mnew) : 0.f;
            const float a = __expf(mrow[r] - mnew);
            lrow[r] = lrow[r] * a + warp_sum32(p);
            mrow[r] = mnew;
            alpha[r] = a;
            Ps[w][r][lane] = p;
        }
        __syncwarp();
#pragma unroll
        for (int r = 0; r < 8; r++) { acc0[r] *= alpha[r]; acc1[r] *= alpha[r]; }

#pragma unroll
        for (int jj4 = 0; jj4 < 8; jj4++) {
            float va[4], vb[4];
#pragma unroll
            for (int u = 0; u < 4; u++) {
                va[u] = Vs[jj4 * 4 + u][lane];
                vb[u] = Vs[jj4 * 4 + u][lane + 32];
            }
#pragma unroll
            for (int r = 0; r < 8; r++) {
                const float4 p4 = *(const float4*)(&Ps[w][r][jj4 * 4]);
                acc0[r] += p4.x * va[0] + p4.y * va[1] + p4.z * va[2] + p4.w * va[3];
                acc1[r] += p4.x * vb[0] + p4.y * vb[1] + p4.z * vb[2] + p4.w * vb[3];
            }
        }
    }

    const size_t obase = (size_t)(b * S_LEN + n * 256 + i_row) * 2048 + h * 64;
#pragma unroll
    for (int r = 0; r < 8; r++) {
        const float invl = 1.f / lrow[r];
        const float v0 = acc0[r] * invl;
        const float v1 = acc1[r] * invl;
        const size_t i0 = obase + (size_t)r * 2048 + lane;
        const size_t i1 = i0 + 32;
        const __nv_bfloat16 h0 = __float2bfloat16(v0);
        const __nv_bfloat16 h1 = __float2bfloat16(v1);
        ohi[i0] = h0;
        ohi[i1] = h1;
        olo[i0] = __float2bfloat16(v0 - __bfloat162float(h0));
        olo[i1] = __float2bfloat16(v1 - __bfloat162float(h1));
    }
}

// ---------------------------------------------------------------------------
// Launch
// ---------------------------------------------------------------------------
extern "C" void kernel_launch(void* const* d_in, const int* in_sizes, int n_in,
                              void* d_out, int out_size) {
    const float* hs = (const float*)d_in[0];
    const float* Wq = (const float*)d_in[1];
    const float* Wk = (const float*)d_in[2];
    const float* Wv = (const float*)d_in[3];
    const float* Wo = (const float*)d_in[4];
    float* out = (float*)d_out;

    float *q, *k, *v;
    __nv_bfloat16 *hs_hi, *hs_lo, *wq_hi, *wq_lo, *wk_hi, *wk_lo;
    __nv_bfloat16 *wv_hi, *wv_lo, *wo_hi, *wo_lo, *att_hi, *att_lo;
    cudaGetSymbolAddress((void**)&q, g_q);
    cudaGetSymbolAddress((void**)&k, g_k);
    cudaGetSymbolAddress((void**)&v, g_v);
    cudaGetSymbolAddress((void**)&hs_hi, g_hs_hi);
    cudaGetSymbolAddress((void**)&hs_lo, g_hs_lo);
    cudaGetSymbolAddress((void**)&wq_hi, g_wq_hi);
    cudaGetSymbolAddress((void**)&wq_lo, g_wq_lo);
    cudaGetSymbolAddress((void**)&wk_hi, g_wk_hi);
    cudaGetSymbolAddress((void**)&wk_lo, g_wk_lo);
    cudaGetSymbolAddress((void**)&wv_hi, g_wv_hi);
    cudaGetSymbolAddress((void**)&wv_lo, g_wv_lo);
    cudaGetSymbolAddress((void**)&wo_hi, g_wo_hi);
    cudaGetSymbolAddress((void**)&wo_lo, g_wo_lo);
    cudaGetSymbolAddress((void**)&att_hi, g_att_hi);
    cudaGetSymbolAddress((void**)&att_lo, g_att_lo);

    cudaFuncSetAttribute(gemm_bf16x3,
                         cudaFuncAttributeMaxDynamicSharedMemorySize, 65536);

    // Split inputs into bf16 hi/lo
    split_kernel<<<(M_ROWS * 2048 / 4 + 255) / 256, 256>>>(hs, hs_hi, hs_lo, M_ROWS * 2048 / 4);
    split_kernel<<<(2048 * 2048 / 4 + 255) / 256, 256>>>(Wq, wq_hi, wq_lo, 2048 * 2048 / 4);
    split_kernel<<<(512 * 2048 / 4 + 255) / 256, 256>>>(Wk, wk_hi, wk_lo, 512 * 2048 / 4);
    split_kernel<<<(512 * 2048 / 4 + 255) / 256, 256>>>(Wv, wv_hi, wv_lo, 512 * 2048 / 4);
    split_kernel<<<(2048 * 2048 / 4 + 255) / 256, 256>>>(Wo, wo_hi, wo_lo, 2048 * 2048 / 4);

    // Q/K/V projections on tensor cores
    gemm_bf16x3<<<dim3(2048 / 128, M_ROWS / 128), 256, 65536>>>(
        hs_hi, hs_lo, wq_hi, wq_lo, q, M_ROWS, 2048, 2048);
    gemm_bf16x3<<<dim3(512 / 128, M_ROWS / 128), 256, 65536>>>(
        hs_hi, hs_lo, wk_hi, wk_lo, k, M_ROWS, 512, 2048);
    gemm_bf16x3<<<dim3(512 / 128, M_ROWS / 128), 256, 65536>>>(
        hs_hi, hs_lo, wv_hi, wv_lo, v, M_ROWS, 512, 2048);

    // RoPE
    {
        const int total = M_ROWS * 40 * 32;
        rope_kernel<<<(total + 255) / 256, 256>>>(q, k);
    }

    // Attention (emits bf16 hi/lo directly)
    attn_kernel<<<dim3(4, 32, 32), 256>>>(q, k, v, att_hi, att_lo);

    // Output projection
    gemm_bf16x3<<<dim3(2048 / 128, M_ROWS / 128), 256, 65536>>>(
        att_hi, att_lo, wo_hi, wo_lo, out, M_ROWS, 2048, 2048);
}

// round 5
// speedup vs baseline: 1.9840x; 1.0012x over previous
#include <cuda_runtime.h>
#include <cuda_bf16.h>
#include <math.h>

// Problem constants
// B=2, S=4096, H=2048, NH=32, NKV=8, HD=64, BL=256, nb=16, rep=4
#define M_ROWS 8192
#define S_LEN  4096

// ---------------------------------------------------------------------------
// Scratch (__device__ globals; no runtime allocation allowed)
// ---------------------------------------------------------------------------
__device__ float g_q[(size_t)M_ROWS * 2048];   // Q after proj (+RoPE)
__device__ float g_k[(size_t)M_ROWS * 512];    // K after proj (+RoPE)
__device__ float g_v[(size_t)M_ROWS * 512];    // V after proj

__device__ __nv_bfloat16 g_hs_hi[(size_t)M_ROWS * 2048];
__device__ __nv_bfloat16 g_hs_lo[(size_t)M_ROWS * 2048];
__device__ __nv_bfloat16 g_wq_hi[(size_t)2048 * 2048];
__device__ __nv_bfloat16 g_wq_lo[(size_t)2048 * 2048];
__device__ __nv_bfloat16 g_wk_hi[(size_t)512 * 2048];
__device__ __nv_bfloat16 g_wk_lo[(size_t)512 * 2048];
__device__ __nv_bfloat16 g_wv_hi[(size_t)512 * 2048];
__device__ __nv_bfloat16 g_wv_lo[(size_t)512 * 2048];
__device__ __nv_bfloat16 g_wo_hi[(size_t)2048 * 2048];
__device__ __nv_bfloat16 g_wo_lo[(size_t)2048 * 2048];
__device__ __nv_bfloat16 g_att_hi[(size_t)M_ROWS * 2048];
__device__ __nv_bfloat16 g_att_lo[(size_t)M_ROWS * 2048];

// ---------------------------------------------------------------------------
// Helpers
// ---------------------------------------------------------------------------
__device__ __forceinline__ unsigned smem_u32(const void* p) {
    unsigned r;
    asm("{ .reg .u64 t; cvta.to.shared.u64 t, %1; cvt.u32.u64 %0, t; }"
        : "=r"(r) : "l"(p));
    return r;
}
__device__ __forceinline__ void cp16(unsigned dst, const void* src) {
    asm volatile("cp.async.cg.shared.global [%0], [%1], 16;\n"
                 :: "r"(dst), "l"(src) : "memory");
}
__device__ __forceinline__ void ldsm4(unsigned* r, unsigned addr) {
    asm volatile("ldmatrix.sync.aligned.m8n8.x4.shared.b16 {%0,%1,%2,%3}, [%4];"
                 : "=r"(r[0]), "=r"(r[1]), "=r"(r[2]), "=r"(r[3]) : "r"(addr));
}
__device__ __forceinline__ void mma16816(float* d, const unsigned* a, const unsigned* b) {
    asm volatile(
        "mma.sync.aligned.m16n8k16.row.col.f32.bf16.bf16.f32 "
        "{%0,%1,%2,%3}, {%4,%5,%6,%7}, {%8,%9}, {%0,%1,%2,%3};"
        : "+f"(d[0]), "+f"(d[1]), "+f"(d[2]), "+f"(d[3])
        : "r"(a[0]), "r"(a[1]), "r"(a[2]), "r"(a[3]), "r"(b[0]), "r"(b[1]));
}

__device__ __forceinline__ float warp_max32(float v) {
#pragma unroll
    for (int o = 16; o > 0; o >>= 1) v = fmaxf(v, __shfl_xor_sync(0xffffffffu, v, o));
    return v;
}
__device__ __forceinline__ float warp_sum32(float v) {
#pragma unroll
    for (int o = 16; o > 0; o >>= 1) v += __shfl_xor_sync(0xffffffffu, v, o);
    return v;
}

// ---------------------------------------------------------------------------
// split: fp32 x -> (hi = bf16(x), lo = bf16(x - hi)) ; n4 = elems/4
// ---------------------------------------------------------------------------
__global__ void split_kernel(const float* __restrict__ x,
                             __nv_bfloat16* __restrict__ hi,
                             __nv_bfloat16* __restrict__ lo, int n4) {
    const int i = blockIdx.x * 256 + threadIdx.x;
    if (i >= n4) return;
    const float4 vv = ((const float4*)x)[i];
    float f[4] = {vv.x, vv.y, vv.z, vv.w};
    __nv_bfloat16 h[4], l[4];
#pragma unroll
    for (int j = 0; j < 4; j++) {
        h[j] = __float2bfloat16(f[j]);
        l[j] = __float2bfloat16(f[j] - __bfloat162float(h[j]));
    }
    __nv_bfloat162* H = (__nv_bfloat162*)hi;
    __nv_bfloat162* L = (__nv_bfloat162*)lo;
    __nv_bfloat162 t;
    t.x = h[0]; t.y = h[1]; H[2 * i]     = t;
    t.x = h[2]; t.y = h[3]; H[2 * i + 1] = t;
    t.x = l[0]; t.y = l[1]; L[2 * i]     = t;
    t.x = l[2]; t.y = l[3]; L[2 * i + 1] = t;
}

// ---------------------------------------------------------------------------
// bf16x3 tensor-core GEMM (NT): C[m][n] = sum_k A[m][k] * W[n][k], fp32 out.
// D += Ahi*Whi + Ahi*Wlo + Alo*Whi.
// CTA tile 128x128, K-tile 32, 256 threads (8 warps, 2x4; warp tile 64x32).
// 3-stage cp.async ring (32KB/stage), 2 CTAs/SM. Planes per stage:
// [Ahi 8K][Alo 8K][Whi 8K][Wlo 8K], 64B rows, XOR-swizzled 16B chunks.
// Requires M%128==0, N%128==0, K%32==0, K/32 >= 2.
// ---------------------------------------------------------------------------
#define GSTAGE 32768u

__global__ __launch_bounds__(256, 2) void gemm_bf16x3(
    const __nv_bfloat16* __restrict__ Ahi, const __nv_bfloat16* __restrict__ Alo,
    const __nv_bfloat16* __restrict__ Whi, const __nv_bfloat16* __restrict__ Wlo,
    float* __restrict__ C, int M, int N, int K) {
    extern __shared__ __align__(16) unsigned char smraw[];
    const unsigned sbase = smem_u32(smraw);

    const int tid = threadIdx.x;
    const int wid = tid >> 5, lane = tid & 31;
    const int warp_m = wid >> 2;  // 0..1
    const int warp_n = wid & 3;   // 0..3
    const int m0 = blockIdx.y << 7;
    const int n0 = blockIdx.x << 7;

    const __nv_bfloat16* srcs[4] = {
        Ahi + (size_t)m0 * K, Alo + (size_t)m0 * K,
        Whi + (size_t)n0 * K, Wlo + (size_t)n0 * K};

    float acc[4][4][4];
#pragma unroll
    for (int i = 0; i < 4; i++)
#pragma unroll
        for (int j = 0; j < 4; j++)
#pragma unroll
            for (int u = 0; u < 4; u++) acc[i][j][u] = 0.f;

    // gmem->smem: thread t loads row r=t/2, 16B chunks c = 2*(t&1), 2*(t&1)+1
    const int ldr = tid >> 1;
    const int ldc = (tid & 1) * 2;

    auto prefetch = [&](int it, int bufi) {
        const int k0 = it * 32;
        const unsigned bufbase = sbase + (unsigned)bufi * GSTAGE;
#pragma unroll
        for (int p = 0; p < 4; p++) {
            const __nv_bfloat16* src = srcs[p] + (size_t)ldr * K + k0 + ldc * 8;
            const unsigned splane = bufbase + p * 8192u;
#pragma unroll
            for (int cc = 0; cc < 2; cc++) {
                const int c = ldc + cc;
                const unsigned dst =
                    splane + ldr * 64u + (unsigned)((c ^ ((ldr >> 1) & 3)) << 4);
                cp16(dst, src + cc * 8);
            }
        }
    };

    auto compute = [&](int bufi) {
        const unsigned base = sbase + (unsigned)bufi * GSTAGE;
        const int arow = (lane & 7) + ((lane >> 3) & 1) * 8;
        const int khalf = (lane >> 4) & 1;
#pragma unroll
        for (int ks = 0; ks < 2; ks++) {
            const int c = ks * 2 + khalf;
            // B fragments for this k16 (held across the i loop)
            unsigned bhi[4][2], blo[4][2];
#pragma unroll
            for (int half = 0; half < 2; half++) {
                const int row = warp_n * 32 + half * 16 + arow;
                const unsigned off =
                    row * 64u + (unsigned)((c ^ ((row >> 1) & 3)) << 4);
                unsigned t[4];
                ldsm4(t, base + 16384u + off);
                bhi[half * 2 + 0][0] = t[0]; bhi[half * 2 + 0][1] = t[2];
                bhi[half * 2 + 1][0] = t[1]; bhi[half * 2 + 1][1] = t[3];
                ldsm4(t, base + 24576u + off);
                blo[half * 2 + 0][0] = t[0]; blo[half * 2 + 0][1] = t[2];
                blo[half * 2 + 1][0] = t[1]; blo[half * 2 + 1][1] = t[3];
            }
            // A fragments loaded per i (keeps register count low for occ=2)
#pragma unroll
            for (int i = 0; i < 4; i++) {
                const int row = warp_m * 64 + i * 16 + arow;
                const unsigned off =
                    row * 64u + (unsigned)((c ^ ((row >> 1) & 3)) << 4);
                unsigned ahi[4], alo[4];
                ldsm4(ahi, base + off);
                ldsm4(alo, base + 8192u + off);
#pragma unroll
                for (int j = 0; j < 4; j++) {
                    mma16816(acc[i][j], ahi, bhi[j]);
                    mma16816(acc[i][j], ahi, blo[j]);
                    mma16816(acc[i][j], alo, bhi[j]);
                }
            }
        }
    };

    const int NIT = K >> 5;
    // Prologue: stages 0 and 1 in flight
    prefetch(0, 0);
    asm volatile("cp.async.commit_group;\n" ::: "memory");
    prefetch(1, 1);
    asm volatile("cp.async.commit_group;\n" ::: "memory");

    for (int it = 0; it < NIT; it++) {
        if (it + 2 < NIT) {
            prefetch(it + 2, (it + 2) % 3);
            asm volatile("cp.async.commit_group;\n" ::: "memory");
            asm volatile("cp.async.wait_group 2;\n" ::: "memory");
        } else if (it + 1 < NIT) {
            asm volatile("cp.async.wait_group 1;\n" ::: "memory");
        } else {
            asm volatile("cp.async.wait_group 0;\n" ::: "memory");
        }
        __syncthreads();
        compute(it % 3);
        __syncthreads();
    }

    // Epilogue: write fp32 C
#pragma unroll
    for (int i = 0; i < 4; i++)
#pragma unroll
        for (int j = 0; j < 4; j++) {
            const int r0 = m0 + warp_m * 64 + i * 16 + (lane >> 2);
            const int cc = n0 + warp_n * 32 + j * 8 + (lane & 3) * 2;
            float2 u;
            u.x = acc[i][j][0]; u.y = acc[i][j][1];
            *(float2*)(C + (size_t)r0 * N + cc) = u;
            u.x = acc[i][j][2]; u.y = acc[i][j][3];
            *(float2*)(C + (size_t)(r0 + 8) * N + cc) = u;
        }
}

// ---------------------------------------------------------------------------
// RoPE in-place on Q (32 heads) and K (8 heads).
// ---------------------------------------------------------------------------
__global__ void rope_kernel(float* __restrict__ q, float* __restrict__ k) {
    const int idx = blockIdx.x * 256 + threadIdx.x;
    const int total = M_ROWS * 40 * 32;
    if (idx >= total) return;
    const int p = idx & 31;
    const int rest = idx >> 5;
    const int head = rest % 40;
    const int m = rest / 40;
    const int s = m & (S_LEN - 1);

    // log2(10000)/32
    const float invf = exp2f(-(float)p * 0.41524101186092027f);
    const float ang = (float)s * invf;
    float sn, c;
    sincosf(ang, &sn, &c);

    float* base = (head < 32) ? (q + (size_t)m * 2048 + head * 64)
                              : (k + (size_t)m * 512 + (head - 32) * 64);
    const float x1 = base[p];
    const float x2 = base[p + 32];
    base[p]      = x1 * c - x2 * sn;
    base[p + 32] = x2 * c + x1 * sn;
}

// ---------------------------------------------------------------------------
// Windowed attention (flash, fp32). Emits hi/lo bf16 split of the output.
// ---------------------------------------------------------------------------
__global__ __launch_bounds__(256) void attn_kernel(
    const float* __restrict__ q, const float* __restrict__ k,
    const float* __restrict__ v,
    __nv_bfloat16* __restrict__ ohi, __nv_bfloat16* __restrict__ olo) {
    __shared__ float Qs[64][68];
    __shared__ float Ks[32][68];
    __shared__ float Vs[32][68];
    __shared__ float Ps[8][8][32];

    const int tid  = threadIdx.x;
    const int lane = tid & 31;
    const int w    = tid >> 5;
    const int t = blockIdx.x;
    const int h = blockIdx.y;
    const int z = blockIdx.z;
    const int b = z >> 4;
    const int n = z & 15;
    const int kvh = h >> 2;

    {
        const size_t qbase = (size_t)(b * S_LEN + n * 256 + t * 64) * 2048 + h * 64;
        for (int idx = tid; idx < 64 * 64; idx += 256) {
            const int r = idx >> 6, d = idx & 63;
            Qs[r][d] = q[qbase + (size_t)r * 2048 + d] * 0.125f;
        }
    }

    float acc0[8], acc1[8], mrow[8], lrow[8];
#pragma unroll
    for (int r = 0; r < 8; r++) { acc0[r] = 0.f; acc1[r] = 0.f; mrow[r] = -1e30f; lrow[r] = 0.f; }

    int c_lo = 2 * t;
    if (n == 0 && c_lo < 8) c_lo = 8;
    int c_hi = 2 * t + 9;
    if (c_hi > 15) c_hi = 15;
    const int i_row = t * 64 + w * 8;

    for (int c = c_lo; c <= c_hi; c++) {
        __syncthreads();
        {
            const int srow0 = b * S_LEN + (n - 1) * 256 + c * 32;
            for (int idx = tid; idx < 32 * 64; idx += 256) {
                const int r = idx >> 6, d = idx & 63;
                const size_t off = (size_t)(srow0 + r) * 512 + kvh * 64 + d;
                Ks[r][d] = k[off];
                Vs[r][d] = v[off];
            }
        }
        __syncthreads();

        float sc[8];
#pragma unroll
        for (int r = 0; r < 8; r++) sc[r] = 0.f;
        const float4* krow = (const float4*)(&Ks[lane][0]);
#pragma unroll
        for (int d4 = 0; d4 < 16; d4++) {
            const float4 kv = krow[d4];
#pragma unroll
            for (int r = 0; r < 8; r++) {
                const float4 qv = *(const float4*)(&Qs[w * 8 + r][d4 * 4]);
                sc[r] += qv.x * kv.x + qv.y * kv.y + qv.z * kv.z + qv.w * kv.w;
            }
        }

        const int j = c * 32 + lane;
        float alpha[8];
#pragma unroll
        for (int r = 0; r < 8; r++) {
            const int i = i_row + r;
            const bool valid = (j >= i) && (j <= i + 256);
            const float s = valid ? sc[r] : -1e30f;
            const float cm = warp_max32(s);
            const float mnew = fmaxf(mrow[r], cm);
            const float p = valid ? __expf(s - mnew) : 0.f;
            const float a = __expf(mrow[r] - mnew);
            lrow[r] = lrow[r] * a + warp_sum32(p);
            mrow[r] = mnew;
            alpha[r] = a;
            Ps[w][r][lane] = p;
        }
        __syncwarp();
#pragma unroll
        for (int r = 0; r < 8; r++) { acc0[r] *= alpha[r]; acc1[r] *= alpha[r]; }

#pragma unroll
        for (int jj4 = 0; jj4 < 8; jj4++) {
            float va[4], vb[4];
#pragma unroll
            for (int u = 0; u < 4; u++) {
                va[u] = Vs[jj4 * 4 + u][lane];
                vb[u] = Vs[jj4 * 4 + u][lane + 32];
            }
#pragma unroll
            for (int r = 0; r < 8; r++) {
                const float4 p4 = *(const float4*)(&Ps[w][r][jj4 * 4]);
                acc0[r] += p4.x * va[0] + p4.y * va[1] + p4.z * va[2] + p4.w * va[3];
                acc1[r] += p4.x * vb[0] + p4.y * vb[1] + p4.z * vb[2] + p4.w * vb[3];
            }
        }
    }

    const size_t obase = (size_t)(b * S_LEN + n * 256 + i_row) * 2048 + h * 64;
#pragma unroll
    for (int r = 0; r < 8; r++) {
        const float invl = 1.f / lrow[r];
        const float v0 = acc0[r] * invl;
        const float v1 = acc1[r] * invl;
        const size_t i0 = obase + (size_t)r * 2048 + lane;
        const size_t i1 = i0 + 32;
        const __nv_bfloat16 h0 = __float2bfloat16(v0);
        const __nv_bfloat16 h1 = __float2bfloat16(v1);
        ohi[i0] = h0;
        ohi[i1] = h1;
        olo[i0] = __float2bfloat16(v0 - __bfloat162float(h0));
        olo[i1] = __float2bfloat16(v1 - __bfloat162float(h1));
    }
}

// ---------------------------------------------------------------------------
// Launch. Order chosen so the ncu capture window (~3rd-4th launch) hits a GEMM.
// ---------------------------------------------------------------------------
extern "C" void kernel_launch(void* const* d_in, const int* in_sizes, int n_in,
                              void* d_out, int out_size) {
    const float* hs = (const float*)d_in[0];
    const float* Wq = (const float*)d_in[1];
    const float* Wk = (const float*)d_in[2];
    const float* Wv = (const float*)d_in[3];
    const float* Wo = (const float*)d_in[4];
    float* out = (float*)d_out;

    float *q, *k, *v;
    __nv_bfloat16 *hs_hi, *hs_lo, *wq_hi, *wq_lo, *wk_hi, *wk_lo;
    __nv_bfloat16 *wv_hi, *wv_lo, *wo_hi, *wo_lo, *att_hi, *att_lo;
    cudaGetSymbolAddress((void**)&q, g_q);
    cudaGetSymbolAddress((void**)&k, g_k);
    cudaGetSymbolAddress((void**)&v, g_v);
    cudaGetSymbolAddress((void**)&hs_hi, g_hs_hi);
    cudaGetSymbolAddress((void**)&hs_lo, g_hs_lo);
    cudaGetSymbolAddress((void**)&wq_hi, g_wq_hi);
    cudaGetSymbolAddress((void**)&wq_lo, g_wq_lo);
    cudaGetSymbolAddress((void**)&wk_hi, g_wk_hi);
    cudaGetSymbolAddress((void**)&wk_lo, g_wk_lo);
    cudaGetSymbolAddress((void**)&wv_hi, g_wv_hi);
    cudaGetSymbolAddress((void**)&wv_lo, g_wv_lo);
    cudaGetSymbolAddress((void**)&wo_hi, g_wo_hi);
    cudaGetSymbolAddress((void**)&wo_lo, g_wo_lo);
    cudaGetSymbolAddress((void**)&att_hi, g_att_hi);
    cudaGetSymbolAddress((void**)&att_lo, g_att_lo);

    cudaFuncSetAttribute(gemm_bf16x3,
                         cudaFuncAttributeMaxDynamicSharedMemorySize, 98304);

    // 1-2: splits needed for Q projection
    split_kernel<<<(M_ROWS * 2048 / 4 + 255) / 256, 256>>>(hs, hs_hi, hs_lo, M_ROWS * 2048 / 4);
    split_kernel<<<(2048 * 2048 / 4 + 255) / 256, 256>>>(Wq, wq_hi, wq_lo, 2048 * 2048 / 4);

    // 3: Q projection (ncu capture target)
    gemm_bf16x3<<<dim3(2048 / 128, M_ROWS / 128), 256, 98304>>>(
        hs_hi, hs_lo, wq_hi, wq_lo, q, M_ROWS, 2048, 2048);

    // 4-7: remaining splits + K/V projections
    split_kernel<<<(512 * 2048 / 4 + 255) / 256, 256>>>(Wk, wk_hi, wk_lo, 512 * 2048 / 4);
    gemm_bf16x3<<<dim3(512 / 128, M_ROWS / 128), 256, 98304>>>(
        hs_hi, hs_lo, wk_hi, wk_lo, k, M_ROWS, 512, 2048);
    split_kernel<<<(512 * 2048 / 4 + 255) / 256, 256>>>(Wv, wv_hi, wv_lo, 512 * 2048 / 4);
    gemm_bf16x3<<<dim3(512 / 128, M_ROWS / 128), 256, 98304>>>(
        hs_hi, hs_lo, wv_hi, wv_lo, v, M_ROWS, 512, 2048);

    // RoPE
    {
        const int total = M_ROWS * 40 * 32;
        rope_kernel<<<(total + 255) / 256, 256>>>(q, k);
    }

    // Attention (emits bf16 hi/lo directly)
    attn_kernel<<<dim3(4, 32, 32), 256>>>(q, k, v, att_hi, att_lo);

    // Output projection
    split_kernel<<<(2048 * 2048 / 4 + 255) / 256, 256>>>(Wo, wo_hi, wo_lo, 2048 * 2048 / 4);
    gemm_bf16x3<<<dim3(2048 / 128, M_ROWS / 128), 256, 98304>>>(
        att_hi, att_lo, wo_hi, wo_lo, out, M_ROWS, 2048, 2048);
}

// round 7
// speedup vs baseline: 2.4351x; 1.2274x over previous
#include <cuda_runtime.h>
#include <cuda_bf16.h>
#include <math.h>

#define M_ROWS 8192
#define S_LEN  4096

// ---------------- scratch ----------------
__device__ float g_q[(size_t)M_ROWS * 2048];
__device__ float g_k[(size_t)M_ROWS * 512];
__device__ float g_v[(size_t)M_ROWS * 512];

__device__ __nv_bfloat16 g_hs_hi[(size_t)M_ROWS * 2048];
__device__ __nv_bfloat16 g_hs_lo[(size_t)M_ROWS * 2048];
__device__ __nv_bfloat16 g_wq_hi[(size_t)2048 * 2048];
__device__ __nv_bfloat16 g_wq_lo[(size_t)2048 * 2048];
__device__ __nv_bfloat16 g_wk_hi[(size_t)512 * 2048];
__device__ __nv_bfloat16 g_wk_lo[(size_t)512 * 2048];
__device__ __nv_bfloat16 g_wv_hi[(size_t)512 * 2048];
__device__ __nv_bfloat16 g_wv_lo[(size_t)512 * 2048];
__device__ __nv_bfloat16 g_wo_hi[(size_t)2048 * 2048];
__device__ __nv_bfloat16 g_wo_lo[(size_t)2048 * 2048];
__device__ __nv_bfloat16 g_att_hi[(size_t)M_ROWS * 2048];
__device__ __nv_bfloat16 g_att_lo[(size_t)M_ROWS * 2048];

__device__ __nv_bfloat16 g_qh[(size_t)M_ROWS * 2048];
__device__ __nv_bfloat16 g_ql[(size_t)M_ROWS * 2048];
__device__ __nv_bfloat16 g_kh[(size_t)M_ROWS * 512];
__device__ __nv_bfloat16 g_kl[(size_t)M_ROWS * 512];
__device__ __nv_bfloat16 g_vh[(size_t)M_ROWS * 512];
__device__ __nv_bfloat16 g_vl[(size_t)M_ROWS * 512];

// ---------------- helpers ----------------
__device__ __forceinline__ unsigned smem_u32(const void* p) {
    unsigned r;
    asm("{ .reg .u64 t; cvta.to.shared.u64 t, %1; cvt.u32.u64 %0, t; }"
        : "=r"(r) : "l"(p));
    return r;
}
__device__ __forceinline__ void cp16(unsigned dst, const void* src) {
    asm volatile("cp.async.cg.shared.global [%0], [%1], 16;\n"
                 :: "r"(dst), "l"(src) : "memory");
}
__device__ __forceinline__ void ldsm4(unsigned* r, unsigned addr) {
    asm volatile("ldmatrix.sync.aligned.m8n8.x4.shared.b16 {%0,%1,%2,%3}, [%4];"
                 : "=r"(r[0]), "=r"(r[1]), "=r"(r[2]), "=r"(r[3]) : "r"(addr));
}
__device__ __forceinline__ void ldsm4t(unsigned* r, unsigned addr) {
    asm volatile("ldmatrix.sync.aligned.m8n8.x4.trans.shared.b16 {%0,%1,%2,%3}, [%4];"
                 : "=r"(r[0]), "=r"(r[1]), "=r"(r[2]), "=r"(r[3]) : "r"(addr));
}
__device__ __forceinline__ void mma16816(float* d, const unsigned* a, const unsigned* b) {
    asm volatile(
        "mma.sync.aligned.m16n8k16.row.col.f32.bf16.bf16.f32 "
        "{%0,%1,%2,%3}, {%4,%5,%6,%7}, {%8,%9}, {%0,%1,%2,%3};"
        : "+f"(d[0]), "+f"(d[1]), "+f"(d[2]), "+f"(d[3])
        : "r"(a[0]), "r"(a[1]), "r"(a[2]), "r"(a[3]), "r"(b[0]), "r"(b[1]));
}
// exp on fma/alu pipes only; arg <= 0 expected; clamp keeps -1e30 harmless.
__device__ __forceinline__ float fexp(float x) {
    float t = fmaxf(x * 1.44269504f, -120.0f);
    float r = t + 12582912.0f;
    int   n = __float_as_int(r) - 0x4B400000;
    float f = t - (r - 12582912.0f);
    float p = 0.00133335581f;
    p = fmaf(p, f, 0.00961812910f);
    p = fmaf(p, f, 0.0555041086f);
    p = fmaf(p, f, 0.240226507f);
    p = fmaf(p, f, 0.693147180f);
    p = fmaf(p, f, 1.0f);
    return __int_as_float(__float_as_int(p) + (n << 23));
}
// (hi,lo) bf16x2 packs of two fp32 values
__device__ __forceinline__ unsigned pack_hl(float a, float b, unsigned* lo) {
    __nv_bfloat16 ha = __float2bfloat16(a), hb = __float2bfloat16(b);
    __nv_bfloat16 la = __float2bfloat16(a - __bfloat162float(ha));
    __nv_bfloat16 lb = __float2bfloat16(b - __bfloat162float(hb));
    __nv_bfloat162 H; H.x = ha; H.y = hb;
    __nv_bfloat162 L; L.x = la; L.y = lb;
    *lo = *(unsigned*)&L;
    return *(unsigned*)&H;
}

// ---------------- split ----------------
__global__ void split_kernel(const float* __restrict__ x,
                             __nv_bfloat16* __restrict__ hi,
                             __nv_bfloat16* __restrict__ lo, int n4) {
    const int i = blockIdx.x * 256 + threadIdx.x;
    if (i >= n4) return;
    const float4 vv = ((const float4*)x)[i];
    float f[4] = {vv.x, vv.y, vv.z, vv.w};
    __nv_bfloat16 h[4], l[4];
#pragma unroll
    for (int j = 0; j < 4; j++) {
        h[j] = __float2bfloat16(f[j]);
        l[j] = __float2bfloat16(f[j] - __bfloat162float(h[j]));
    }
    __nv_bfloat162* H = (__nv_bfloat162*)hi;
    __nv_bfloat162* L = (__nv_bfloat162*)lo;
    __nv_bfloat162 t;
    t.x = h[0]; t.y = h[1]; H[2 * i]     = t;
    t.x = h[2]; t.y = h[3]; H[2 * i + 1] = t;
    t.x = l[0]; t.y = l[1]; L[2 * i]     = t;
    t.x = l[2]; t.y = l[3]; L[2 * i + 1] = t;
}

// ---------------- bf16x3 GEMM (NT) — unchanged, at HMMA ceiling ----------------
#define GSTAGE 32768u

__global__ __launch_bounds__(256, 2) void gemm_bf16x3(
    const __nv_bfloat16* __restrict__ Ahi, const __nv_bfloat16* __restrict__ Alo,
    const __nv_bfloat16* __restrict__ Whi, const __nv_bfloat16* __restrict__ Wlo,
    float* __restrict__ C, int M, int N, int K) {
    extern __shared__ __align__(16) unsigned char smraw[];
    const unsigned sbase = smem_u32(smraw);

    const int tid = threadIdx.x;
    const int wid = tid >> 5, lane = tid & 31;
    const int warp_m = wid >> 2;
    const int warp_n = wid & 3;
    const int m0 = blockIdx.y << 7;
    const int n0 = blockIdx.x << 7;

    const __nv_bfloat16* srcs[4] = {
        Ahi + (size_t)m0 * K, Alo + (size_t)m0 * K,
        Whi + (size_t)n0 * K, Wlo + (size_t)n0 * K};

    float acc[4][4][4];
#pragma unroll
    for (int i = 0; i < 4; i++)
#pragma unroll
        for (int j = 0; j < 4; j++)
#pragma unroll
            for (int u = 0; u < 4; u++) acc[i][j][u] = 0.f;

    const int ldr = tid >> 1;
    const int ldc = (tid & 1) * 2;

    auto prefetch = [&](int it, int bufi) {
        const int k0 = it * 32;
        const unsigned bufbase = sbase + (unsigned)bufi * GSTAGE;
#pragma unroll
        for (int p = 0; p < 4; p++) {
            const __nv_bfloat16* src = srcs[p] + (size_t)ldr * K + k0 + ldc * 8;
            const unsigned splane = bufbase + p * 8192u;
#pragma unroll
            for (int cc = 0; cc < 2; cc++) {
                const int c = ldc + cc;
                const unsigned dst =
                    splane + ldr * 64u + (unsigned)((c ^ ((ldr >> 1) & 3)) << 4);
                cp16(dst, src + cc * 8);
            }
        }
    };

    auto compute = [&](int bufi) {
        const unsigned base = sbase + (unsigned)bufi * GSTAGE;
        const int arow = (lane & 7) + ((lane >> 3) & 1) * 8;
        const int khalf = (lane >> 4) & 1;
#pragma unroll
        for (int ks = 0; ks < 2; ks++) {
            const int c = ks * 2 + khalf;
            unsigned bhi[4][2], blo[4][2];
#pragma unroll
            for (int half = 0; half < 2; half++) {
                const int row = warp_n * 32 + half * 16 + arow;
                const unsigned off =
                    row * 64u + (unsigned)((c ^ ((row >> 1) & 3)) << 4);
                unsigned t[4];
                ldsm4(t, base + 16384u + off);
                bhi[half * 2 + 0][0] = t[0]; bhi[half * 2 + 0][1] = t[2];
                bhi[half * 2 + 1][0] = t[1]; bhi[half * 2 + 1][1] = t[3];
                ldsm4(t, base + 24576u + off);
                blo[half * 2 + 0][0] = t[0]; blo[half * 2 + 0][1] = t[2];
                blo[half * 2 + 1][0] = t[1]; blo[half * 2 + 1][1] = t[3];
            }
#pragma unroll
            for (int i = 0; i < 4; i++) {
                const int row = warp_m * 64 + i * 16 + arow;
                const unsigned off =
                    row * 64u + (unsigned)((c ^ ((row >> 1) & 3)) << 4);
                unsigned ahi[4], alo[4];
                ldsm4(ahi, base + off);
                ldsm4(alo, base + 8192u + off);
#pragma unroll
                for (int j = 0; j < 4; j++) {
                    mma16816(acc[i][j], ahi, bhi[j]);
                    mma16816(acc[i][j], ahi, blo[j]);
                    mma16816(acc[i][j], alo, bhi[j]);
                }
            }
        }
    };

    const int NIT = K >> 5;
    prefetch(0, 0);
    asm volatile("cp.async.commit_group;\n" ::: "memory");
    prefetch(1, 1);
    asm volatile("cp.async.commit_group;\n" ::: "memory");

    for (int it = 0; it < NIT; it++) {
        if (it + 2 < NIT) {
            prefetch(it + 2, (it + 2) % 3);
            asm volatile("cp.async.commit_group;\n" ::: "memory");
            asm volatile("cp.async.wait_group 2;\n" ::: "memory");
        } else if (it + 1 < NIT) {
            asm volatile("cp.async.wait_group 1;\n" ::: "memory");
        } else {
            asm volatile("cp.async.wait_group 0;\n" ::: "memory");
        }
        __syncthreads();
        compute(it % 3);
        __syncthreads();
    }

#pragma unroll
    for (int i = 0; i < 4; i++)
#pragma unroll
        for (int j = 0; j < 4; j++) {
            const int r0 = m0 + warp_m * 64 + i * 16 + (lane >> 2);
            const int cc = n0 + warp_n * 32 + j * 8 + (lane & 3) * 2;
            float2 u;
            u.x = acc[i][j][0]; u.y = acc[i][j][1];
            *(float2*)(C + (size_t)r0 * N + cc) = u;
            u.x = acc[i][j][2]; u.y = acc[i][j][3];
            *(float2*)(C + (size_t)(r0 + 8) * N + cc) = u;
        }
}

// ---------------- RoPE + bf16 hi/lo split (Q scaled 0.125) ----------------
__global__ void rope_split_kernel(
    const float* __restrict__ q, const float* __restrict__ k,
    __nv_bfloat16* __restrict__ qh, __nv_bfloat16* __restrict__ ql,
    __nv_bfloat16* __restrict__ kh, __nv_bfloat16* __restrict__ kl) {
    const int idx = blockIdx.x * 256 + threadIdx.x;
    const int total = M_ROWS * 40 * 32;
    if (idx >= total) return;
    const int p = idx & 31;
    const int rest = idx >> 5;
    const int head = rest % 40;
    const int m = rest / 40;
    const int s = m & (S_LEN - 1);

    const float invf = exp2f(-(float)p * 0.41524101186092027f);
    const float ang = (float)s * invf;
    float sn, c;
    sincosf(ang, &sn, &c);

    float x1, x2, scale;
    size_t o;
    __nv_bfloat16 *dh, *dl;
    if (head < 32) {
        o = (size_t)m * 2048 + head * 64;
        x1 = q[o + p]; x2 = q[o + p + 32];
        scale = 0.125f; dh = qh; dl = ql;
    } else {
        o = (size_t)m * 512 + (head - 32) * 64;
        x1 = k[o + p]; x2 = k[o + p + 32];
        scale = 1.0f; dh = kh; dl = kl;
    }
    const float y1 = (x1 * c - x2 * sn) * scale;
    const float y2 = (x2 * c + x1 * sn) * scale;
    const __nv_bfloat16 h1 = __float2bfloat16(y1);
    const __nv_bfloat16 h2 = __float2bfloat16(y2);
    dh[o + p]      = h1;
    dh[o + p + 32] = h2;
    dl[o + p]      = __float2bfloat16(y1 - __bfloat162float(h1));
    dl[o + p + 32] = __float2bfloat16(y2 - __bfloat162float(h2));
}

// ---------------- tensor-core windowed attention ----------------
// grid (2, 32, 32): (q-tile of 128, head, b*16+n). 256 threads = 8 warps,
// warp w owns q rows t128*128 + [16w, 16w+15]. Key chunks of 64 within the
// 512-key window; online softmax in registers (fexp, no MUFU); P stays in
// registers (S-frag -> A-frag). V via ldmatrix.trans. Emits att hi/lo bf16.
// smem (dynamic, 73728B): Qhi[128x144] Qlo | Khi[64x144] Klo Vhi Vlo.
__global__ __launch_bounds__(256) void attn_tc(
    const __nv_bfloat16* __restrict__ qh_, const __nv_bfloat16* __restrict__ ql_,
    const __nv_bfloat16* __restrict__ kh_, const __nv_bfloat16* __restrict__ kl_,
    const __nv_bfloat16* __restrict__ vh_, const __nv_bfloat16* __restrict__ vl_,
    __nv_bfloat16* __restrict__ ohi, __nv_bfloat16* __restrict__ olo) {
    extern __shared__ __align__(16) unsigned char smraw[];
    const unsigned SB = smem_u32(smraw);
    const unsigned QHI = SB, QLO = SB + 18432u;
    const unsigned KHI = SB + 36864u;  // + p*9216 for KLO/VHI/VLO

    const int tid = threadIdx.x, lane = tid & 31, w = tid >> 5;
    const int t128 = blockIdx.x;
    const int h = blockIdx.y;
    const int z = blockIdx.z;
    const int b = z >> 4, n = z & 15;
    const int kvh = h >> 2;

    // Q tile: 128 rows x 64 bf16, hi+lo
    {
        const size_t qrow0 = (size_t)(b * S_LEN + n * 256 + t128 * 128);
        for (int g = tid; g < 2048; g += 256) {
            const int p = g >> 10, r = (g >> 3) & 127, c8 = g & 7;
            const __nv_bfloat16* src =
                (p ? ql_ : qh_) + (qrow0 + r) * 2048 + h * 64 + c8 * 8;
            cp16((p ? QLO : QHI) + (unsigned)r * 144u + (unsigned)c8 * 16u, src);
        }
        asm volatile("cp.async.commit_group;\n" ::: "memory");
        asm volatile("cp.async.wait_group 0;\n" ::: "memory");
        __syncthreads();
    }

    // Q fragments, held for all chunks
    unsigned qfh[4][4], qfl[4][4];
    {
        const unsigned rr = (unsigned)(w * 16 + (lane & 15));
        const unsigned cb = (unsigned)((lane >> 4) * 16);
#pragma unroll
        for (int ks = 0; ks < 4; ks++) {
            ldsm4(qfh[ks], QHI + rr * 144u + (unsigned)ks * 32u + cb);
            ldsm4(qfl[ks], QLO + rr * 144u + (unsigned)ks * 32u + cb);
        }
    }

    float oacc[8][4];
#pragma unroll
    for (int j = 0; j < 8; j++)
#pragma unroll
        for (int u = 0; u < 4; u++) oacc[j][u] = 0.f;
    float m0 = -1e30f, m1 = -1e30f, l0 = 0.f, l1 = 0.f;

    const int rbase = t128 * 128 + w * 16 + (lane >> 2);  // window row (c0/c1)
    int c_lo = 2 * t128;
    if (n == 0 && c_lo < 4) c_lo = 4;
    const int c_hi = (t128 == 0) ? 5 : 7;

    for (int c = c_lo; c <= c_hi; c++) {
        __syncthreads();  // prior chunk's smem reads complete
        {
            const size_t srow0 = (size_t)(b * S_LEN + (n - 1) * 256 + c * 64);
            for (int g = tid; g < 2048; g += 256) {
                const int p = g >> 9, r = (g >> 3) & 63, c8 = g & 7;
                const __nv_bfloat16* sp =
                    (p == 0 ? kh_ : p == 1 ? kl_ : p == 2 ? vh_ : vl_);
                cp16(KHI + (unsigned)p * 9216u + (unsigned)r * 144u +
                         (unsigned)c8 * 16u,
                     sp + (srow0 + r) * 512 + kvh * 64 + c8 * 8);
            }
            asm volatile("cp.async.commit_group;\n" ::: "memory");
            asm volatile("cp.async.wait_group 0;\n" ::: "memory");
            __syncthreads();
        }

        // ---- scores: 16 rows x 64 keys ----
        float sf[8][4];
#pragma unroll
        for (int j = 0; j < 8; j++)
#pragma unroll
            for (int u = 0; u < 4; u++) sf[j][u] = 0.f;

        const unsigned kb = (unsigned)((lane >> 4) * 16);
#pragma unroll
        for (int ks = 0; ks < 4; ks++) {
#pragma unroll
            for (int kg = 0; kg < 4; kg++) {
                const unsigned off = (unsigned)(kg * 16 + (lane & 15)) * 144u +
                                     (unsigned)ks * 32u + kb;
                unsigned th[4], tl[4];
                ldsm4(th, KHI + off);
                ldsm4(tl, KHI + 9216u + off);
                unsigned bh0[2] = {th[0], th[2]}, bh1[2] = {th[1], th[3]};
                unsigned bl0[2] = {tl[0], tl[2]}, bl1[2] = {tl[1], tl[3]};
                mma16816(sf[2 * kg], qfh[ks], bh0);
                mma16816(sf[2 * kg], qfh[ks], bl0);
                mma16816(sf[2 * kg], qfl[ks], bh0);
                mma16816(sf[2 * kg + 1], qfh[ks], bh1);
                mma16816(sf[2 * kg + 1], qfh[ks], bl1);
                mma16816(sf[2 * kg + 1], qfl[ks], bh1);
            }
        }

        // ---- mask + online softmax (no MUFU) ----
        const int jb = c * 64 + (lane & 3) * 2;
        const float NEG = -1e30f;
#pragma unroll
        for (int j8 = 0; j8 < 8; j8++) {
            const int j0 = jb + j8 * 8;
            if (j0 < rbase     || j0 > rbase + 256) sf[j8][0] = NEG;
            if (j0 + 1 < rbase || j0 + 1 > rbase + 256) sf[j8][1] = NEG;
            if (j0 < rbase + 8 || j0 > rbase + 264) sf[j8][2] = NEG;
            if (j0 + 1 < rbase + 8 || j0 + 1 > rbase + 264) sf[j8][3] = NEG;
        }
        float mx0 = NEG, mx1 = NEG;
#pragma unroll
        for (int j8 = 0; j8 < 8; j8++) {
            mx0 = fmaxf(mx0, fmaxf(sf[j8][0], sf[j8][1]));
            mx1 = fmaxf(mx1, fmaxf(sf[j8][2], sf[j8][3]));
        }
        mx0 = fmaxf(mx0, __shfl_xor_sync(0xffffffffu, mx0, 1));
        mx0 = fmaxf(mx0, __shfl_xor_sync(0xffffffffu, mx0, 2));
        mx1 = fmaxf(mx1, __shfl_xor_sync(0xffffffffu, mx1, 1));
        mx1 = fmaxf(mx1, __shfl_xor_sync(0xffffffffu, mx1, 2));
        const float mn0 = fmaxf(m0, mx0), mn1 = fmaxf(m1, mx1);
        const float a0 = fexp(m0 - mn0), a1 = fexp(m1 - mn1);
        m0 = mn0; m1 = mn1;
        float s0 = 0.f, s1 = 0.f;
#pragma unroll
        for (int j8 = 0; j8 < 8; j8++) {
            sf[j8][0] = fexp(sf[j8][0] - mn0);
            sf[j8][1] = fexp(sf[j8][1] - mn0);
            sf[j8][2] = fexp(sf[j8][2] - mn1);
            sf[j8][3] = fexp(sf[j8][3] - mn1);
            s0 += sf[j8][0] + sf[j8][1];
            s1 += sf[j8][2] + sf[j8][3];
        }
        s0 += __shfl_xor_sync(0xffffffffu, s0, 1);
        s0 += __shfl_xor_sync(0xffffffffu, s0, 2);
        s1 += __shfl_xor_sync(0xffffffffu, s1, 1);
        s1 += __shfl_xor_sync(0xffffffffu, s1, 2);
        l0 = l0 * a0 + s0;
        l1 = l1 * a1 + s1;
#pragma unroll
        for (int j = 0; j < 8; j++) {
            oacc[j][0] *= a0; oacc[j][1] *= a0;
            oacc[j][2] *= a1; oacc[j][3] *= a1;
        }

        // ---- PV: P (regs) x V (ldmatrix.trans) ----
#pragma unroll
        for (int kg = 0; kg < 4; kg++) {
            unsigned pah[4], pal[4];
            pah[0] = pack_hl(sf[2 * kg][0],     sf[2 * kg][1],     &pal[0]);
            pah[1] = pack_hl(sf[2 * kg][2],     sf[2 * kg][3],     &pal[1]);
            pah[2] = pack_hl(sf[2 * kg + 1][0], sf[2 * kg + 1][1], &pal[2]);
            pah[3] = pack_hl(sf[2 * kg + 1][2], sf[2 * kg + 1][3], &pal[3]);
            const unsigned vrow =
                (unsigned)(kg * 16 + ((lane >> 3) & 1) * 8 + (lane & 7)) * 144u;
#pragma unroll
            for (int dh = 0; dh < 4; dh++) {
                const unsigned voff =
                    vrow + (unsigned)dh * 32u + (unsigned)(lane >> 4) * 16u;
                unsigned vh4[4], vl4[4];
                ldsm4t(vh4, KHI + 18432u + voff);
                ldsm4t(vl4, KHI + 27648u + voff);
                unsigned vbh0[2] = {vh4[0], vh4[1]}, vbh1[2] = {vh4[2], vh4[3]};
                unsigned vbl0[2] = {vl4[0], vl4[1]}, vbl1[2] = {vl4[2], vl4[3]};
                mma16816(oacc[2 * dh], pah, vbh0);
                mma16816(oacc[2 * dh], pah, vbl0);
                mma16816(oacc[2 * dh], pal, vbh0);
                mma16816(oacc[2 * dh + 1], pah, vbh1);
                mma16816(oacc[2 * dh + 1], pah, vbl1);
                mma16816(oacc[2 * dh + 1], pal, vbh1);
            }
        }
    }

    // ---- epilogue: normalize, split hi/lo, store ----
    const float inv0 = 1.f / l0, inv1 = 1.f / l1;
    const size_t grow0 =
        (size_t)(b * S_LEN + n * 256 + t128 * 128 + w * 16 + (lane >> 2));
    const int colb = h * 64 + (lane & 3) * 2;
#pragma unroll
    for (int j8 = 0; j8 < 8; j8++) {
        unsigned hi0, lo0, hi1, lo1;
        hi0 = pack_hl(oacc[j8][0] * inv0, oacc[j8][1] * inv0, &lo0);
        hi1 = pack_hl(oacc[j8][2] * inv1, oacc[j8][3] * inv1, &lo1);
        const size_t i0 = grow0 * 2048 + colb + j8 * 8;
        const size_t i1 = i0 + 8 * 2048;
        *(unsigned*)(ohi + i0) = hi0;
        *(unsigned*)(olo + i0) = lo0;
        *(unsigned*)(ohi + i1) = hi1;
        *(unsigned*)(olo + i1) = lo1;
    }
}

// ---------------- launch ----------------
extern "C" void kernel_launch(void* const* d_in, const int* in_sizes, int n_in,
                              void* d_out, int out_size) {
    const float* hs = (const float*)d_in[0];
    const float* Wq = (const float*)d_in[1];
    const float* Wk = (const float*)d_in[2];
    const float* Wv = (const float*)d_in[3];
    const float* Wo = (const float*)d_in[4];
    float* out = (float*)d_out;

    float *q, *k, *v;
    __nv_bfloat16 *hs_hi, *hs_lo, *wq_hi, *wq_lo, *wk_hi, *wk_lo;
    __nv_bfloat16 *wv_hi, *wv_lo, *wo_hi, *wo_lo, *att_hi, *att_lo;
    __nv_bfloat16 *qh, *ql, *kh, *kl, *vh, *vl;
    cudaGetSymbolAddress((void**)&q, g_q);
    cudaGetSymbolAddress((void**)&k, g_k);
    cudaGetSymbolAddress((void**)&v, g_v);
    cudaGetSymbolAddress((void**)&hs_hi, g_hs_hi);
    cudaGetSymbolAddress((void**)&hs_lo, g_hs_lo);
    cudaGetSymbolAddress((void**)&wq_hi, g_wq_hi);
    cudaGetSymbolAddress((void**)&wq_lo, g_wq_lo);
    cudaGetSymbolAddress((void**)&wk_hi, g_wk_hi);
    cudaGetSymbolAddress((void**)&wk_lo, g_wk_lo);
    cudaGetSymbolAddress((void**)&wv_hi, g_wv_hi);
    cudaGetSymbolAddress((void**)&wv_lo, g_wv_lo);
    cudaGetSymbolAddress((void**)&wo_hi, g_wo_hi);
    cudaGetSymbolAddress((void**)&wo_lo, g_wo_lo);
    cudaGetSymbolAddress((void**)&att_hi, g_att_hi);
    cudaGetSymbolAddress((void**)&att_lo, g_att_lo);
    cudaGetSymbolAddress((void**)&qh, g_qh);
    cudaGetSymbolAddress((void**)&ql, g_ql);
    cudaGetSymbolAddress((void**)&kh, g_kh);
    cudaGetSymbolAddress((void**)&kl, g_kl);
    cudaGetSymbolAddress((void**)&vh, g_vh);
    cudaGetSymbolAddress((void**)&vl, g_vl);

    cudaFuncSetAttribute(gemm_bf16x3,
                         cudaFuncAttributeMaxDynamicSharedMemorySize, 98304);
    cudaFuncSetAttribute(attn_tc,
                         cudaFuncAttributeMaxDynamicSharedMemorySize, 73728);

    // launches 0-2, then gemmQ at #3 (ncu capture slot)
    split_kernel<<<(M_ROWS * 2048 / 4 + 255) / 256, 256>>>(hs, hs_hi, hs_lo, M_ROWS * 2048 / 4);
    split_kernel<<<(2048 * 2048 / 4 + 255) / 256, 256>>>(Wq, wq_hi, wq_lo, 2048 * 2048 / 4);
    split_kernel<<<(512 * 2048 / 4 + 255) / 256, 256>>>(Wk, wk_hi, wk_lo, 512 * 2048 / 4);
    gemm_bf16x3<<<dim3(2048 / 128, M_ROWS / 128), 256, 98304>>>(
        hs_hi, hs_lo, wq_hi, wq_lo, q, M_ROWS, 2048, 2048);
    gemm_bf16x3<<<dim3(512 / 128, M_ROWS / 128), 256, 98304>>>(
        hs_hi, hs_lo, wk_hi, wk_lo, k, M_ROWS, 512, 2048);
    split_kernel<<<(512 * 2048 / 4 + 255) / 256, 256>>>(Wv, wv_hi, wv_lo, 512 * 2048 / 4);
    gemm_bf16x3<<<dim3(512 / 128, M_ROWS / 128), 256, 98304>>>(
        hs_hi, hs_lo, wv_hi, wv_lo, v, M_ROWS, 512, 2048);

    // RoPE + Q/K splits; V split
    rope_split_kernel<<<(M_ROWS * 40 * 32 + 255) / 256, 256>>>(q, k, qh, ql, kh, kl);
    split_kernel<<<(M_ROWS * 512 / 4 + 255) / 256, 256>>>(v, vh, vl, M_ROWS * 512 / 4);

    // Tensor-core attention
    attn_tc<<<dim3(2, 32, 32), 256, 73728>>>(qh, ql, kh, kl, vh, vl, att_hi, att_lo);

    // Output projection
    split_kernel<<<(2048 * 2048 / 4 + 255) / 256, 256>>>(Wo, wo_hi, wo_lo, 2048 * 2048 / 4);
    gemm_bf16x3<<<dim3(2048 / 128, M_ROWS / 128), 256, 98304>>>(
        att_hi, att_lo, wo_hi, wo_lo, out, M_ROWS, 2048, 2048);
}

// round 8
// speedup vs baseline: 2.4728x; 1.0155x over previous
#include <cuda_runtime.h>
#include <cuda_bf16.h>
#include <math.h>

#define M_ROWS 8192
#define S_LEN  4096

// ---------------- scratch ----------------
__device__ float g_q[(size_t)M_ROWS * 2048];
__device__ float g_k[(size_t)M_ROWS * 512];
__device__ float g_v[(size_t)M_ROWS * 512];

__device__ __nv_bfloat16 g_hs_hi[(size_t)M_ROWS * 2048];
__device__ __nv_bfloat16 g_hs_lo[(size_t)M_ROWS * 2048];
__device__ __nv_bfloat16 g_wq_hi[(size_t)2048 * 2048];
__device__ __nv_bfloat16 g_wq_lo[(size_t)2048 * 2048];
__device__ __nv_bfloat16 g_wk_hi[(size_t)512 * 2048];
__device__ __nv_bfloat16 g_wk_lo[(size_t)512 * 2048];
__device__ __nv_bfloat16 g_wv_hi[(size_t)512 * 2048];
__device__ __nv_bfloat16 g_wv_lo[(size_t)512 * 2048];
__device__ __nv_bfloat16 g_wo_hi[(size_t)2048 * 2048];
__device__ __nv_bfloat16 g_wo_lo[(size_t)2048 * 2048];
__device__ __nv_bfloat16 g_att_hi[(size_t)M_ROWS * 2048];
__device__ __nv_bfloat16 g_att_lo[(size_t)M_ROWS * 2048];

__device__ __nv_bfloat16 g_qh[(size_t)M_ROWS * 2048];
__device__ __nv_bfloat16 g_ql[(size_t)M_ROWS * 2048];
__device__ __nv_bfloat16 g_kh[(size_t)M_ROWS * 512];
__device__ __nv_bfloat16 g_kl[(size_t)M_ROWS * 512];
__device__ __nv_bfloat16 g_vh[(size_t)M_ROWS * 512];
__device__ __nv_bfloat16 g_vl[(size_t)M_ROWS * 512];

// ---------------- helpers ----------------
__device__ __forceinline__ unsigned smem_u32(const void* p) {
    unsigned r;
    asm("{ .reg .u64 t; cvta.to.shared.u64 t, %1; cvt.u32.u64 %0, t; }"
        : "=r"(r) : "l"(p));
    return r;
}
__device__ __forceinline__ void cp16(unsigned dst, const void* src) {
    asm volatile("cp.async.cg.shared.global [%0], [%1], 16;\n"
                 :: "r"(dst), "l"(src) : "memory");
}
__device__ __forceinline__ void ldsm4(unsigned* r, unsigned addr) {
    asm volatile("ldmatrix.sync.aligned.m8n8.x4.shared.b16 {%0,%1,%2,%3}, [%4];"
                 : "=r"(r[0]), "=r"(r[1]), "=r"(r[2]), "=r"(r[3]) : "r"(addr));
}
__device__ __forceinline__ void ldsm4t(unsigned* r, unsigned addr) {
    asm volatile("ldmatrix.sync.aligned.m8n8.x4.trans.shared.b16 {%0,%1,%2,%3}, [%4];"
                 : "=r"(r[0]), "=r"(r[1]), "=r"(r[2]), "=r"(r[3]) : "r"(addr));
}
__device__ __forceinline__ void mma16816(float* d, const unsigned* a, const unsigned* b) {
    asm volatile(
        "mma.sync.aligned.m16n8k16.row.col.f32.bf16.bf16.f32 "
        "{%0,%1,%2,%3}, {%4,%5,%6,%7}, {%8,%9}, {%0,%1,%2,%3};"
        : "+f"(d[0]), "+f"(d[1]), "+f"(d[2]), "+f"(d[3])
        : "r"(a[0]), "r"(a[1]), "r"(a[2]), "r"(a[3]), "r"(b[0]), "r"(b[1]));
}
// exp on fma/alu pipes only; arg <= 0 expected; clamp keeps -1e30 harmless.
__device__ __forceinline__ float fexp(float x) {
    float t = fmaxf(x * 1.44269504f, -120.0f);
    float r = t + 12582912.0f;
    int   n = __float_as_int(r) - 0x4B400000;
    float f = t - (r - 12582912.0f);
    float p = 0.00133335581f;
    p = fmaf(p, f, 0.00961812910f);
    p = fmaf(p, f, 0.0555041086f);
    p = fmaf(p, f, 0.240226507f);
    p = fmaf(p, f, 0.693147180f);
    p = fmaf(p, f, 1.0f);
    return __int_as_float(__float_as_int(p) + (n << 23));
}
__device__ __forceinline__ unsigned pack_hl(float a, float b, unsigned* lo) {
    __nv_bfloat16 ha = __float2bfloat16(a), hb = __float2bfloat16(b);
    __nv_bfloat16 la = __float2bfloat16(a - __bfloat162float(ha));
    __nv_bfloat16 lb = __float2bfloat16(b - __bfloat162float(hb));
    __nv_bfloat162 H; H.x = ha; H.y = hb;
    __nv_bfloat162 L; L.x = la; L.y = lb;
    *lo = *(unsigned*)&L;
    return *(unsigned*)&H;
}

// ---------------- split ----------------
__global__ void split_kernel(const float* __restrict__ x,
                             __nv_bfloat16* __restrict__ hi,
                             __nv_bfloat16* __restrict__ lo, int n4) {
    const int i = blockIdx.x * 256 + threadIdx.x;
    if (i >= n4) return;
    const float4 vv = ((const float4*)x)[i];
    float f[4] = {vv.x, vv.y, vv.z, vv.w};
    __nv_bfloat16 h[4], l[4];
#pragma unroll
    for (int j = 0; j < 4; j++) {
        h[j] = __float2bfloat16(f[j]);
        l[j] = __float2bfloat16(f[j] - __bfloat162float(h[j]));
    }
    __nv_bfloat162* H = (__nv_bfloat162*)hi;
    __nv_bfloat162* L = (__nv_bfloat162*)lo;
    __nv_bfloat162 t;
    t.x = h[0]; t.y = h[1]; H[2 * i]     = t;
    t.x = h[2]; t.y = h[3]; H[2 * i + 1] = t;
    t.x = l[0]; t.y = l[1]; L[2 * i]     = t;
    t.x = l[2]; t.y = l[3]; L[2 * i + 1] = t;
}

// ---------------- bf16x3 GEMM (NT) ----------------
// Pass-grouped mma order (hh over j, hl over j, lh over j) -> acc reuse
// distance 4 instead of 1. Single __syncthreads per K-tile.
#define GSTAGE 32768u

__global__ __launch_bounds__(256, 2) void gemm_bf16x3(
    const __nv_bfloat16* __restrict__ Ahi, const __nv_bfloat16* __restrict__ Alo,
    const __nv_bfloat16* __restrict__ Whi, const __nv_bfloat16* __restrict__ Wlo,
    float* __restrict__ C, int M, int N, int K) {
    extern __shared__ __align__(16) unsigned char smraw[];
    const unsigned sbase = smem_u32(smraw);

    const int tid = threadIdx.x;
    const int wid = tid >> 5, lane = tid & 31;
    const int warp_m = wid >> 2;
    const int warp_n = wid & 3;
    const int m0 = blockIdx.y << 7;
    const int n0 = blockIdx.x << 7;

    const __nv_bfloat16* srcs[4] = {
        Ahi + (size_t)m0 * K, Alo + (size_t)m0 * K,
        Whi + (size_t)n0 * K, Wlo + (size_t)n0 * K};

    float acc[4][4][4];
#pragma unroll
    for (int i = 0; i < 4; i++)
#pragma unroll
        for (int j = 0; j < 4; j++)
#pragma unroll
            for (int u = 0; u < 4; u++) acc[i][j][u] = 0.f;

    const int ldr = tid >> 1;
    const int ldc = (tid & 1) * 2;

    auto prefetch = [&](int it, int bufi) {
        const int k0 = it * 32;
        const unsigned bufbase = sbase + (unsigned)bufi * GSTAGE;
#pragma unroll
        for (int p = 0; p < 4; p++) {
            const __nv_bfloat16* src = srcs[p] + (size_t)ldr * K + k0 + ldc * 8;
            const unsigned splane = bufbase + p * 8192u;
#pragma unroll
            for (int cc = 0; cc < 2; cc++) {
                const int c = ldc + cc;
                const unsigned dst =
                    splane + ldr * 64u + (unsigned)((c ^ ((ldr >> 1) & 3)) << 4);
                cp16(dst, src + cc * 8);
            }
        }
    };

    auto compute = [&](int bufi) {
        const unsigned base = sbase + (unsigned)bufi * GSTAGE;
        const int arow = (lane & 7) + ((lane >> 3) & 1) * 8;
        const int khalf = (lane >> 4) & 1;
#pragma unroll
        for (int ks = 0; ks < 2; ks++) {
            const int c = ks * 2 + khalf;
            unsigned bhi[4][2], blo[4][2];
#pragma unroll
            for (int half = 0; half < 2; half++) {
                const int row = warp_n * 32 + half * 16 + arow;
                const unsigned off =
                    row * 64u + (unsigned)((c ^ ((row >> 1) & 3)) << 4);
                unsigned t[4];
                ldsm4(t, base + 16384u + off);
                bhi[half * 2 + 0][0] = t[0]; bhi[half * 2 + 0][1] = t[2];
                bhi[half * 2 + 1][0] = t[1]; bhi[half * 2 + 1][1] = t[3];
                ldsm4(t, base + 24576u + off);
                blo[half * 2 + 0][0] = t[0]; blo[half * 2 + 0][1] = t[2];
                blo[half * 2 + 1][0] = t[1]; blo[half * 2 + 1][1] = t[3];
            }
#pragma unroll
            for (int i = 0; i < 4; i++) {
                const int row = warp_m * 64 + i * 16 + arow;
                const unsigned off =
                    row * 64u + (unsigned)((c ^ ((row >> 1) & 3)) << 4);
                unsigned ahi[4], alo[4];
                ldsm4(ahi, base + off);
                ldsm4(alo, base + 8192u + off);
                // pass-grouped: same acc reused only every 4 mmas
#pragma unroll
                for (int j = 0; j < 4; j++) mma16816(acc[i][j], ahi, bhi[j]);
#pragma unroll
                for (int j = 0; j < 4; j++) mma16816(acc[i][j], ahi, blo[j]);
#pragma unroll
                for (int j = 0; j < 4; j++) mma16816(acc[i][j], alo, bhi[j]);
            }
        }
    };

    const int NIT = K >> 5;
    prefetch(0, 0);
    asm volatile("cp.async.commit_group;\n" ::: "memory");
    prefetch(1, 1);
    asm volatile("cp.async.commit_group;\n" ::: "memory");

    for (int it = 0; it < NIT; it++) {
        if (it + 1 < NIT) {
            asm volatile("cp.async.wait_group 1;\n" ::: "memory");
        } else {
            asm volatile("cp.async.wait_group 0;\n" ::: "memory");
        }
        __syncthreads();
        // Stage (it+2)%3 == (it-1)%3: the barrier above guarantees everyone
        // has finished compute(it-1), so refilling it now is safe.
        if (it + 2 < NIT) {
            prefetch(it + 2, (it + 2) % 3);
            asm volatile("cp.async.commit_group;\n" ::: "memory");
        }
        compute(it % 3);
    }

#pragma unroll
    for (int i = 0; i < 4; i++)
#pragma unroll
        for (int j = 0; j < 4; j++) {
            const int r0 = m0 + warp_m * 64 + i * 16 + (lane >> 2);
            const int cc = n0 + warp_n * 32 + j * 8 + (lane & 3) * 2;
            float2 u;
            u.x = acc[i][j][0]; u.y = acc[i][j][1];
            *(float2*)(C + (size_t)r0 * N + cc) = u;
            u.x = acc[i][j][2]; u.y = acc[i][j][3];
            *(float2*)(C + (size_t)(r0 + 8) * N + cc) = u;
        }
}

// ---------------- RoPE + bf16 hi/lo split (Q scaled 0.125) ----------------
__global__ void rope_split_kernel(
    const float* __restrict__ q, const float* __restrict__ k,
    __nv_bfloat16* __restrict__ qh, __nv_bfloat16* __restrict__ ql,
    __nv_bfloat16* __restrict__ kh, __nv_bfloat16* __restrict__ kl) {
    const int idx = blockIdx.x * 256 + threadIdx.x;
    const int total = M_ROWS * 40 * 32;
    if (idx >= total) return;
    const int p = idx & 31;
    const int rest = idx >> 5;
    const int head = rest % 40;
    const int m = rest / 40;
    const int s = m & (S_LEN - 1);

    const float invf = exp2f(-(float)p * 0.41524101186092027f);
    const float ang = (float)s * invf;
    float sn, c;
    sincosf(ang, &sn, &c);

    float x1, x2, scale;
    size_t o;
    __nv_bfloat16 *dh, *dl;
    if (head < 32) {
        o = (size_t)m * 2048 + head * 64;
        x1 = q[o + p]; x2 = q[o + p + 32];
        scale = 0.125f; dh = qh; dl = ql;
    } else {
        o = (size_t)m * 512 + (head - 32) * 64;
        x1 = k[o + p]; x2 = k[o + p + 32];
        scale = 1.0f; dh = kh; dl = kl;
    }
    const float y1 = (x1 * c - x2 * sn) * scale;
    const float y2 = (x2 * c + x1 * sn) * scale;
    const __nv_bfloat16 h1 = __float2bfloat16(y1);
    const __nv_bfloat16 h2 = __float2bfloat16(y2);
    dh[o + p]      = h1;
    dh[o + p + 32] = h2;
    dl[o + p]      = __float2bfloat16(y1 - __bfloat162float(h1));
    dl[o + p + 32] = __float2bfloat16(y2 - __bfloat162float(h2));
}

// ---------------- tensor-core windowed attention ----------------
__global__ __launch_bounds__(256) void attn_tc(
    const __nv_bfloat16* __restrict__ qh_, const __nv_bfloat16* __restrict__ ql_,
    const __nv_bfloat16* __restrict__ kh_, const __nv_bfloat16* __restrict__ kl_,
    const __nv_bfloat16* __restrict__ vh_, const __nv_bfloat16* __restrict__ vl_,
    __nv_bfloat16* __restrict__ ohi, __nv_bfloat16* __restrict__ olo) {
    extern __shared__ __align__(16) unsigned char smraw[];
    const unsigned SB = smem_u32(smraw);
    const unsigned QHI = SB, QLO = SB + 18432u;
    const unsigned KHI = SB + 36864u;  // + p*9216 for KLO/VHI/VLO

    const int tid = threadIdx.x, lane = tid & 31, w = tid >> 5;
    const int t128 = blockIdx.x;
    const int h = blockIdx.y;
    const int z = blockIdx.z;
    const int b = z >> 4, n = z & 15;
    const int kvh = h >> 2;

    {
        const size_t qrow0 = (size_t)(b * S_LEN + n * 256 + t128 * 128);
        for (int g = tid; g < 2048; g += 256) {
            const int p = g >> 10, r = (g >> 3) & 127, c8 = g & 7;
            const __nv_bfloat16* src =
                (p ? ql_ : qh_) + (qrow0 + r) * 2048 + h * 64 + c8 * 8;
            cp16((p ? QLO : QHI) + (unsigned)r * 144u + (unsigned)c8 * 16u, src);
        }
        asm volatile("cp.async.commit_group;\n" ::: "memory");
        asm volatile("cp.async.wait_group 0;\n" ::: "memory");
        __syncthreads();
    }

    unsigned qfh[4][4], qfl[4][4];
    {
        const unsigned rr = (unsigned)(w * 16 + (lane & 15));
        const unsigned cb = (unsigned)((lane >> 4) * 16);
#pragma unroll
        for (int ks = 0; ks < 4; ks++) {
            ldsm4(qfh[ks], QHI + rr * 144u + (unsigned)ks * 32u + cb);
            ldsm4(qfl[ks], QLO + rr * 144u + (unsigned)ks * 32u + cb);
        }
    }

    float oacc[8][4];
#pragma unroll
    for (int j = 0; j < 8; j++)
#pragma unroll
        for (int u = 0; u < 4; u++) oacc[j][u] = 0.f;
    float m0 = -1e30f, m1 = -1e30f, l0 = 0.f, l1 = 0.f;

    const int rbase = t128 * 128 + w * 16 + (lane >> 2);
    int c_lo = 2 * t128;
    if (n == 0 && c_lo < 4) c_lo = 4;
    const int c_hi = (t128 == 0) ? 5 : 7;

    for (int c = c_lo; c <= c_hi; c++) {
        __syncthreads();
        {
            const size_t srow0 = (size_t)(b * S_LEN + (n - 1) * 256 + c * 64);
            for (int g = tid; g < 2048; g += 256) {
                const int p = g >> 9, r = (g >> 3) & 63, c8 = g & 7;
                const __nv_bfloat16* sp =
                    (p == 0 ? kh_ : p == 1 ? kl_ : p == 2 ? vh_ : vl_);
                cp16(KHI + (unsigned)p * 9216u + (unsigned)r * 144u +
                         (unsigned)c8 * 16u,
                     sp + (srow0 + r) * 512 + kvh * 64 + c8 * 8);
            }
            asm volatile("cp.async.commit_group;\n" ::: "memory");
            asm volatile("cp.async.wait_group 0;\n" ::: "memory");
            __syncthreads();
        }

        // ---- scores ----
        float sf[8][4];
#pragma unroll
        for (int j = 0; j < 8; j++)
#pragma unroll
            for (int u = 0; u < 4; u++) sf[j][u] = 0.f;

        const unsigned kb = (unsigned)((lane >> 4) * 16);
#pragma unroll
        for (int ks = 0; ks < 4; ks++) {
#pragma unroll
            for (int kg = 0; kg < 4; kg++) {
                const unsigned off = (unsigned)(kg * 16 + (lane & 15)) * 144u +
                                     (unsigned)ks * 32u + kb;
                unsigned th[4], tl[4];
                ldsm4(th, KHI + off);
                ldsm4(tl, KHI + 9216u + off);
                unsigned bh0[2] = {th[0], th[2]}, bh1[2] = {th[1], th[3]};
                unsigned bl0[2] = {tl[0], tl[2]}, bl1[2] = {tl[1], tl[3]};
                // pass-grouped across the two accumulators
                mma16816(sf[2 * kg],     qfh[ks], bh0);
                mma16816(sf[2 * kg + 1], qfh[ks], bh1);
                mma16816(sf[2 * kg],     qfh[ks], bl0);
                mma16816(sf[2 * kg + 1], qfh[ks], bl1);
                mma16816(sf[2 * kg],     qfl[ks], bh0);
                mma16816(sf[2 * kg + 1], qfl[ks], bh1);
            }
        }

        // ---- mask + online softmax (no MUFU) ----
        const int jb = c * 64 + (lane & 3) * 2;
        const float NEG = -1e30f;
#pragma unroll
        for (int j8 = 0; j8 < 8; j8++) {
            const int j0 = jb + j8 * 8;
            if (j0 < rbase     || j0 > rbase + 256) sf[j8][0] = NEG;
            if (j0 + 1 < rbase || j0 + 1 > rbase + 256) sf[j8][1] = NEG;
            if (j0 < rbase + 8 || j0 > rbase + 264) sf[j8][2] = NEG;
            if (j0 + 1 < rbase + 8 || j0 + 1 > rbase + 264) sf[j8][3] = NEG;
        }
        float mx0 = NEG, mx1 = NEG;
#pragma unroll
        for (int j8 = 0; j8 < 8; j8++) {
            mx0 = fmaxf(mx0, fmaxf(sf[j8][0], sf[j8][1]));
            mx1 = fmaxf(mx1, fmaxf(sf[j8][2], sf[j8][3]));
        }
        mx0 = fmaxf(mx0, __shfl_xor_sync(0xffffffffu, mx0, 1));
        mx0 = fmaxf(mx0, __shfl_xor_sync(0xffffffffu, mx0, 2));
        mx1 = fmaxf(mx1, __shfl_xor_sync(0xffffffffu, mx1, 1));
        mx1 = fmaxf(mx1, __shfl_xor_sync(0xffffffffu, mx1, 2));
        const float mn0 = fmaxf(m0, mx0), mn1 = fmaxf(m1, mx1);
        const float a0 = fexp(m0 - mn0), a1 = fexp(m1 - mn1);
        m0 = mn0; m1 = mn1;
        float s0 = 0.f, s1 = 0.f;
#pragma unroll
        for (int j8 = 0; j8 < 8; j8++) {
            sf[j8][0] = fexp(sf[j8][0] - mn0);
            sf[j8][1] = fexp(sf[j8][1] - mn0);
            sf[j8][2] = fexp(sf[j8][2] - mn1);
            sf[j8][3] = fexp(sf[j8][3] - mn1);
            s0 += sf[j8][0] + sf[j8][1];
            s1 += sf[j8][2] + sf[j8][3];
        }
        s0 += __shfl_xor_sync(0xffffffffu, s0, 1);
        s0 += __shfl_xor_sync(0xffffffffu, s0, 2);
        s1 += __shfl_xor_sync(0xffffffffu, s1, 1);
        s1 += __shfl_xor_sync(0xffffffffu, s1, 2);
        l0 = l0 * a0 + s0;
        l1 = l1 * a1 + s1;
#pragma unroll
        for (int j = 0; j < 8; j++) {
            oacc[j][0] *= a0; oacc[j][1] *= a0;
            oacc[j][2] *= a1; oacc[j][3] *= a1;
        }

        // ---- PV ----
#pragma unroll
        for (int kg = 0; kg < 4; kg++) {
            unsigned pah[4], pal[4];
            pah[0] = pack_hl(sf[2 * kg][0],     sf[2 * kg][1],     &pal[0]);
            pah[1] = pack_hl(sf[2 * kg][2],     sf[2 * kg][3],     &pal[1]);
            pah[2] = pack_hl(sf[2 * kg + 1][0], sf[2 * kg + 1][1], &pal[2]);
            pah[3] = pack_hl(sf[2 * kg + 1][2], sf[2 * kg + 1][3], &pal[3]);
            const unsigned vrow =
                (unsigned)(kg * 16 + ((lane >> 3) & 1) * 8 + (lane & 7)) * 144u;
#pragma unroll
            for (int dh = 0; dh < 4; dh++) {
                const unsigned voff =
                    vrow + (unsigned)dh * 32u + (unsigned)(lane >> 4) * 16u;
                unsigned vh4[4], vl4[4];
                ldsm4t(vh4, KHI + 18432u + voff);
                ldsm4t(vl4, KHI + 27648u + voff);
                unsigned vbh0[2] = {vh4[0], vh4[1]}, vbh1[2] = {vh4[2], vh4[3]};
                unsigned vbl0[2] = {vl4[0], vl4[1]}, vbl1[2] = {vl4[2], vl4[3]};
                // pass-grouped across the two accumulators
                mma16816(oacc[2 * dh],     pah, vbh0);
                mma16816(oacc[2 * dh + 1], pah, vbh1);
                mma16816(oacc[2 * dh],     pah, vbl0);
                mma16816(oacc[2 * dh + 1], pah, vbl1);
                mma16816(oacc[2 * dh],     pal, vbh0);
                mma16816(oacc[2 * dh + 1], pal, vbh1);
            }
        }
    }

    // ---- epilogue ----
    const float inv0 = 1.f / l0, inv1 = 1.f / l1;
    const size_t grow0 =
        (size_t)(b * S_LEN + n * 256 + t128 * 128 + w * 16 + (lane >> 2));
    const int colb = h * 64 + (lane & 3) * 2;
#pragma unroll
    for (int j8 = 0; j8 < 8; j8++) {
        unsigned hi0, lo0, hi1, lo1;
        hi0 = pack_hl(oacc[j8][0] * inv0, oacc[j8][1] * inv0, &lo0);
        hi1 = pack_hl(oacc[j8][2] * inv1, oacc[j8][3] * inv1, &lo1);
        const size_t i0 = grow0 * 2048 + colb + j8 * 8;
        const size_t i1 = i0 + 8 * 2048;
        *(unsigned*)(ohi + i0) = hi0;
        *(unsigned*)(olo + i0) = lo0;
        *(unsigned*)(ohi + i1) = hi1;
        *(unsigned*)(olo + i1) = lo1;
    }
}

// ---------------- launch ----------------
extern "C" void kernel_launch(void* const* d_in, const int* in_sizes, int n_in,
                              void* d_out, int out_size) {
    const float* hs = (const float*)d_in[0];
    const float* Wq = (const float*)d_in[1];
    const float* Wk = (const float*)d_in[2];
    const float* Wv = (const float*)d_in[3];
    const float* Wo = (const float*)d_in[4];
    float* out = (float*)d_out;

    float *q, *k, *v;
    __nv_bfloat16 *hs_hi, *hs_lo, *wq_hi, *wq_lo, *wk_hi, *wk_lo;
    __nv_bfloat16 *wv_hi, *wv_lo, *wo_hi, *wo_lo, *att_hi, *att_lo;
    __nv_bfloat16 *qh, *ql, *kh, *kl, *vh, *vl;
    cudaGetSymbolAddress((void**)&q, g_q);
    cudaGetSymbolAddress((void**)&k, g_k);
    cudaGetSymbolAddress((void**)&v, g_v);
    cudaGetSymbolAddress((void**)&hs_hi, g_hs_hi);
    cudaGetSymbolAddress((void**)&hs_lo, g_hs_lo);
    cudaGetSymbolAddress((void**)&wq_hi, g_wq_hi);
    cudaGetSymbolAddress((void**)&wq_lo, g_wq_lo);
    cudaGetSymbolAddress((void**)&wk_hi, g_wk_hi);
    cudaGetSymbolAddress((void**)&wk_lo, g_wk_lo);
    cudaGetSymbolAddress((void**)&wv_hi, g_wv_hi);
    cudaGetSymbolAddress((void**)&wv_lo, g_wv_lo);
    cudaGetSymbolAddress((void**)&wo_hi, g_wo_hi);
    cudaGetSymbolAddress((void**)&wo_lo, g_wo_lo);
    cudaGetSymbolAddress((void**)&att_hi, g_att_hi);
    cudaGetSymbolAddress((void**)&att_lo, g_att_lo);
    cudaGetSymbolAddress((void**)&qh, g_qh);
    cudaGetSymbolAddress((void**)&ql, g_ql);
    cudaGetSymbolAddress((void**)&kh, g_kh);
    cudaGetSymbolAddress((void**)&kl, g_kl);
    cudaGetSymbolAddress((void**)&vh, g_vh);
    cudaGetSymbolAddress((void**)&vl, g_vl);

    cudaFuncSetAttribute(gemm_bf16x3,
                         cudaFuncAttributeMaxDynamicSharedMemorySize, 98304);
    cudaFuncSetAttribute(attn_tc,
                         cudaFuncAttributeMaxDynamicSharedMemorySize, 73728);

    split_kernel<<<(M_ROWS * 2048 / 4 + 255) / 256, 256>>>(hs, hs_hi, hs_lo, M_ROWS * 2048 / 4);
    split_kernel<<<(2048 * 2048 / 4 + 255) / 256, 256>>>(Wq, wq_hi, wq_lo, 2048 * 2048 / 4);
    split_kernel<<<(512 * 2048 / 4 + 255) / 256, 256>>>(Wk, wk_hi, wk_lo, 512 * 2048 / 4);
    gemm_bf16x3<<<dim3(2048 / 128, M_ROWS / 128), 256, 98304>>>(
        hs_hi, hs_lo, wq_hi, wq_lo, q, M_ROWS, 2048, 2048);
    gemm_bf16x3<<<dim3(512 / 128, M_ROWS / 128), 256, 98304>>>(
        hs_hi, hs_lo, wk_hi, wk_lo, k, M_ROWS, 512, 2048);
    split_kernel<<<(512 * 2048 / 4 + 255) / 256, 256>>>(Wv, wv_hi, wv_lo, 512 * 2048 / 4);
    gemm_bf16x3<<<dim3(512 / 128, M_ROWS / 128), 256, 98304>>>(
        hs_hi, hs_lo, wv_hi, wv_lo, v, M_ROWS, 512, 2048);

    rope_split_kernel<<<(M_ROWS * 40 * 32 + 255) / 256, 256>>>(q, k, qh, ql, kh, kl);
    split_kernel<<<(M_ROWS * 512 / 4 + 255) / 256, 256>>>(v, vh, vl, M_ROWS * 512 / 4);

    attn_tc<<<dim3(2, 32, 32), 256, 73728>>>(qh, ql, kh, kl, vh, vl, att_hi, att_lo);

    split_kernel<<<(2048 * 2048 / 4 + 255) / 256, 256>>>(Wo, wo_hi, wo_lo, 2048 * 2048 / 4);
    gemm_bf16x3<<<dim3(2048 / 128, M_ROWS / 128), 256, 98304>>>(
        att_hi, att_lo, wo_hi, wo_lo, out, M_ROWS, 2048, 2048);
}

// round 9
// speedup vs baseline: 3.2321x; 1.3071x over previous
#include <cuda_runtime.h>
#include <cuda_bf16.h>
#include <cuda_fp16.h>
#include <math.h>

#define M_ROWS 8192
#define S_LEN  4096

// ---------------- scratch ----------------
__device__ float g_q[(size_t)M_ROWS * 2048];
__device__ float g_k[(size_t)M_ROWS * 512];
__device__ float g_v[(size_t)M_ROWS * 512];

// fp16 planes for GEMMs (activations hi+lo, weights hi only)
__device__ __half g_hs16h[(size_t)M_ROWS * 2048];
__device__ __half g_hs16l[(size_t)M_ROWS * 2048];
__device__ __half g_wq16[(size_t)2048 * 2048];
__device__ __half g_wk16[(size_t)512 * 2048];
__device__ __half g_wv16[(size_t)512 * 2048];
__device__ __half g_wo16[(size_t)2048 * 2048];
__device__ __half g_att16h[(size_t)M_ROWS * 2048];
__device__ __half g_att16l[(size_t)M_ROWS * 2048];

// bf16 planes for attention (unchanged bf16x3 path)
__device__ __nv_bfloat16 g_qh[(size_t)M_ROWS * 2048];
__device__ __nv_bfloat16 g_ql[(size_t)M_ROWS * 2048];
__device__ __nv_bfloat16 g_kh[(size_t)M_ROWS * 512];
__device__ __nv_bfloat16 g_kl[(size_t)M_ROWS * 512];
__device__ __nv_bfloat16 g_vh[(size_t)M_ROWS * 512];
__device__ __nv_bfloat16 g_vl[(size_t)M_ROWS * 512];

// ---------------- helpers ----------------
__device__ __forceinline__ unsigned smem_u32(const void* p) {
    unsigned r;
    asm("{ .reg .u64 t; cvta.to.shared.u64 t, %1; cvt.u32.u64 %0, t; }"
        : "=r"(r) : "l"(p));
    return r;
}
__device__ __forceinline__ void cp16(unsigned dst, const void* src) {
    asm volatile("cp.async.cg.shared.global [%0], [%1], 16;\n"
                 :: "r"(dst), "l"(src) : "memory");
}
__device__ __forceinline__ void ldsm4(unsigned* r, unsigned addr) {
    asm volatile("ldmatrix.sync.aligned.m8n8.x4.shared.b16 {%0,%1,%2,%3}, [%4];"
                 : "=r"(r[0]), "=r"(r[1]), "=r"(r[2]), "=r"(r[3]) : "r"(addr));
}
__device__ __forceinline__ void ldsm4t(unsigned* r, unsigned addr) {
    asm volatile("ldmatrix.sync.aligned.m8n8.x4.trans.shared.b16 {%0,%1,%2,%3}, [%4];"
                 : "=r"(r[0]), "=r"(r[1]), "=r"(r[2]), "=r"(r[3]) : "r"(addr));
}
// bf16 mma (attention)
__device__ __forceinline__ void mma16816(float* d, const unsigned* a, const unsigned* b) {
    asm volatile(
        "mma.sync.aligned.m16n8k16.row.col.f32.bf16.bf16.f32 "
        "{%0,%1,%2,%3}, {%4,%5,%6,%7}, {%8,%9}, {%0,%1,%2,%3};"
        : "+f"(d[0]), "+f"(d[1]), "+f"(d[2]), "+f"(d[3])
        : "r"(a[0]), "r"(a[1]), "r"(a[2]), "r"(a[3]), "r"(b[0]), "r"(b[1]));
}
// fp16 mma (projections)
__device__ __forceinline__ void mma16816h(float* d, const unsigned* a, const unsigned* b) {
    asm volatile(
        "mma.sync.aligned.m16n8k16.row.col.f32.f16.f16.f32 "
        "{%0,%1,%2,%3}, {%4,%5,%6,%7}, {%8,%9}, {%0,%1,%2,%3};"
        : "+f"(d[0]), "+f"(d[1]), "+f"(d[2]), "+f"(d[3])
        : "r"(a[0]), "r"(a[1]), "r"(a[2]), "r"(a[3]), "r"(b[0]), "r"(b[1]));
}
// exp on fma/alu pipes only
__device__ __forceinline__ float fexp(float x) {
    float t = fmaxf(x * 1.44269504f, -120.0f);
    float r = t + 12582912.0f;
    int   n = __float_as_int(r) - 0x4B400000;
    float f = t - (r - 12582912.0f);
    float p = 0.00133335581f;
    p = fmaf(p, f, 0.00961812910f);
    p = fmaf(p, f, 0.0555041086f);
    p = fmaf(p, f, 0.240226507f);
    p = fmaf(p, f, 0.693147180f);
    p = fmaf(p, f, 1.0f);
    return __int_as_float(__float_as_int(p) + (n << 23));
}
__device__ __forceinline__ unsigned pack_hl(float a, float b, unsigned* lo) {
    __nv_bfloat16 ha = __float2bfloat16(a), hb = __float2bfloat16(b);
    __nv_bfloat16 la = __float2bfloat16(a - __bfloat162float(ha));
    __nv_bfloat16 lb = __float2bfloat16(b - __bfloat162float(hb));
    __nv_bfloat162 H; H.x = ha; H.y = hb;
    __nv_bfloat162 L; L.x = la; L.y = lb;
    *lo = *(unsigned*)&L;
    return *(unsigned*)&H;
}
__device__ __forceinline__ unsigned pack_hl16(float a, float b, unsigned* lo) {
    __half ha = __float2half_rn(a), hb = __float2half_rn(b);
    __half la = __float2half_rn(a - __half2float(ha));
    __half lb = __float2half_rn(b - __half2float(hb));
    __half2 H; H.x = ha; H.y = hb;
    __half2 L; L.x = la; L.y = lb;
    *lo = *(unsigned*)&L;
    return *(unsigned*)&H;
}

// ---------------- converts ----------------
// fp32 -> fp16 hi + fp16 residual
__global__ void split16_kernel(const float* __restrict__ x,
                               __half* __restrict__ hi,
                               __half* __restrict__ lo, int n4) {
    const int i = blockIdx.x * 256 + threadIdx.x;
    if (i >= n4) return;
    const float4 vv = ((const float4*)x)[i];
    float f[4] = {vv.x, vv.y, vv.z, vv.w};
    __half h[4], l[4];
#pragma unroll
    for (int j = 0; j < 4; j++) {
        h[j] = __float2half_rn(f[j]);
        l[j] = __float2half_rn(f[j] - __half2float(h[j]));
    }
    __half2* H = (__half2*)hi;
    __half2* L = (__half2*)lo;
    __half2 t;
    t.x = h[0]; t.y = h[1]; H[2 * i]     = t;
    t.x = h[2]; t.y = h[3]; H[2 * i + 1] = t;
    t.x = l[0]; t.y = l[1]; L[2 * i]     = t;
    t.x = l[2]; t.y = l[3]; L[2 * i + 1] = t;
}
// fp32 -> fp16 (weights, hi only)
__global__ void cvt16_kernel(const float* __restrict__ x,
                             __half* __restrict__ hi, int n4) {
    const int i = blockIdx.x * 256 + threadIdx.x;
    if (i >= n4) return;
    const float4 vv = ((const float4*)x)[i];
    __half2* H = (__half2*)hi;
    __half2 t;
    t.x = __float2half_rn(vv.x); t.y = __float2half_rn(vv.y); H[2 * i] = t;
    t.x = __float2half_rn(vv.z); t.y = __float2half_rn(vv.w); H[2 * i + 1] = t;
}
// fp32 -> bf16 hi/lo (V for attention)
__global__ void split_kernel(const float* __restrict__ x,
                             __nv_bfloat16* __restrict__ hi,
                             __nv_bfloat16* __restrict__ lo, int n4) {
    const int i = blockIdx.x * 256 + threadIdx.x;
    if (i >= n4) return;
    const float4 vv = ((const float4*)x)[i];
    float f[4] = {vv.x, vv.y, vv.z, vv.w};
    __nv_bfloat16 h[4], l[4];
#pragma unroll
    for (int j = 0; j < 4; j++) {
        h[j] = __float2bfloat16(f[j]);
        l[j] = __float2bfloat16(f[j] - __bfloat162float(h[j]));
    }
    __nv_bfloat162* H = (__nv_bfloat162*)hi;
    __nv_bfloat162* L = (__nv_bfloat162*)lo;
    __nv_bfloat162 t;
    t.x = h[0]; t.y = h[1]; H[2 * i]     = t;
    t.x = h[2]; t.y = h[3]; H[2 * i + 1] = t;
    t.x = l[0]; t.y = l[1]; L[2 * i]     = t;
    t.x = l[2]; t.y = l[3]; L[2 * i + 1] = t;
}

// ---------------- fp16 two-pass GEMM (NT) ----------------
// C[m][n] = sum_k A[m][k]*W[n][k], A = Ahi + Alo (fp16), W ~ Whi (fp16).
// Two passes: Ahi*Whi + Alo*Whi == A*Whi (drops only A*Wlo, ~2^-11 rel).
// CTA 128x128, K-tile 32, 256 thr (8 warps 2x4, warp tile 64x32).
// Stage = [Ahi 8K][Alo 8K][Whi 8K] = 24KB, 3-stage ring, 2 CTAs/SM.
#define GSTAGE16 24576u

__global__ __launch_bounds__(256, 2) void gemm_f16x2(
    const __half* __restrict__ Ahi, const __half* __restrict__ Alo,
    const __half* __restrict__ Whi,
    float* __restrict__ C, int M, int N, int K) {
    extern __shared__ __align__(16) unsigned char smraw[];
    const unsigned sbase = smem_u32(smraw);

    const int tid = threadIdx.x;
    const int wid = tid >> 5, lane = tid & 31;
    const int warp_m = wid >> 2;
    const int warp_n = wid & 3;
    const int m0 = blockIdx.y << 7;
    const int n0 = blockIdx.x << 7;

    const __half* srcs[3] = {
        Ahi + (size_t)m0 * K, Alo + (size_t)m0 * K, Whi + (size_t)n0 * K};

    float acc[4][4][4];
#pragma unroll
    for (int i = 0; i < 4; i++)
#pragma unroll
        for (int j = 0; j < 4; j++)
#pragma unroll
            for (int u = 0; u < 4; u++) acc[i][j][u] = 0.f;

    const int ldr = tid >> 1;
    const int ldc = (tid & 1) * 2;

    auto prefetch = [&](int it, int bufi) {
        const int k0 = it * 32;
        const unsigned bufbase = sbase + (unsigned)bufi * GSTAGE16;
#pragma unroll
        for (int p = 0; p < 3; p++) {
            const __half* src = srcs[p] + (size_t)ldr * K + k0 + ldc * 8;
            const unsigned splane = bufbase + p * 8192u;
#pragma unroll
            for (int cc = 0; cc < 2; cc++) {
                const int c = ldc + cc;
                const unsigned dst =
                    splane + ldr * 64u + (unsigned)((c ^ ((ldr >> 1) & 3)) << 4);
                cp16(dst, src + cc * 8);
            }
        }
    };

    auto compute = [&](int bufi) {
        const unsigned base = sbase + (unsigned)bufi * GSTAGE16;
        const int arow = (lane & 7) + ((lane >> 3) & 1) * 8;
        const int khalf = (lane >> 4) & 1;
#pragma unroll
        for (int ks = 0; ks < 2; ks++) {
            const int c = ks * 2 + khalf;
            unsigned bh[4][2];
#pragma unroll
            for (int half = 0; half < 2; half++) {
                const int row = warp_n * 32 + half * 16 + arow;
                const unsigned off =
                    row * 64u + (unsigned)((c ^ ((row >> 1) & 3)) << 4);
                unsigned t[4];
                ldsm4(t, base + 16384u + off);
                bh[half * 2 + 0][0] = t[0]; bh[half * 2 + 0][1] = t[2];
                bh[half * 2 + 1][0] = t[1]; bh[half * 2 + 1][1] = t[3];
            }
#pragma unroll
            for (int i = 0; i < 4; i++) {
                const int row = warp_m * 64 + i * 16 + arow;
                const unsigned off =
                    row * 64u + (unsigned)((c ^ ((row >> 1) & 3)) << 4);
                unsigned ahi[4], alo[4];
                ldsm4(ahi, base + off);
                ldsm4(alo, base + 8192u + off);
#pragma unroll
                for (int j = 0; j < 4; j++) mma16816h(acc[i][j], ahi, bh[j]);
#pragma unroll
                for (int j = 0; j < 4; j++) mma16816h(acc[i][j], alo, bh[j]);
            }
        }
    };

    const int NIT = K >> 5;
    prefetch(0, 0);
    asm volatile("cp.async.commit_group;\n" ::: "memory");
    prefetch(1, 1);
    asm volatile("cp.async.commit_group;\n" ::: "memory");

    for (int it = 0; it < NIT; it++) {
        if (it + 1 < NIT) {
            asm volatile("cp.async.wait_group 1;\n" ::: "memory");
        } else {
            asm volatile("cp.async.wait_group 0;\n" ::: "memory");
        }
        __syncthreads();
        if (it + 2 < NIT) {
            prefetch(it + 2, (it + 2) % 3);
            asm volatile("cp.async.commit_group;\n" ::: "memory");
        }
        compute(it % 3);
    }

#pragma unroll
    for (int i = 0; i < 4; i++)
#pragma unroll
        for (int j = 0; j < 4; j++) {
            const int r0 = m0 + warp_m * 64 + i * 16 + (lane >> 2);
            const int cc = n0 + warp_n * 32 + j * 8 + (lane & 3) * 2;
            float2 u;
            u.x = acc[i][j][0]; u.y = acc[i][j][1];
            *(float2*)(C + (size_t)r0 * N + cc) = u;
            u.x = acc[i][j][2]; u.y = acc[i][j][3];
            *(float2*)(C + (size_t)(r0 + 8) * N + cc) = u;
        }
}

// ---------------- RoPE + bf16 hi/lo split (Q scaled 0.125) ----------------
__global__ void rope_split_kernel(
    const float* __restrict__ q, const float* __restrict__ k,
    __nv_bfloat16* __restrict__ qh, __nv_bfloat16* __restrict__ ql,
    __nv_bfloat16* __restrict__ kh, __nv_bfloat16* __restrict__ kl) {
    const int idx = blockIdx.x * 256 + threadIdx.x;
    const int total = M_ROWS * 40 * 32;
    if (idx >= total) return;
    const int p = idx & 31;
    const int rest = idx >> 5;
    const int head = rest % 40;
    const int m = rest / 40;
    const int s = m & (S_LEN - 1);

    const float invf = exp2f(-(float)p * 0.41524101186092027f);
    const float ang = (float)s * invf;
    float sn, c;
    sincosf(ang, &sn, &c);

    float x1, x2, scale;
    size_t o;
    __nv_bfloat16 *dh, *dl;
    if (head < 32) {
        o = (size_t)m * 2048 + head * 64;
        x1 = q[o + p]; x2 = q[o + p + 32];
        scale = 0.125f; dh = qh; dl = ql;
    } else {
        o = (size_t)m * 512 + (head - 32) * 64;
        x1 = k[o + p]; x2 = k[o + p + 32];
        scale = 1.0f; dh = kh; dl = kl;
    }
    const float y1 = (x1 * c - x2 * sn) * scale;
    const float y2 = (x2 * c + x1 * sn) * scale;
    const __nv_bfloat16 h1 = __float2bfloat16(y1);
    const __nv_bfloat16 h2 = __float2bfloat16(y2);
    dh[o + p]      = h1;
    dh[o + p + 32] = h2;
    dl[o + p]      = __float2bfloat16(y1 - __bfloat162float(h1));
    dl[o + p + 32] = __float2bfloat16(y2 - __bfloat162float(h2));
}

// ---------------- tensor-core windowed attention (bf16x3) ----------------
// Emits fp16 hi/lo for the fp16 O-projection.
__global__ __launch_bounds__(256) void attn_tc(
    const __nv_bfloat16* __restrict__ qh_, const __nv_bfloat16* __restrict__ ql_,
    const __nv_bfloat16* __restrict__ kh_, const __nv_bfloat16* __restrict__ kl_,
    const __nv_bfloat16* __restrict__ vh_, const __nv_bfloat16* __restrict__ vl_,
    __half* __restrict__ ohi, __half* __restrict__ olo) {
    extern __shared__ __align__(16) unsigned char smraw[];
    const unsigned SB = smem_u32(smraw);
    const unsigned QHI = SB, QLO = SB + 18432u;
    const unsigned KHI = SB + 36864u;  // + p*9216 for KLO/VHI/VLO

    const int tid = threadIdx.x, lane = tid & 31, w = tid >> 5;
    const int t128 = blockIdx.x;
    const int h = blockIdx.y;
    const int z = blockIdx.z;
    const int b = z >> 4, n = z & 15;
    const int kvh = h >> 2;

    {
        const size_t qrow0 = (size_t)(b * S_LEN + n * 256 + t128 * 128);
        for (int g = tid; g < 2048; g += 256) {
            const int p = g >> 10, r = (g >> 3) & 127, c8 = g & 7;
            const __nv_bfloat16* src =
                (p ? ql_ : qh_) + (qrow0 + r) * 2048 + h * 64 + c8 * 8;
            cp16((p ? QLO : QHI) + (unsigned)r * 144u + (unsigned)c8 * 16u, src);
        }
        asm volatile("cp.async.commit_group;\n" ::: "memory");
        asm volatile("cp.async.wait_group 0;\n" ::: "memory");
        __syncthreads();
    }

    unsigned qfh[4][4], qfl[4][4];
    {
        const unsigned rr = (unsigned)(w * 16 + (lane & 15));
        const unsigned cb = (unsigned)((lane >> 4) * 16);
#pragma unroll
        for (int ks = 0; ks < 4; ks++) {
            ldsm4(qfh[ks], QHI + rr * 144u + (unsigned)ks * 32u + cb);
            ldsm4(qfl[ks], QLO + rr * 144u + (unsigned)ks * 32u + cb);
        }
    }

    float oacc[8][4];
#pragma unroll
    for (int j = 0; j < 8; j++)
#pragma unroll
        for (int u = 0; u < 4; u++) oacc[j][u] = 0.f;
    float m0 = -1e30f, m1 = -1e30f, l0 = 0.f, l1 = 0.f;

    const int rbase = t128 * 128 + w * 16 + (lane >> 2);
    int c_lo = 2 * t128;
    if (n == 0 && c_lo < 4) c_lo = 4;
    const int c_hi = (t128 == 0) ? 5 : 7;

    for (int c = c_lo; c <= c_hi; c++) {
        __syncthreads();
        {
            const size_t srow0 = (size_t)(b * S_LEN + (n - 1) * 256 + c * 64);
            for (int g = tid; g < 2048; g += 256) {
                const int p = g >> 9, r = (g >> 3) & 63, c8 = g & 7;
                const __nv_bfloat16* sp =
                    (p == 0 ? kh_ : p == 1 ? kl_ : p == 2 ? vh_ : vl_);
                cp16(KHI + (unsigned)p * 9216u + (unsigned)r * 144u +
                         (unsigned)c8 * 16u,
                     sp + (srow0 + r) * 512 + kvh * 64 + c8 * 8);
            }
            asm volatile("cp.async.commit_group;\n" ::: "memory");
            asm volatile("cp.async.wait_group 0;\n" ::: "memory");
            __syncthreads();
        }

        // ---- scores ----
        float sf[8][4];
#pragma unroll
        for (int j = 0; j < 8; j++)
#pragma unroll
            for (int u = 0; u < 4; u++) sf[j][u] = 0.f;

        const unsigned kb = (unsigned)((lane >> 4) * 16);
#pragma unroll
        for (int ks = 0; ks < 4; ks++) {
#pragma unroll
            for (int kg = 0; kg < 4; kg++) {
                const unsigned off = (unsigned)(kg * 16 + (lane & 15)) * 144u +
                                     (unsigned)ks * 32u + kb;
                unsigned th[4], tl[4];
                ldsm4(th, KHI + off);
                ldsm4(tl, KHI + 9216u + off);
                unsigned bh0[2] = {th[0], th[2]}, bh1[2] = {th[1], th[3]};
                unsigned bl0[2] = {tl[0], tl[2]}, bl1[2] = {tl[1], tl[3]};
                mma16816(sf[2 * kg],     qfh[ks], bh0);
                mma16816(sf[2 * kg + 1], qfh[ks], bh1);
                mma16816(sf[2 * kg],     qfh[ks], bl0);
                mma16816(sf[2 * kg + 1], qfh[ks], bl1);
                mma16816(sf[2 * kg],     qfl[ks], bh0);
                mma16816(sf[2 * kg + 1], qfl[ks], bh1);
            }
        }

        // ---- mask + online softmax (no MUFU) ----
        const int jb = c * 64 + (lane & 3) * 2;
        const float NEG = -1e30f;
#pragma unroll
        for (int j8 = 0; j8 < 8; j8++) {
            const int j0 = jb + j8 * 8;
            if (j0 < rbase     || j0 > rbase + 256) sf[j8][0] = NEG;
            if (j0 + 1 < rbase || j0 + 1 > rbase + 256) sf[j8][1] = NEG;
            if (j0 < rbase + 8 || j0 > rbase + 264) sf[j8][2] = NEG;
            if (j0 + 1 < rbase + 8 || j0 + 1 > rbase + 264) sf[j8][3] = NEG;
        }
        float mx0 = NEG, mx1 = NEG;
#pragma unroll
        for (int j8 = 0; j8 < 8; j8++) {
            mx0 = fmaxf(mx0, fmaxf(sf[j8][0], sf[j8][1]));
            mx1 = fmaxf(mx1, fmaxf(sf[j8][2], sf[j8][3]));
        }
        mx0 = fmaxf(mx0, __shfl_xor_sync(0xffffffffu, mx0, 1));
        mx0 = fmaxf(mx0, __shfl_xor_sync(0xffffffffu, mx0, 2));
        mx1 = fmaxf(mx1, __shfl_xor_sync(0xffffffffu, mx1, 1));
        mx1 = fmaxf(mx1, __shfl_xor_sync(0xffffffffu, mx1, 2));
        const float mn0 = fmaxf(m0, mx0), mn1 = fmaxf(m1, mx1);
        const float a0 = fexp(m0 - mn0), a1 = fexp(m1 - mn1);
        m0 = mn0; m1 = mn1;
        float s0 = 0.f, s1 = 0.f;
#pragma unroll
        for (int j8 = 0; j8 < 8; j8++) {
            sf[j8][0] = fexp(sf[j8][0] - mn0);
            sf[j8][1] = fexp(sf[j8][1] - mn0);
            sf[j8][2] = fexp(sf[j8][2] - mn1);
            sf[j8][3] = fexp(sf[j8][3] - mn1);
            s0 += sf[j8][0] + sf[j8][1];
            s1 += sf[j8][2] + sf[j8][3];
        }
        s0 += __shfl_xor_sync(0xffffffffu, s0, 1);
        s0 += __shfl_xor_sync(0xffffffffu, s0, 2);
        s1 += __shfl_xor_sync(0xffffffffu, s1, 1);
        s1 += __shfl_xor_sync(0xffffffffu, s1, 2);
        l0 = l0 * a0 + s0;
        l1 = l1 * a1 + s1;
#pragma unroll
        for (int j = 0; j < 8; j++) {
            oacc[j][0] *= a0; oacc[j][1] *= a0;
            oacc[j][2] *= a1; oacc[j][3] *= a1;
        }

        // ---- PV ----
#pragma unroll
        for (int kg = 0; kg < 4; kg++) {
            unsigned pah[4], pal[4];
            pah[0] = pack_hl(sf[2 * kg][0],     sf[2 * kg][1],     &pal[0]);
            pah[1] = pack_hl(sf[2 * kg][2],     sf[2 * kg][3],     &pal[1]);
            pah[2] = pack_hl(sf[2 * kg + 1][0], sf[2 * kg + 1][1], &pal[2]);
            pah[3] = pack_hl(sf[2 * kg + 1][2], sf[2 * kg + 1][3], &pal[3]);
            const unsigned vrow =
                (unsigned)(kg * 16 + ((lane >> 3) & 1) * 8 + (lane & 7)) * 144u;
#pragma unroll
            for (int dh = 0; dh < 4; dh++) {
                const unsigned voff =
                    vrow + (unsigned)dh * 32u + (unsigned)(lane >> 4) * 16u;
                unsigned vh4[4], vl4[4];
                ldsm4t(vh4, KHI + 18432u + voff);
                ldsm4t(vl4, KHI + 27648u + voff);
                unsigned vbh0[2] = {vh4[0], vh4[1]}, vbh1[2] = {vh4[2], vh4[3]};
                unsigned vbl0[2] = {vl4[0], vl4[1]}, vbl1[2] = {vl4[2], vl4[3]};
                mma16816(oacc[2 * dh],     pah, vbh0);
                mma16816(oacc[2 * dh + 1], pah, vbh1);
                mma16816(oacc[2 * dh],     pah, vbl0);
                mma16816(oacc[2 * dh + 1], pah, vbl1);
                mma16816(oacc[2 * dh],     pal, vbh0);
                mma16816(oacc[2 * dh + 1], pal, vbh1);
            }
        }
    }

    // ---- epilogue: normalize, fp16 hi/lo, store ----
    const float inv0 = 1.f / l0, inv1 = 1.f / l1;
    const size_t grow0 =
        (size_t)(b * S_LEN + n * 256 + t128 * 128 + w * 16 + (lane >> 2));
    const int colb = h * 64 + (lane & 3) * 2;
#pragma unroll
    for (int j8 = 0; j8 < 8; j8++) {
        unsigned hi0, lo0, hi1, lo1;
        hi0 = pack_hl16(oacc[j8][0] * inv0, oacc[j8][1] * inv0, &lo0);
        hi1 = pack_hl16(oacc[j8][2] * inv1, oacc[j8][3] * inv1, &lo1);
        const size_t i0 = grow0 * 2048 + colb + j8 * 8;
        const size_t i1 = i0 + 8 * 2048;
        *(unsigned*)(ohi + i0) = hi0;
        *(unsigned*)(olo + i0) = lo0;
        *(unsigned*)(ohi + i1) = hi1;
        *(unsigned*)(olo + i1) = lo1;
    }
}

// ---------------- launch ----------------
extern "C" void kernel_launch(void* const* d_in, const int* in_sizes, int n_in,
                              void* d_out, int out_size) {
    const float* hs = (const float*)d_in[0];
    const float* Wq = (const float*)d_in[1];
    const float* Wk = (const float*)d_in[2];
    const float* Wv = (const float*)d_in[3];
    const float* Wo = (const float*)d_in[4];
    float* out = (float*)d_out;

    float *q, *k, *v;
    __half *hs16h, *hs16l, *wq16, *wk16, *wv16, *wo16, *att16h, *att16l;
    __nv_bfloat16 *qh, *ql, *kh, *kl, *vh, *vl;
    cudaGetSymbolAddress((void**)&q, g_q);
    cudaGetSymbolAddress((void**)&k, g_k);
    cudaGetSymbolAddress((void**)&v, g_v);
    cudaGetSymbolAddress((void**)&hs16h, g_hs16h);
    cudaGetSymbolAddress((void**)&hs16l, g_hs16l);
    cudaGetSymbolAddress((void**)&wq16, g_wq16);
    cudaGetSymbolAddress((void**)&wk16, g_wk16);
    cudaGetSymbolAddress((void**)&wv16, g_wv16);
    cudaGetSymbolAddress((void**)&wo16, g_wo16);
    cudaGetSymbolAddress((void**)&att16h, g_att16h);
    cudaGetSymbolAddress((void**)&att16l, g_att16l);
    cudaGetSymbolAddress((void**)&qh, g_qh);
    cudaGetSymbolAddress((void**)&ql, g_ql);
    cudaGetSymbolAddress((void**)&kh, g_kh);
    cudaGetSymbolAddress((void**)&kl, g_kl);
    cudaGetSymbolAddress((void**)&vh, g_vh);
    cudaGetSymbolAddress((void**)&vl, g_vl);

    cudaFuncSetAttribute(gemm_f16x2,
                         cudaFuncAttributeMaxDynamicSharedMemorySize, 73728);
    cudaFuncSetAttribute(attn_tc,
                         cudaFuncAttributeMaxDynamicSharedMemorySize, 73728);

    // launches 0-2, then gemmQ at #4 overall (ncu capture slot)
    split16_kernel<<<(M_ROWS * 2048 / 4 + 255) / 256, 256>>>(hs, hs16h, hs16l, M_ROWS * 2048 / 4);
    cvt16_kernel<<<(2048 * 2048 / 4 + 255) / 256, 256>>>(Wq, wq16, 2048 * 2048 / 4);
    cvt16_kernel<<<(512 * 2048 / 4 + 255) / 256, 256>>>(Wk, wk16, 512 * 2048 / 4);
    gemm_f16x2<<<dim3(2048 / 128, M_ROWS / 128), 256, 73728>>>(
        hs16h, hs16l, wq16, q, M_ROWS, 2048, 2048);
    gemm_f16x2<<<dim3(512 / 128, M_ROWS / 128), 256, 73728>>>(
        hs16h, hs16l, wk16, k, M_ROWS, 512, 2048);
    cvt16_kernel<<<(512 * 2048 / 4 + 255) / 256, 256>>>(Wv, wv16, 512 * 2048 / 4);
    gemm_f16x2<<<dim3(512 / 128, M_ROWS / 128), 256, 73728>>>(
        hs16h, hs16l, wv16, v, M_ROWS, 512, 2048);

    rope_split_kernel<<<(M_ROWS * 40 * 32 + 255) / 256, 256>>>(q, k, qh, ql, kh, kl);
    split_kernel<<<(M_ROWS * 512 / 4 + 255) / 256, 256>>>(v, vh, vl, M_ROWS * 512 / 4);

    attn_tc<<<dim3(2, 32, 32), 256, 73728>>>(qh, ql, kh, kl, vh, vl, att16h, att16l);

    cvt16_kernel<<<(2048 * 2048 / 4 + 255) / 256, 256>>>(Wo, wo16, 2048 * 2048 / 4);
    gemm_f16x2<<<dim3(2048 / 128, M_ROWS / 128), 256, 73728>>>(
        att16h, att16l, wo16, out, M_ROWS, 2048, 2048);
}

// round 12
// speedup vs baseline: 4.7281x; 1.4629x over previous
#include <cuda_runtime.h>
#include <cuda_bf16.h>
#include <cuda_fp16.h>
#include <math.h>

#define M_ROWS 8192
#define S_LEN  4096

// ---------------- scratch ----------------
__device__ float g_q[(size_t)M_ROWS * 2048];
__device__ float g_k[(size_t)M_ROWS * 512];
__device__ float g_v[(size_t)M_ROWS * 512];

// fp16 planes for GEMMs (single plane per operand)
__device__ __half g_hs16[(size_t)M_ROWS * 2048];
__device__ __half g_wq16[(size_t)2048 * 2048];
__device__ __half g_wk16[(size_t)512 * 2048];
__device__ __half g_wv16[(size_t)512 * 2048];
__device__ __half g_wo16[(size_t)2048 * 2048];
__device__ __half g_att16[(size_t)M_ROWS * 2048];

// bf16 planes for attention (unchanged bf16x3 path)
__device__ __nv_bfloat16 g_qh[(size_t)M_ROWS * 2048];
__device__ __nv_bfloat16 g_ql[(size_t)M_ROWS * 2048];
__device__ __nv_bfloat16 g_kh[(size_t)M_ROWS * 512];
__device__ __nv_bfloat16 g_kl[(size_t)M_ROWS * 512];
__device__ __nv_bfloat16 g_vh[(size_t)M_ROWS * 512];
__device__ __nv_bfloat16 g_vl[(size_t)M_ROWS * 512];

// ---------------- helpers ----------------
__device__ __forceinline__ unsigned smem_u32(const void* p) {
    unsigned r;
    asm("{ .reg .u64 t; cvta.to.shared.u64 t, %1; cvt.u32.u64 %0, t; }"
        : "=r"(r) : "l"(p));
    return r;
}
__device__ __forceinline__ void cp16(unsigned dst, const void* src) {
    asm volatile("cp.async.cg.shared.global [%0], [%1], 16;\n"
                 :: "r"(dst), "l"(src) : "memory");
}
__device__ __forceinline__ void ldsm4(unsigned* r, unsigned addr) {
    asm volatile("ldmatrix.sync.aligned.m8n8.x4.shared.b16 {%0,%1,%2,%3}, [%4];"
                 : "=r"(r[0]), "=r"(r[1]), "=r"(r[2]), "=r"(r[3]) : "r"(addr));
}
__device__ __forceinline__ void ldsm4t(unsigned* r, unsigned addr) {
    asm volatile("ldmatrix.sync.aligned.m8n8.x4.trans.shared.b16 {%0,%1,%2,%3}, [%4];"
                 : "=r"(r[0]), "=r"(r[1]), "=r"(r[2]), "=r"(r[3]) : "r"(addr));
}
// bf16 mma (attention)
__device__ __forceinline__ void mma16816(float* d, const unsigned* a, const unsigned* b) {
    asm volatile(
        "mma.sync.aligned.m16n8k16.row.col.f32.bf16.bf16.f32 "
        "{%0,%1,%2,%3}, {%4,%5,%6,%7}, {%8,%9}, {%0,%1,%2,%3};"
        : "+f"(d[0]), "+f"(d[1]), "+f"(d[2]), "+f"(d[3])
        : "r"(a[0]), "r"(a[1]), "r"(a[2]), "r"(a[3]), "r"(b[0]), "r"(b[1]));
}
// fp16 mma (projections)
__device__ __forceinline__ void mma16816h(float* d, const unsigned* a, const unsigned* b) {
    asm volatile(
        "mma.sync.aligned.m16n8k16.row.col.f32.f16.f16.f32 "
        "{%0,%1,%2,%3}, {%4,%5,%6,%7}, {%8,%9}, {%0,%1,%2,%3};"
        : "+f"(d[0]), "+f"(d[1]), "+f"(d[2]), "+f"(d[3])
        : "r"(a[0]), "r"(a[1]), "r"(a[2]), "r"(a[3]), "r"(b[0]), "r"(b[1]));
}
// exp on fma/alu pipes only
__device__ __forceinline__ float fexp(float x) {
    float t = fmaxf(x * 1.44269504f, -120.0f);
    float r = t + 12582912.0f;
    int   n = __float_as_int(r) - 0x4B400000;
    float f = t - (r - 12582912.0f);
    float p = 0.00133335581f;
    p = fmaf(p, f, 0.00961812910f);
    p = fmaf(p, f, 0.0555041086f);
    p = fmaf(p, f, 0.240226507f);
    p = fmaf(p, f, 0.693147180f);
    p = fmaf(p, f, 1.0f);
    return __int_as_float(__float_as_int(p) + (n << 23));
}
__device__ __forceinline__ unsigned pack_hl(float a, float b, unsigned* lo) {
    __nv_bfloat16 ha = __float2bfloat16(a), hb = __float2bfloat16(b);
    __nv_bfloat16 la = __float2bfloat16(a - __bfloat162float(ha));
    __nv_bfloat16 lb = __float2bfloat16(b - __bfloat162float(hb));
    __nv_bfloat162 H; H.x = ha; H.y = hb;
    __nv_bfloat162 L; L.x = la; L.y = lb;
    *lo = *(unsigned*)&L;
    return *(unsigned*)&H;
}
__device__ __forceinline__ unsigned pack_h16(float a, float b) {
    __half2 H; H.x = __float2half_rn(a); H.y = __float2half_rn(b);
    return *(unsigned*)&H;
}

// ---------------- converts ----------------
// fp32 -> fp16
__global__ void cvt16_kernel(const float* __restrict__ x,
                             __half* __restrict__ hi, int n4) {
    const int i = blockIdx.x * 256 + threadIdx.x;
    if (i >= n4) return;
    const float4 vv = ((const float4*)x)[i];
    __half2* H = (__half2*)hi;
    __half2 t;
    t.x = __float2half_rn(vv.x); t.y = __float2half_rn(vv.y); H[2 * i] = t;
    t.x = __float2half_rn(vv.z); t.y = __float2half_rn(vv.w); H[2 * i + 1] = t;
}
// fp32 -> bf16 hi/lo (V for attention)
__global__ void split_kernel(const float* __restrict__ x,
                             __nv_bfloat16* __restrict__ hi,
                             __nv_bfloat16* __restrict__ lo, int n4) {
    const int i = blockIdx.x * 256 + threadIdx.x;
    if (i >= n4) return;
    const float4 vv = ((const float4*)x)[i];
    float f[4] = {vv.x, vv.y, vv.z, vv.w};
    __nv_bfloat16 h[4], l[4];
#pragma unroll
    for (int j = 0; j < 4; j++) {
        h[j] = __float2bfloat16(f[j]);
        l[j] = __float2bfloat16(f[j] - __bfloat162float(h[j]));
    }
    __nv_bfloat162* H = (__nv_bfloat162*)hi;
    __nv_bfloat162* L = (__nv_bfloat162*)lo;
    __nv_bfloat162 t;
    t.x = h[0]; t.y = h[1]; H[2 * i]     = t;
    t.x = h[2]; t.y = h[3]; H[2 * i + 1] = t;
    t.x = l[0]; t.y = l[1]; L[2 * i]     = t;
    t.x = l[2]; t.y = l[3]; L[2 * i + 1] = t;
}

// ---------------- fp16 single-pass GEMM (NT) ----------------
// C[m][n] = sum_k A[m][k]*W[n][k], both fp16, fp32 accum.
// CTA 128x128, K-tile 32, 256 thr (8 warps 2x4, warp tile 64x32).
// Stage = [A 8K][W 8K] = 16KB, 3-stage ring, 2 CTAs/SM.
#define GSTAGEF 16384u

__global__ __launch_bounds__(256, 2) void gemm_f16(
    const __half* __restrict__ A, const __half* __restrict__ Whi,
    float* __restrict__ C, int M, int N, int K) {
    extern __shared__ __align__(16) unsigned char smraw[];
    const unsigned sbase = smem_u32(smraw);

    const int tid = threadIdx.x;
    const int wid = tid >> 5, lane = tid & 31;
    const int warp_m = wid >> 2;
    const int warp_n = wid & 3;
    const int m0 = blockIdx.y << 7;
    const int n0 = blockIdx.x << 7;

    const __half* srcs[2] = {A + (size_t)m0 * K, Whi + (size_t)n0 * K};

    float acc[4][4][4];
#pragma unroll
    for (int i = 0; i < 4; i++)
#pragma unroll
        for (int j = 0; j < 4; j++)
#pragma unroll
            for (int u = 0; u < 4; u++) acc[i][j][u] = 0.f;

    const int ldr = tid >> 1;
    const int ldc = (tid & 1) * 2;

    auto prefetch = [&](int it, int bufi) {
        const int k0 = it * 32;
        const unsigned bufbase = sbase + (unsigned)bufi * GSTAGEF;
#pragma unroll
        for (int p = 0; p < 2; p++) {
            const __half* src = srcs[p] + (size_t)ldr * K + k0 + ldc * 8;
            const unsigned splane = bufbase + p * 8192u;
#pragma unroll
            for (int cc = 0; cc < 2; cc++) {
                const int c = ldc + cc;
                const unsigned dst =
                    splane + ldr * 64u + (unsigned)((c ^ ((ldr >> 1) & 3)) << 4);
                cp16(dst, src + cc * 8);
            }
        }
    };

    auto compute = [&](int bufi) {
        const unsigned base = sbase + (unsigned)bufi * GSTAGEF;
        const int arow = (lane & 7) + ((lane >> 3) & 1) * 8;
        const int khalf = (lane >> 4) & 1;
#pragma unroll
        for (int ks = 0; ks < 2; ks++) {
            const int c = ks * 2 + khalf;
            unsigned bh[4][2];
#pragma unroll
            for (int half = 0; half < 2; half++) {
                const int row = warp_n * 32 + half * 16 + arow;
                const unsigned off =
                    row * 64u + (unsigned)((c ^ ((row >> 1) & 3)) << 4);
                unsigned t[4];
                ldsm4(t, base + 8192u + off);
                bh[half * 2 + 0][0] = t[0]; bh[half * 2 + 0][1] = t[2];
                bh[half * 2 + 1][0] = t[1]; bh[half * 2 + 1][1] = t[3];
            }
#pragma unroll
            for (int i = 0; i < 4; i++) {
                const int row = warp_m * 64 + i * 16 + arow;
                const unsigned off =
                    row * 64u + (unsigned)((c ^ ((row >> 1) & 3)) << 4);
                unsigned ah[4];
                ldsm4(ah, base + off);
#pragma unroll
                for (int j = 0; j < 4; j++) mma16816h(acc[i][j], ah, bh[j]);
            }
        }
    };

    const int NIT = K >> 5;
    prefetch(0, 0);
    asm volatile("cp.async.commit_group;\n" ::: "memory");
    prefetch(1, 1);
    asm volatile("cp.async.commit_group;\n" ::: "memory");

    for (int it = 0; it < NIT; it++) {
        if (it + 1 < NIT) {
            asm volatile("cp.async.wait_group 1;\n" ::: "memory");
        } else {
            asm volatile("cp.async.wait_group 0;\n" ::: "memory");
        }
        __syncthreads();
        if (it + 2 < NIT) {
            prefetch(it + 2, (it + 2) % 3);
            asm volatile("cp.async.commit_group;\n" ::: "memory");
        }
        compute(it % 3);
    }

#pragma unroll
    for (int i = 0; i < 4; i++)
#pragma unroll
        for (int j = 0; j < 4; j++) {
            const int r0 = m0 + warp_m * 64 + i * 16 + (lane >> 2);
            const int cc = n0 + warp_n * 32 + j * 8 + (lane & 3) * 2;
            float2 u;
            u.x = acc[i][j][0]; u.y = acc[i][j][1];
            *(float2*)(C + (size_t)r0 * N + cc) = u;
            u.x = acc[i][j][2]; u.y = acc[i][j][3];
            *(float2*)(C + (size_t)(r0 + 8) * N + cc) = u;
        }
}

// ---------------- RoPE + bf16 hi/lo split (Q scaled 0.125) ----------------
__global__ void rope_split_kernel(
    const float* __restrict__ q, const float* __restrict__ k,
    __nv_bfloat16* __restrict__ qh, __nv_bfloat16* __restrict__ ql,
    __nv_bfloat16* __restrict__ kh, __nv_bfloat16* __restrict__ kl) {
    const int idx = blockIdx.x * 256 + threadIdx.x;
    const int total = M_ROWS * 40 * 32;
    if (idx >= total) return;
    const int p = idx & 31;
    const int rest = idx >> 5;
    const int head = rest % 40;
    const int m = rest / 40;
    const int s = m & (S_LEN - 1);

    const float invf = exp2f(-(float)p * 0.41524101186092027f);
    const float ang = (float)s * invf;
    float sn, c;
    sincosf(ang, &sn, &c);

    float x1, x2, scale;
    size_t o;
    __nv_bfloat16 *dh, *dl;
    if (head < 32) {
        o = (size_t)m * 2048 + head * 64;
        x1 = q[o + p]; x2 = q[o + p + 32];
        scale = 0.125f; dh = qh; dl = ql;
    } else {
        o = (size_t)m * 512 + (head - 32) * 64;
        x1 = k[o + p]; x2 = k[o + p + 32];
        scale = 1.0f; dh = kh; dl = kl;
    }
    const float y1 = (x1 * c - x2 * sn) * scale;
    const float y2 = (x2 * c + x1 * sn) * scale;
    const __nv_bfloat16 h1 = __float2bfloat16(y1);
    const __nv_bfloat16 h2 = __float2bfloat16(y2);
    dh[o + p]      = h1;
    dh[o + p + 32] = h2;
    dl[o + p]      = __float2bfloat16(y1 - __bfloat162float(h1));
    dl[o + p + 32] = __float2bfloat16(y2 - __bfloat162float(h2));
}

// ---------------- tensor-core windowed attention (bf16x3) ----------------
// Emits fp16 (single plane) for the fp16 O-projection.
__global__ __launch_bounds__(256) void attn_tc(
    const __nv_bfloat16* __restrict__ qh_, const __nv_bfloat16* __restrict__ ql_,
    const __nv_bfloat16* __restrict__ kh_, const __nv_bfloat16* __restrict__ kl_,
    const __nv_bfloat16* __restrict__ vh_, const __nv_bfloat16* __restrict__ vl_,
    __half* __restrict__ oatt) {
    extern __shared__ __align__(16) unsigned char smraw[];
    const unsigned SB = smem_u32(smraw);
    const unsigned QHI = SB, QLO = SB + 18432u;
    const unsigned KHI = SB + 36864u;  // + p*9216 for KLO/VHI/VLO

    const int tid = threadIdx.x, lane = tid & 31, w = tid >> 5;
    const int t128 = blockIdx.x;
    const int h = blockIdx.y;
    const int z = blockIdx.z;
    const int b = z >> 4, n = z & 15;
    const int kvh = h >> 2;

    {
        const size_t qrow0 = (size_t)(b * S_LEN + n * 256 + t128 * 128);
        for (int g = tid; g < 2048; g += 256) {
            const int p = g >> 10, r = (g >> 3) & 127, c8 = g & 7;
            const __nv_bfloat16* src =
                (p ? ql_ : qh_) + (qrow0 + r) * 2048 + h * 64 + c8 * 8;
            cp16((p ? QLO : QHI) + (unsigned)r * 144u + (unsigned)c8 * 16u, src);
        }
        asm volatile("cp.async.commit_group;\n" ::: "memory");
        asm volatile("cp.async.wait_group 0;\n" ::: "memory");
        __syncthreads();
    }

    unsigned qfh[4][4], qfl[4][4];
    {
        const unsigned rr = (unsigned)(w * 16 + (lane & 15));
        const unsigned cb = (unsigned)((lane >> 4) * 16);
#pragma unroll
        for (int ks = 0; ks < 4; ks++) {
            ldsm4(qfh[ks], QHI + rr * 144u + (unsigned)ks * 32u + cb);
            ldsm4(qfl[ks], QLO + rr * 144u + (unsigned)ks * 32u + cb);
        }
    }

    float oacc[8][4];
#pragma unroll
    for (int j = 0; j < 8; j++)
#pragma unroll
        for (int u = 0; u < 4; u++) oacc[j][u] = 0.f;
    float m0 = -1e30f, m1 = -1e30f, l0 = 0.f, l1 = 0.f;

    const int rbase = t128 * 128 + w * 16 + (lane >> 2);
    int c_lo = 2 * t128;
    if (n == 0 && c_lo < 4) c_lo = 4;
    const int c_hi = (t128 == 0) ? 5 : 7;

    for (int c = c_lo; c <= c_hi; c++) {
        __syncthreads();
        {
            const size_t srow0 = (size_t)(b * S_LEN + (n - 1) * 256 + c * 64);
            for (int g = tid; g < 2048; g += 256) {
                const int p = g >> 9, r = (g >> 3) & 63, c8 = g & 7;
                const __nv_bfloat16* sp =
                    (p == 0 ? kh_ : p == 1 ? kl_ : p == 2 ? vh_ : vl_);
                cp16(KHI + (unsigned)p * 9216u + (unsigned)r * 144u +
                         (unsigned)c8 * 16u,
                     sp + (srow0 + r) * 512 + kvh * 64 + c8 * 8);
            }
            asm volatile("cp.async.commit_group;\n" ::: "memory");
            asm volatile("cp.async.wait_group 0;\n" ::: "memory");
            __syncthreads();
        }

        // ---- scores ----
        float sf[8][4];
#pragma unroll
        for (int j = 0; j < 8; j++)
#pragma unroll
            for (int u = 0; u < 4; u++) sf[j][u] = 0.f;

        const unsigned kb = (unsigned)((lane >> 4) * 16);
#pragma unroll
        for (int ks = 0; ks < 4; ks++) {
#pragma unroll
            for (int kg = 0; kg < 4; kg++) {
                const unsigned off = (unsigned)(kg * 16 + (lane & 15)) * 144u +
                                     (unsigned)ks * 32u + kb;
                unsigned th[4], tl[4];
                ldsm4(th, KHI + off);
                ldsm4(tl, KHI + 9216u + off);
                unsigned bh0[2] = {th[0], th[2]}, bh1[2] = {th[1], th[3]};
                unsigned bl0[2] = {tl[0], tl[2]}, bl1[2] = {tl[1], tl[3]};
                mma16816(sf[2 * kg],     qfh[ks], bh0);
                mma16816(sf[2 * kg + 1], qfh[ks], bh1);
                mma16816(sf[2 * kg],     qfh[ks], bl0);
                mma16816(sf[2 * kg + 1], qfh[ks], bl1);
                mma16816(sf[2 * kg],     qfl[ks], bh0);
                mma16816(sf[2 * kg + 1], qfl[ks], bh1);
            }
        }

        // ---- mask + online softmax (no MUFU) ----
        const int jb = c * 64 + (lane & 3) * 2;
        const float NEG = -1e30f;
#pragma unroll
        for (int j8 = 0; j8 < 8; j8++) {
            const int j0 = jb + j8 * 8;
            if (j0 < rbase     || j0 > rbase + 256) sf[j8][0] = NEG;
            if (j0 + 1 < rbase || j0 + 1 > rbase + 256) sf[j8][1] = NEG;
            if (j0 < rbase + 8 || j0 > rbase + 264) sf[j8][2] = NEG;
            if (j0 + 1 < rbase + 8 || j0 + 1 > rbase + 264) sf[j8][3] = NEG;
        }
        float mx0 = NEG, mx1 = NEG;
#pragma unroll
        for (int j8 = 0; j8 < 8; j8++) {
            mx0 = fmaxf(mx0, fmaxf(sf[j8][0], sf[j8][1]));
            mx1 = fmaxf(mx1, fmaxf(sf[j8][2], sf[j8][3]));
        }
        mx0 = fmaxf(mx0, __shfl_xor_sync(0xffffffffu, mx0, 1));
        mx0 = fmaxf(mx0, __shfl_xor_sync(0xffffffffu, mx0, 2));
        mx1 = fmaxf(mx1, __shfl_xor_sync(0xffffffffu, mx1, 1));
        mx1 = fmaxf(mx1, __shfl_xor_sync(0xffffffffu, mx1, 2));
        const float mn0 = fmaxf(m0, mx0), mn1 = fmaxf(m1, mx1);
        const float a0 = fexp(m0 - mn0), a1 = fexp(m1 - mn1);
        m0 = mn0; m1 = mn1;
        float s0 = 0.f, s1 = 0.f;
#pragma unroll
        for (int j8 = 0; j8 < 8; j8++) {
            sf[j8][0] = fexp(sf[j8][0] - mn0);
            sf[j8][1] = fexp(sf[j8][1] - mn0);
            sf[j8][2] = fexp(sf[j8][2] - mn1);
            sf[j8][3] = fexp(sf[j8][3] - mn1);
            s0 += sf[j8][0] + sf[j8][1];
            s1 += sf[j8][2] + sf[j8][3];
        }
        s0 += __shfl_xor_sync(0xffffffffu, s0, 1);
        s0 += __shfl_xor_sync(0xffffffffu, s0, 2);
        s1 += __shfl_xor_sync(0xffffffffu, s1, 1);
        s1 += __shfl_xor_sync(0xffffffffu, s1, 2);
        l0 = l0 * a0 + s0;
        l1 = l1 * a1 + s1;
#pragma unroll
        for (int j = 0; j < 8; j++) {
            oacc[j][0] *= a0; oacc[j][1] *= a0;
            oacc[j][2] *= a1; oacc[j][3] *= a1;
        }

        // ---- PV ----
#pragma unroll
        for (int kg = 0; kg < 4; kg++) {
            unsigned pah[4], pal[4];
            pah[0] = pack_hl(sf[2 * kg][0],     sf[2 * kg][1],     &pal[0]);
            pah[1] = pack_hl(sf[2 * kg][2],     sf[2 * kg][3],     &pal[1]);
            pah[2] = pack_hl(sf[2 * kg + 1][0], sf[2 * kg + 1][1], &pal[2]);
            pah[3] = pack_hl(sf[2 * kg + 1][2], sf[2 * kg + 1][3], &pal[3]);
            const unsigned vrow =
                (unsigned)(kg * 16 + ((lane >> 3) & 1) * 8 + (lane & 7)) * 144u;
#pragma unroll
            for (int dh = 0; dh < 4; dh++) {
                const unsigned voff =
                    vrow + (unsigned)dh * 32u + (unsigned)(lane >> 4) * 16u;
                unsigned vh4[4], vl4[4];
                ldsm4t(vh4, KHI + 18432u + voff);
                ldsm4t(vl4, KHI + 27648u + voff);
                unsigned vbh0[2] = {vh4[0], vh4[1]}, vbh1[2] = {vh4[2], vh4[3]};
                unsigned vbl0[2] = {vl4[0], vl4[1]}, vbl1[2] = {vl4[2], vl4[3]};
                mma16816(oacc[2 * dh],     pah, vbh0);
                mma16816(oacc[2 * dh + 1], pah, vbh1);
                mma16816(oacc[2 * dh],     pah, vbl0);
                mma16816(oacc[2 * dh + 1], pah, vbl1);
                mma16816(oacc[2 * dh],     pal, vbh0);
                mma16816(oacc[2 * dh + 1], pal, vbh1);
            }
        }
    }

    // ---- epilogue: normalize, fp16, store ----
    const float inv0 = 1.f / l0, inv1 = 1.f / l1;
    const size_t grow0 =
        (size_t)(b * S_LEN + n * 256 + t128 * 128 + w * 16 + (lane >> 2));
    const int colb = h * 64 + (lane & 3) * 2;
#pragma unroll
    for (int j8 = 0; j8 < 8; j8++) {
        const unsigned u0 = pack_h16(oacc[j8][0] * inv0, oacc[j8][1] * inv0);
        const unsigned u1 = pack_h16(oacc[j8][2] * inv1, oacc[j8][3] * inv1);
        const size_t i0 = grow0 * 2048 + colb + j8 * 8;
        const size_t i1 = i0 + 8 * 2048;
        *(unsigned*)(oatt + i0) = u0;
        *(unsigned*)(oatt + i1) = u1;
    }
}

// ---------------- launch ----------------
extern "C" void kernel_launch(void* const* d_in, const int* in_sizes, int n_in,
                              void* d_out, int out_size) {
    const float* hs = (const float*)d_in[0];
    const float* Wq = (const float*)d_in[1];
    const float* Wk = (const float*)d_in[2];
    const float* Wv = (const float*)d_in[3];
    const float* Wo = (const float*)d_in[4];
    float* out = (float*)d_out;

    float *q, *k, *v;
    __half *hs16, *wq16, *wk16, *wv16, *wo16, *att16;
    __nv_bfloat16 *qh, *ql, *kh, *kl, *vh, *vl;
    cudaGetSymbolAddress((void**)&q, g_q);
    cudaGetSymbolAddress((void**)&k, g_k);
    cudaGetSymbolAddress((void**)&v, g_v);
    cudaGetSymbolAddress((void**)&hs16, g_hs16);
    cudaGetSymbolAddress((void**)&wq16, g_wq16);
    cudaGetSymbolAddress((void**)&wk16, g_wk16);
    cudaGetSymbolAddress((void**)&wv16, g_wv16);
    cudaGetSymbolAddress((void**)&wo16, g_wo16);
    cudaGetSymbolAddress((void**)&att16, g_att16);
    cudaGetSymbolAddress((void**)&qh, g_qh);
    cudaGetSymbolAddress((void**)&ql, g_ql);
    cudaGetSymbolAddress((void**)&kh, g_kh);
    cudaGetSymbolAddress((void**)&kl, g_kl);
    cudaGetSymbolAddress((void**)&vh, g_vh);
    cudaGetSymbolAddress((void**)&vl, g_vl);

    cudaFuncSetAttribute(gemm_f16,
                         cudaFuncAttributeMaxDynamicSharedMemorySize, 49152);
    cudaFuncSetAttribute(attn_tc,
                         cudaFuncAttributeMaxDynamicSharedMemorySize, 73728);

    // launches 0-2, then gemmQ at #4 overall (ncu capture slot)
    cvt16_kernel<<<(M_ROWS * 2048 / 4 + 255) / 256, 256>>>(hs, hs16, M_ROWS * 2048 / 4);
    cvt16_kernel<<<(2048 * 2048 / 4 + 255) / 256, 256>>>(Wq, wq16, 2048 * 2048 / 4);
    cvt16_kernel<<<(512 * 2048 / 4 + 255) / 256, 256>>>(Wk, wk16, 512 * 2048 / 4);
    gemm_f16<<<dim3(2048 / 128, M_ROWS / 128), 256, 49152>>>(
        hs16, wq16, q, M_ROWS, 2048, 2048);
    gemm_f16<<<dim3(512 / 128, M_ROWS / 128), 256, 49152>>>(
        hs16, wk16, k, M_ROWS, 512, 2048);
    cvt16_kernel<<<(512 * 2048 / 4 + 255) / 256, 256>>>(Wv, wv16, 512 * 2048 / 4);
    gemm_f16<<<dim3(512 / 128, M_ROWS / 128), 256, 49152>>>(
        hs16, wv16, v, M_ROWS, 512, 2048);

    rope_split_kernel<<<(M_ROWS * 40 * 32 + 255) / 256, 256>>>(q, k, qh, ql, kh, kl);
    split_kernel<<<(M_ROWS * 512 / 4 + 255) / 256, 256>>>(v, vh, vl, M_ROWS * 512 / 4);

    attn_tc<<<dim3(2, 32, 32), 256, 73728>>>(qh, ql, kh, kl, vh, vl, att16);

    cvt16_kernel<<<(2048 * 2048 / 4 + 255) / 256, 256>>>(Wo, wo16, 2048 * 2048 / 4);
    gemm_f16<<<dim3(2048 / 128, M_ROWS / 128), 256, 49152>>>(
        att16, wo16, out, M_ROWS, 2048, 2048);
}

// round 14
// speedup vs baseline: 5.8246x; 1.2319x over previous
#include <cuda_runtime.h>
#include <cuda_fp16.h>
#include <math.h>

#define M_ROWS 8192
#define S_LEN  4096

// ---------------- scratch ----------------
__device__ float g_q[(size_t)M_ROWS * 2048];
__device__ float g_k[(size_t)M_ROWS * 512];
__device__ float g_v[(size_t)M_ROWS * 512];

// fp16 planes
__device__ __half g_hs16[(size_t)M_ROWS * 2048];
__device__ __half g_wq16[(size_t)2048 * 2048];
__device__ __half g_wk16[(size_t)512 * 2048];
__device__ __half g_wv16[(size_t)512 * 2048];
__device__ __half g_wo16[(size_t)2048 * 2048];
__device__ __half g_att16[(size_t)M_ROWS * 2048];
__device__ __half g_qa16[(size_t)M_ROWS * 2048];  // Q after RoPE, scaled
__device__ __half g_ka16[(size_t)M_ROWS * 512];   // K after RoPE
__device__ __half g_va16[(size_t)M_ROWS * 512];   // V

// ---------------- helpers ----------------
__device__ __forceinline__ unsigned smem_u32(const void* p) {
    unsigned r;
    asm("{ .reg .u64 t; cvta.to.shared.u64 t, %1; cvt.u32.u64 %0, t; }"
        : "=r"(r) : "l"(p));
    return r;
}
__device__ __forceinline__ void cp16(unsigned dst, const void* src) {
    asm volatile("cp.async.cg.shared.global [%0], [%1], 16;\n"
                 :: "r"(dst), "l"(src) : "memory");
}
__device__ __forceinline__ void ldsm4(unsigned* r, unsigned addr) {
    asm volatile("ldmatrix.sync.aligned.m8n8.x4.shared.b16 {%0,%1,%2,%3}, [%4];"
                 : "=r"(r[0]), "=r"(r[1]), "=r"(r[2]), "=r"(r[3]) : "r"(addr));
}
__device__ __forceinline__ void ldsm4t(unsigned* r, unsigned addr) {
    asm volatile("ldmatrix.sync.aligned.m8n8.x4.trans.shared.b16 {%0,%1,%2,%3}, [%4];"
                 : "=r"(r[0]), "=r"(r[1]), "=r"(r[2]), "=r"(r[3]) : "r"(addr));
}
// fp16 mma, fp32 accum
__device__ __forceinline__ void mma16816h(float* d, const unsigned* a, const unsigned* b) {
    asm volatile(
        "mma.sync.aligned.m16n8k16.row.col.f32.f16.f16.f32 "
        "{%0,%1,%2,%3}, {%4,%5,%6,%7}, {%8,%9}, {%0,%1,%2,%3};"
        : "+f"(d[0]), "+f"(d[1]), "+f"(d[2]), "+f"(d[3])
        : "r"(a[0]), "r"(a[1]), "r"(a[2]), "r"(a[3]), "r"(b[0]), "r"(b[1]));
}
// exp on fma/alu pipes only
__device__ __forceinline__ float fexp(float x) {
    float t = fmaxf(x * 1.44269504f, -120.0f);
    float r = t + 12582912.0f;
    int   n = __float_as_int(r) - 0x4B400000;
    float f = t - (r - 12582912.0f);
    float p = 0.00133335581f;
    p = fmaf(p, f, 0.00961812910f);
    p = fmaf(p, f, 0.0555041086f);
    p = fmaf(p, f, 0.240226507f);
    p = fmaf(p, f, 0.693147180f);
    p = fmaf(p, f, 1.0f);
    return __int_as_float(__float_as_int(p) + (n << 23));
}
__device__ __forceinline__ unsigned pack_h16(float a, float b) {
    __half2 H; H.x = __float2half_rn(a); H.y = __float2half_rn(b);
    return *(unsigned*)&H;
}

// ---------------- converts ----------------
__global__ void cvt16_kernel(const float* __restrict__ x,
                             __half* __restrict__ hi, int n4) {
    const int i = blockIdx.x * 256 + threadIdx.x;
    if (i >= n4) return;
    const float4 vv = ((const float4*)x)[i];
    __half2* H = (__half2*)hi;
    __half2 t;
    t.x = __float2half_rn(vv.x); t.y = __float2half_rn(vv.y); H[2 * i] = t;
    t.x = __float2half_rn(vv.z); t.y = __float2half_rn(vv.w); H[2 * i + 1] = t;
}

// ---------------- fp16 single-pass GEMM (NT) — unchanged from R12 ----------------
#define GSTAGEF 16384u

__global__ __launch_bounds__(256, 2) void gemm_f16(
    const __half* __restrict__ A, const __half* __restrict__ Whi,
    float* __restrict__ C, int M, int N, int K) {
    extern __shared__ __align__(16) unsigned char smraw[];
    const unsigned sbase = smem_u32(smraw);

    const int tid = threadIdx.x;
    const int wid = tid >> 5, lane = tid & 31;
    const int warp_m = wid >> 2;
    const int warp_n = wid & 3;
    const int m0 = blockIdx.y << 7;
    const int n0 = blockIdx.x << 7;

    const __half* srcs[2] = {A + (size_t)m0 * K, Whi + (size_t)n0 * K};

    float acc[4][4][4];
#pragma unroll
    for (int i = 0; i < 4; i++)
#pragma unroll
        for (int j = 0; j < 4; j++)
#pragma unroll
            for (int u = 0; u < 4; u++) acc[i][j][u] = 0.f;

    const int ldr = tid >> 1;
    const int ldc = (tid & 1) * 2;

    auto prefetch = [&](int it, int bufi) {
        const int k0 = it * 32;
        const unsigned bufbase = sbase + (unsigned)bufi * GSTAGEF;
#pragma unroll
        for (int p = 0; p < 2; p++) {
            const __half* src = srcs[p] + (size_t)ldr * K + k0 + ldc * 8;
            const unsigned splane = bufbase + p * 8192u;
#pragma unroll
            for (int cc = 0; cc < 2; cc++) {
                const int c = ldc + cc;
                const unsigned dst =
                    splane + ldr * 64u + (unsigned)((c ^ ((ldr >> 1) & 3)) << 4);
                cp16(dst, src + cc * 8);
            }
        }
    };

    auto compute = [&](int bufi) {
        const unsigned base = sbase + (unsigned)bufi * GSTAGEF;
        const int arow = (lane & 7) + ((lane >> 3) & 1) * 8;
        const int khalf = (lane >> 4) & 1;
#pragma unroll
        for (int ks = 0; ks < 2; ks++) {
            const int c = ks * 2 + khalf;
            unsigned bh[4][2];
#pragma unroll
            for (int half = 0; half < 2; half++) {
                const int row = warp_n * 32 + half * 16 + arow;
                const unsigned off =
                    row * 64u + (unsigned)((c ^ ((row >> 1) & 3)) << 4);
                unsigned t[4];
                ldsm4(t, base + 8192u + off);
                bh[half * 2 + 0][0] = t[0]; bh[half * 2 + 0][1] = t[2];
                bh[half * 2 + 1][0] = t[1]; bh[half * 2 + 1][1] = t[3];
            }
#pragma unroll
            for (int i = 0; i < 4; i++) {
                const int row = warp_m * 64 + i * 16 + arow;
                const unsigned off =
                    row * 64u + (unsigned)((c ^ ((row >> 1) & 3)) << 4);
                unsigned ah[4];
                ldsm4(ah, base + off);
#pragma unroll
                for (int j = 0; j < 4; j++) mma16816h(acc[i][j], ah, bh[j]);
            }
        }
    };

    const int NIT = K >> 5;
    prefetch(0, 0);
    asm volatile("cp.async.commit_group;\n" ::: "memory");
    prefetch(1, 1);
    asm volatile("cp.async.commit_group;\n" ::: "memory");

    for (int it = 0; it < NIT; it++) {
        if (it + 1 < NIT) {
            asm volatile("cp.async.wait_group 1;\n" ::: "memory");
        } else {
            asm volatile("cp.async.wait_group 0;\n" ::: "memory");
        }
        __syncthreads();
        if (it + 2 < NIT) {
            prefetch(it + 2, (it + 2) % 3);
            asm volatile("cp.async.commit_group;\n" ::: "memory");
        }
        compute(it % 3);
    }

#pragma unroll
    for (int i = 0; i < 4; i++)
#pragma unroll
        for (int j = 0; j < 4; j++) {
            const int r0 = m0 + warp_m * 64 + i * 16 + (lane >> 2);
            const int cc = n0 + warp_n * 32 + j * 8 + (lane & 3) * 2;
            float2 u;
            u.x = acc[i][j][0]; u.y = acc[i][j][1];
            *(float2*)(C + (size_t)r0 * N + cc) = u;
            u.x = acc[i][j][2]; u.y = acc[i][j][3];
            *(float2*)(C + (size_t)(r0 + 8) * N + cc) = u;
        }
}

// ---------------- RoPE -> fp16 (Q scaled 0.125) ----------------
__global__ void rope16_kernel(
    const float* __restrict__ q, const float* __restrict__ k,
    __half* __restrict__ qa, __half* __restrict__ ka) {
    const int idx = blockIdx.x * 256 + threadIdx.x;
    const int total = M_ROWS * 40 * 32;
    if (idx >= total) return;
    const int p = idx & 31;
    const int rest = idx >> 5;
    const int head = rest % 40;
    const int m = rest / 40;
    const int s = m & (S_LEN - 1);

    const float invf = exp2f(-(float)p * 0.41524101186092027f);
    const float ang = (float)s * invf;
    float sn, c;
    sincosf(ang, &sn, &c);

    float x1, x2, scale;
    size_t o;
    __half* d;
    if (head < 32) {
        o = (size_t)m * 2048 + head * 64;
        x1 = q[o + p]; x2 = q[o + p + 32];
        scale = 0.125f; d = qa;
    } else {
        o = (size_t)m * 512 + (head - 32) * 64;
        x1 = k[o + p]; x2 = k[o + p + 32];
        scale = 1.0f; d = ka;
    }
    d[o + p]      = __float2half_rn((x1 * c - x2 * sn) * scale);
    d[o + p + 32] = __float2half_rn((x2 * c + x1 * sn) * scale);
}

// ---------------- tensor-core windowed attention (fp16 single-pass) --------
// grid (2, 32, 32): (q-tile of 128, head, b*16+n). 256 threads = 8 warps,
// warp w owns q rows t128*128 + [16w, 16w+15]. Key chunks of 64; online
// softmax (fexp, no MUFU); P in registers fp16. Emits fp16 att.
// smem: Q[128][144B] = 18432 | K[64][144] = 9216 | V[64][144] = 9216.
__global__ __launch_bounds__(256) void attn_tc(
    const __half* __restrict__ q_, const __half* __restrict__ k_,
    const __half* __restrict__ v_, __half* __restrict__ oatt) {
    extern __shared__ __align__(16) unsigned char smraw[];
    const unsigned SB = smem_u32(smraw);
    const unsigned QS = SB;
    const unsigned KS = SB + 18432u;
    const unsigned VS = SB + 27648u;

    const int tid = threadIdx.x, lane = tid & 31, w = tid >> 5;
    const int t128 = blockIdx.x;
    const int h = blockIdx.y;
    const int z = blockIdx.z;
    const int b = z >> 4, n = z & 15;
    const int kvh = h >> 2;

    // Q tile: 128 rows x 64 fp16
    {
        const size_t qrow0 = (size_t)(b * S_LEN + n * 256 + t128 * 128);
        for (int g = tid; g < 1024; g += 256) {
            const int r = g >> 3, c8 = g & 7;
            cp16(QS + (unsigned)r * 144u + (unsigned)c8 * 16u,
                 q_ + (qrow0 + r) * 2048 + h * 64 + c8 * 8);
        }
        asm volatile("cp.async.commit_group;\n" ::: "memory");
        asm volatile("cp.async.wait_group 0;\n" ::: "memory");
        __syncthreads();
    }

    // Q fragments, held for all chunks
    unsigned qf[4][4];
    {
        const unsigned rr = (unsigned)(w * 16 + (lane & 15));
        const unsigned cb = (unsigned)((lane >> 4) * 16);
#pragma unroll
        for (int ks = 0; ks < 4; ks++)
            ldsm4(qf[ks], QS + rr * 144u + (unsigned)ks * 32u + cb);
    }

    float oacc[8][4];
#pragma unroll
    for (int j = 0; j < 8; j++)
#pragma unroll
        for (int u = 0; u < 4; u++) oacc[j][u] = 0.f;
    float m0 = -1e30f, m1 = -1e30f, l0 = 0.f, l1 = 0.f;

    const int rbase = t128 * 128 + w * 16 + (lane >> 2);
    int c_lo = 2 * t128;
    if (n == 0 && c_lo < 4) c_lo = 4;
    const int c_hi = (t128 == 0) ? 5 : 7;

    for (int c = c_lo; c <= c_hi; c++) {
        __syncthreads();
        {
            const size_t srow0 = (size_t)(b * S_LEN + (n - 1) * 256 + c * 64);
            for (int g = tid; g < 1024; g += 256) {
                const int p = g >> 9, r = (g >> 3) & 63, c8 = g & 7;
                const __half* sp = p ? v_ : k_;
                cp16((p ? VS : KS) + (unsigned)r * 144u + (unsigned)c8 * 16u,
                     sp + (srow0 + r) * 512 + kvh * 64 + c8 * 8);
            }
            asm volatile("cp.async.commit_group;\n" ::: "memory");
            asm volatile("cp.async.wait_group 0;\n" ::: "memory");
            __syncthreads();
        }

        // ---- scores: 16 rows x 64 keys, single fp16 pass ----
        float sf[8][4];
#pragma unroll
        for (int j = 0; j < 8; j++)
#pragma unroll
            for (int u = 0; u < 4; u++) sf[j][u] = 0.f;

        const unsigned kb = (unsigned)((lane >> 4) * 16);
#pragma unroll
        for (int ks = 0; ks < 4; ks++) {
#pragma unroll
            for (int kg = 0; kg < 4; kg++) {
                const unsigned off = (unsigned)(kg * 16 + (lane & 15)) * 144u +
                                     (unsigned)ks * 32u + kb;
                unsigned th[4];
                ldsm4(th, KS + off);
                unsigned bh0[2] = {th[0], th[2]}, bh1[2] = {th[1], th[3]};
                mma16816h(sf[2 * kg],     qf[ks], bh0);
                mma16816h(sf[2 * kg + 1], qf[ks], bh1);
            }
        }

        // ---- mask + online softmax (no MUFU) ----
        const int jb = c * 64 + (lane & 3) * 2;
        const float NEG = -1e30f;
#pragma unroll
        for (int j8 = 0; j8 < 8; j8++) {
            const int j0 = jb + j8 * 8;
            if (j0 < rbase     || j0 > rbase + 256) sf[j8][0] = NEG;
            if (j0 + 1 < rbase || j0 + 1 > rbase + 256) sf[j8][1] = NEG;
            if (j0 < rbase + 8 || j0 > rbase + 264) sf[j8][2] = NEG;
            if (j0 + 1 < rbase + 8 || j0 + 1 > rbase + 264) sf[j8][3] = NEG;
        }
        float mx0 = NEG, mx1 = NEG;
#pragma unroll
        for (int j8 = 0; j8 < 8; j8++) {
            mx0 = fmaxf(mx0, fmaxf(sf[j8][0], sf[j8][1]));
            mx1 = fmaxf(mx1, fmaxf(sf[j8][2], sf[j8][3]));
        }
        mx0 = fmaxf(mx0, __shfl_xor_sync(0xffffffffu, mx0, 1));
        mx0 = fmaxf(mx0, __shfl_xor_sync(0xffffffffu, mx0, 2));
        mx1 = fmaxf(mx1, __shfl_xor_sync(0xffffffffu, mx1, 1));
        mx1 = fmaxf(mx1, __shfl_xor_sync(0xffffffffu, mx1, 2));
        const float mn0 = fmaxf(m0, mx0), mn1 = fmaxf(m1, mx1);
        const float a0 = fexp(m0 - mn0), a1 = fexp(m1 - mn1);
        m0 = mn0; m1 = mn1;
        float s0 = 0.f, s1 = 0.f;
#pragma unroll
        for (int j8 = 0; j8 < 8; j8++) {
            sf[j8][0] = fexp(sf[j8][0] - mn0);
            sf[j8][1] = fexp(sf[j8][1] - mn0);
            sf[j8][2] = fexp(sf[j8][2] - mn1);
            sf[j8][3] = fexp(sf[j8][3] - mn1);
            s0 += sf[j8][0] + sf[j8][1];
            s1 += sf[j8][2] + sf[j8][3];
        }
        s0 += __shfl_xor_sync(0xffffffffu, s0, 1);
        s0 += __shfl_xor_sync(0xffffffffu, s0, 2);
        s1 += __shfl_xor_sync(0xffffffffu, s1, 1);
        s1 += __shfl_xor_sync(0xffffffffu, s1, 2);
        l0 = l0 * a0 + s0;
        l1 = l1 * a1 + s1;
#pragma unroll
        for (int j = 0; j < 8; j++) {
            oacc[j][0] *= a0; oacc[j][1] *= a0;
            oacc[j][2] *= a1; oacc[j][3] *= a1;
        }

        // ---- PV: P (fp16 regs) x V (ldmatrix.trans) ----
#pragma unroll
        for (int kg = 0; kg < 4; kg++) {
            unsigned pa[4];
            pa[0] = pack_h16(sf[2 * kg][0],     sf[2 * kg][1]);
            pa[1] = pack_h16(sf[2 * kg][2],     sf[2 * kg][3]);
            pa[2] = pack_h16(sf[2 * kg + 1][0], sf[2 * kg + 1][1]);
            pa[3] = pack_h16(sf[2 * kg + 1][2], sf[2 * kg + 1][3]);
            const unsigned vrow =
                (unsigned)(kg * 16 + ((lane >> 3) & 1) * 8 + (lane & 7)) * 144u;
#pragma unroll
            for (int dh = 0; dh < 4; dh++) {
                const unsigned voff =
                    vrow + (unsigned)dh * 32u + (unsigned)(lane >> 4) * 16u;
                unsigned vh4[4];
                ldsm4t(vh4, VS + voff);
                unsigned vb0[2] = {vh4[0], vh4[1]}, vb1[2] = {vh4[2], vh4[3]};
                mma16816h(oacc[2 * dh],     pa, vb0);
                mma16816h(oacc[2 * dh + 1], pa, vb1);
            }
        }
    }

    // ---- epilogue: normalize, fp16, store ----
    const float inv0 = 1.f / l0, inv1 = 1.f / l1;
    const size_t grow0 =
        (size_t)(b * S_LEN + n * 256 + t128 * 128 + w * 16 + (lane >> 2));
    const int colb = h * 64 + (lane & 3) * 2;
#pragma unroll
    for (int j8 = 0; j8 < 8; j8++) {
        const unsigned u0 = pack_h16(oacc[j8][0] * inv0, oacc[j8][1] * inv0);
        const unsigned u1 = pack_h16(oacc[j8][2] * inv1, oacc[j8][3] * inv1);
        const size_t i0 = grow0 * 2048 + colb + j8 * 8;
        const size_t i1 = i0 + 8 * 2048;
        *(unsigned*)(oatt + i0) = u0;
        *(unsigned*)(oatt + i1) = u1;
    }
}

// ---------------- launch ----------------
extern "C" void kernel_launch(void* const* d_in, const int* in_sizes, int n_in,
                              void* d_out, int out_size) {
    const float* hs = (const float*)d_in[0];
    const float* Wq = (const float*)d_in[1];
    const float* Wk = (const float*)d_in[2];
    const float* Wv = (const float*)d_in[3];
    const float* Wo = (const float*)d_in[4];
    float* out = (float*)d_out;

    float *q, *k, *v;
    __half *hs16, *wq16, *wk16, *wv16, *wo16, *att16, *qa16, *ka16, *va16;
    cudaGetSymbolAddress((void**)&q, g_q);
    cudaGetSymbolAddress((void**)&k, g_k);
    cudaGetSymbolAddress((void**)&v, g_v);
    cudaGetSymbolAddress((void**)&hs16, g_hs16);
    cudaGetSymbolAddress((void**)&wq16, g_wq16);
    cudaGetSymbolAddress((void**)&wk16, g_wk16);
    cudaGetSymbolAddress((void**)&wv16, g_wv16);
    cudaGetSymbolAddress((void**)&wo16, g_wo16);
    cudaGetSymbolAddress((void**)&att16, g_att16);
    cudaGetSymbolAddress((void**)&qa16, g_qa16);
    cudaGetSymbolAddress((void**)&ka16, g_ka16);
    cudaGetSymbolAddress((void**)&va16, g_va16);

    cudaFuncSetAttribute(gemm_f16,
                         cudaFuncAttributeMaxDynamicSharedMemorySize, 49152);
    cudaFuncSetAttribute(attn_tc,
                         cudaFuncAttributeMaxDynamicSharedMemorySize, 36864);

    // launches 0-2, then gemmQ at #4 overall (ncu capture slot)
    cvt16_kernel<<<(M_ROWS * 2048 / 4 + 255) / 256, 256>>>(hs, hs16, M_ROWS * 2048 / 4);
    cvt16_kernel<<<(2048 * 2048 / 4 + 255) / 256, 256>>>(Wq, wq16, 2048 * 2048 / 4);
    cvt16_kernel<<<(512 * 2048 / 4 + 255) / 256, 256>>>(Wk, wk16, 512 * 2048 / 4);
    gemm_f16<<<dim3(2048 / 128, M_ROWS / 128), 256, 49152>>>(
        hs16, wq16, q, M_ROWS, 2048, 2048);
    gemm_f16<<<dim3(512 / 128, M_ROWS / 128), 256, 49152>>>(
        hs16, wk16, k, M_ROWS, 512, 2048);
    cvt16_kernel<<<(512 * 2048 / 4 + 255) / 256, 256>>>(Wv, wv16, 512 * 2048 / 4);
    gemm_f16<<<dim3(512 / 128, M_ROWS / 128), 256, 49152>>>(
        hs16, wv16, v, M_ROWS, 512, 2048);

    // RoPE -> fp16 Q/K; V -> fp16
    rope16_kernel<<<(M_ROWS * 40 * 32 + 255) / 256, 256>>>(q, k, qa16, ka16);
    cvt16_kernel<<<(M_ROWS * 512 / 4 + 255) / 256, 256>>>(v, va16, M_ROWS * 512 / 4);

    // fp16 tensor-core attention
    attn_tc<<<dim3(2, 32, 32), 256, 36864>>>(qa16, ka16, va16, att16);

    // Output projection
    cvt16_kernel<<<(2048 * 2048 / 4 + 255) / 256, 256>>>(Wo, wo16, 2048 * 2048 / 4);
    gemm_f16<<<dim3(2048 / 128, M_ROWS / 128), 256, 49152>>>(
        att16, wo16, out, M_ROWS, 2048, 2048);
}

// round 15
// speedup vs baseline: 6.1282x; 1.0521x over previous
#include <cuda_runtime.h>
#include <cuda_fp16.h>
#include <math.h>

#define M_ROWS 8192
#define S_LEN  4096

// ---------------- scratch ----------------
__device__ float g_q[(size_t)M_ROWS * 2048];
__device__ float g_k[(size_t)M_ROWS * 512];
__device__ float g_v[(size_t)M_ROWS * 512];

// fp16 planes
__device__ __half g_hs16[(size_t)M_ROWS * 2048];
__device__ __half g_wq16[(size_t)2048 * 2048];
__device__ __half g_wk16[(size_t)512 * 2048];
__device__ __half g_wv16[(size_t)512 * 2048];
__device__ __half g_wo16[(size_t)2048 * 2048];
__device__ __half g_att16[(size_t)M_ROWS * 2048];
__device__ __half g_qa16[(size_t)M_ROWS * 2048];  // Q after RoPE, scaled
__device__ __half g_ka16[(size_t)M_ROWS * 512];   // K after RoPE
__device__ __half g_va16[(size_t)M_ROWS * 512];   // V

// ---------------- helpers ----------------
__device__ __forceinline__ unsigned smem_u32(const void* p) {
    unsigned r;
    asm("{ .reg .u64 t; cvta.to.shared.u64 t, %1; cvt.u32.u64 %0, t; }"
        : "=r"(r) : "l"(p));
    return r;
}
__device__ __forceinline__ void cp16(unsigned dst, const void* src) {
    asm volatile("cp.async.cg.shared.global [%0], [%1], 16;\n"
                 :: "r"(dst), "l"(src) : "memory");
}
__device__ __forceinline__ void ldsm4(unsigned* r, unsigned addr) {
    asm volatile("ldmatrix.sync.aligned.m8n8.x4.shared.b16 {%0,%1,%2,%3}, [%4];"
                 : "=r"(r[0]), "=r"(r[1]), "=r"(r[2]), "=r"(r[3]) : "r"(addr));
}
__device__ __forceinline__ void ldsm4t(unsigned* r, unsigned addr) {
    asm volatile("ldmatrix.sync.aligned.m8n8.x4.trans.shared.b16 {%0,%1,%2,%3}, [%4];"
                 : "=r"(r[0]), "=r"(r[1]), "=r"(r[2]), "=r"(r[3]) : "r"(addr));
}
// fp16 mma, fp32 accum
__device__ __forceinline__ void mma16816h(float* d, const unsigned* a, const unsigned* b) {
    asm volatile(
        "mma.sync.aligned.m16n8k16.row.col.f32.f16.f16.f32 "
        "{%0,%1,%2,%3}, {%4,%5,%6,%7}, {%8,%9}, {%0,%1,%2,%3};"
        : "+f"(d[0]), "+f"(d[1]), "+f"(d[2]), "+f"(d[3])
        : "r"(a[0]), "r"(a[1]), "r"(a[2]), "r"(a[3]), "r"(b[0]), "r"(b[1]));
}
// exp on fma/alu pipes only
__device__ __forceinline__ float fexp(float x) {
    float t = fmaxf(x * 1.44269504f, -120.0f);
    float r = t + 12582912.0f;
    int   n = __float_as_int(r) - 0x4B400000;
    float f = t - (r - 12582912.0f);
    float p = 0.00133335581f;
    p = fmaf(p, f, 0.00961812910f);
    p = fmaf(p, f, 0.0555041086f);
    p = fmaf(p, f, 0.240226507f);
    p = fmaf(p, f, 0.693147180f);
    p = fmaf(p, f, 1.0f);
    return __int_as_float(__float_as_int(p) + (n << 23));
}
__device__ __forceinline__ unsigned pack_h16(float a, float b) {
    __half2 H; H.x = __float2half_rn(a); H.y = __float2half_rn(b);
    return *(unsigned*)&H;
}

// ---------------- converts ----------------
__global__ void cvt16_kernel(const float* __restrict__ x,
                             __half* __restrict__ hi, int n4) {
    const int i = blockIdx.x * 256 + threadIdx.x;
    if (i >= n4) return;
    const float4 vv = ((const float4*)x)[i];
    __half2* H = (__half2*)hi;
    __half2 t;
    t.x = __float2half_rn(vv.x); t.y = __float2half_rn(vv.y); H[2 * i] = t;
    t.x = __float2half_rn(vv.z); t.y = __float2half_rn(vv.w); H[2 * i + 1] = t;
}

// ---------------- fp16 single-pass GEMM (NT), fat tiles ----------------
// C[m][n] = sum_k A[m][k]*W[n][k], both fp16, fp32 accum.
// CTA 128x256, K-tile 32, 256 thr (8 warps 2x4, warp tile 64x64).
// Stage = [A 8K][W 16K] = 24KB, 3-stage ring, 1 CTA/SM.
// mma:ldsm = 4:1 (vs 2.67 for the 64x32 warp tile).
#define GSTAGEF 24576u

__global__ __launch_bounds__(256, 1) void gemm_f16(
    const __half* __restrict__ A, const __half* __restrict__ Whi,
    float* __restrict__ C, int M, int N, int K) {
    extern __shared__ __align__(16) unsigned char smraw[];
    const unsigned sbase = smem_u32(smraw);

    const int tid = threadIdx.x;
    const int wid = tid >> 5, lane = tid & 31;
    const int warp_m = wid >> 2;   // 0..1
    const int warp_n = wid & 3;    // 0..3
    const int m0 = blockIdx.y << 7;
    const int n0 = blockIdx.x << 8;

    const __half* srcA = A + (size_t)m0 * K;
    const __half* srcW = Whi + (size_t)n0 * K;

    float acc[4][8][4];
#pragma unroll
    for (int i = 0; i < 4; i++)
#pragma unroll
        for (int j = 0; j < 8; j++)
#pragma unroll
            for (int u = 0; u < 4; u++) acc[i][j][u] = 0.f;

    auto prefetch = [&](int it, int bufi) {
        const int k0 = it * 32;
        const unsigned bufbase = sbase + (unsigned)bufi * GSTAGEF;
        // A plane: 128 rows x 4 chunks(16B) = 512 chunks
#pragma unroll
        for (int gg = 0; gg < 2; gg++) {
            const int g = tid + gg * 256;
            const int row = g >> 2, c = g & 3;
            const unsigned dst =
                bufbase + (unsigned)row * 64u +
                (unsigned)((c ^ ((row >> 1) & 3)) << 4);
            cp16(dst, srcA + (size_t)row * K + k0 + c * 8);
        }
        // W plane: 256 rows x 4 chunks = 1024 chunks
#pragma unroll
        for (int gg = 0; gg < 4; gg++) {
            const int g = tid + gg * 256;
            const int row = g >> 2, c = g & 3;
            const unsigned dst =
                bufbase + 8192u + (unsigned)row * 64u +
                (unsigned)((c ^ ((row >> 1) & 3)) << 4);
            cp16(dst, srcW + (size_t)row * K + k0 + c * 8);
        }
    };

    auto compute = [&](int bufi) {
        const unsigned base = sbase + (unsigned)bufi * GSTAGEF;
        const int arow = (lane & 7) + ((lane >> 3) & 1) * 8;
        const int khalf = (lane >> 4) & 1;
#pragma unroll
        for (int ks = 0; ks < 2; ks++) {
            const int c = ks * 2 + khalf;
            // B fragments: 8 x n8 (64 cols), 4 ldsm
            unsigned bh[8][2];
#pragma unroll
            for (int half = 0; half < 4; half++) {
                const int row = warp_n * 64 + half * 16 + arow;
                const unsigned off =
                    row * 64u + (unsigned)((c ^ ((row >> 1) & 3)) << 4);
                unsigned t[4];
                ldsm4(t, base + 8192u + off);
                bh[half * 2 + 0][0] = t[0]; bh[half * 2 + 0][1] = t[2];
                bh[half * 2 + 1][0] = t[1]; bh[half * 2 + 1][1] = t[3];
            }
#pragma unroll
            for (int i = 0; i < 4; i++) {
                const int row = warp_m * 64 + i * 16 + arow;
                const unsigned off =
                    row * 64u + (unsigned)((c ^ ((row >> 1) & 3)) << 4);
                unsigned ah[4];
                ldsm4(ah, base + off);
#pragma unroll
                for (int j = 0; j < 8; j++) mma16816h(acc[i][j], ah, bh[j]);
            }
        }
    };

    const int NIT = K >> 5;
    prefetch(0, 0);
    asm volatile("cp.async.commit_group;\n" ::: "memory");
    prefetch(1, 1);
    asm volatile("cp.async.commit_group;\n" ::: "memory");

    for (int it = 0; it < NIT; it++) {
        if (it + 1 < NIT) {
            asm volatile("cp.async.wait_group 1;\n" ::: "memory");
        } else {
            asm volatile("cp.async.wait_group 0;\n" ::: "memory");
        }
        __syncthreads();
        if (it + 2 < NIT) {
            prefetch(it + 2, (it + 2) % 3);
            asm volatile("cp.async.commit_group;\n" ::: "memory");
        }
        compute(it % 3);
    }

#pragma unroll
    for (int i = 0; i < 4; i++)
#pragma unroll
        for (int j = 0; j < 8; j++) {
            const int r0 = m0 + warp_m * 64 + i * 16 + (lane >> 2);
            const int cc = n0 + warp_n * 64 + j * 8 + (lane & 3) * 2;
            float2 u;
            u.x = acc[i][j][0]; u.y = acc[i][j][1];
            *(float2*)(C + (size_t)r0 * N + cc) = u;
            u.x = acc[i][j][2]; u.y = acc[i][j][3];
            *(float2*)(C + (size_t)(r0 + 8) * N + cc) = u;
        }
}

// ---------------- RoPE -> fp16 (Q scaled 0.125) ----------------
__global__ void rope16_kernel(
    const float* __restrict__ q, const float* __restrict__ k,
    __half* __restrict__ qa, __half* __restrict__ ka) {
    const int idx = blockIdx.x * 256 + threadIdx.x;
    const int total = M_ROWS * 40 * 32;
    if (idx >= total) return;
    const int p = idx & 31;
    const int rest = idx >> 5;
    const int head = rest % 40;
    const int m = rest / 40;
    const int s = m & (S_LEN - 1);

    const float invf = exp2f(-(float)p * 0.41524101186092027f);
    const float ang = (float)s * invf;
    float sn, c;
    sincosf(ang, &sn, &c);

    float x1, x2, scale;
    size_t o;
    __half* d;
    if (head < 32) {
        o = (size_t)m * 2048 + head * 64;
        x1 = q[o + p]; x2 = q[o + p + 32];
        scale = 0.125f; d = qa;
    } else {
        o = (size_t)m * 512 + (head - 32) * 64;
        x1 = k[o + p]; x2 = k[o + p + 32];
        scale = 1.0f; d = ka;
    }
    d[o + p]      = __float2half_rn((x1 * c - x2 * sn) * scale);
    d[o + p + 32] = __float2half_rn((x2 * c + x1 * sn) * scale);
}

// ---------------- tensor-core windowed attention (fp16) — unchanged -------
__global__ __launch_bounds__(256) void attn_tc(
    const __half* __restrict__ q_, const __half* __restrict__ k_,
    const __half* __restrict__ v_, __half* __restrict__ oatt) {
    extern __shared__ __align__(16) unsigned char smraw[];
    const unsigned SB = smem_u32(smraw);
    const unsigned QS = SB;
    const unsigned KS = SB + 18432u;
    const unsigned VS = SB + 27648u;

    const int tid = threadIdx.x, lane = tid & 31, w = tid >> 5;
    const int t128 = blockIdx.x;
    const int h = blockIdx.y;
    const int z = blockIdx.z;
    const int b = z >> 4, n = z & 15;
    const int kvh = h >> 2;

    {
        const size_t qrow0 = (size_t)(b * S_LEN + n * 256 + t128 * 128);
        for (int g = tid; g < 1024; g += 256) {
            const int r = g >> 3, c8 = g & 7;
            cp16(QS + (unsigned)r * 144u + (unsigned)c8 * 16u,
                 q_ + (qrow0 + r) * 2048 + h * 64 + c8 * 8);
        }
        asm volatile("cp.async.commit_group;\n" ::: "memory");
        asm volatile("cp.async.wait_group 0;\n" ::: "memory");
        __syncthreads();
    }

    unsigned qf[4][4];
    {
        const unsigned rr = (unsigned)(w * 16 + (lane & 15));
        const unsigned cb = (unsigned)((lane >> 4) * 16);
#pragma unroll
        for (int ks = 0; ks < 4; ks++)
            ldsm4(qf[ks], QS + rr * 144u + (unsigned)ks * 32u + cb);
    }

    float oacc[8][4];
#pragma unroll
    for (int j = 0; j < 8; j++)
#pragma unroll
        for (int u = 0; u < 4; u++) oacc[j][u] = 0.f;
    float m0 = -1e30f, m1 = -1e30f, l0 = 0.f, l1 = 0.f;

    const int rbase = t128 * 128 + w * 16 + (lane >> 2);
    int c_lo = 2 * t128;
    if (n == 0 && c_lo < 4) c_lo = 4;
    const int c_hi = (t128 == 0) ? 5 : 7;

    for (int c = c_lo; c <= c_hi; c++) {
        __syncthreads();
        {
            const size_t srow0 = (size_t)(b * S_LEN + (n - 1) * 256 + c * 64);
            for (int g = tid; g < 1024; g += 256) {
                const int p = g >> 9, r = (g >> 3) & 63, c8 = g & 7;
                const __half* sp = p ? v_ : k_;
                cp16((p ? VS : KS) + (unsigned)r * 144u + (unsigned)c8 * 16u,
                     sp + (srow0 + r) * 512 + kvh * 64 + c8 * 8);
            }
            asm volatile("cp.async.commit_group;\n" ::: "memory");
            asm volatile("cp.async.wait_group 0;\n" ::: "memory");
            __syncthreads();
        }

        float sf[8][4];
#pragma unroll
        for (int j = 0; j < 8; j++)
#pragma unroll
            for (int u = 0; u < 4; u++) sf[j][u] = 0.f;

        const unsigned kb = (unsigned)((lane >> 4) * 16);
#pragma unroll
        for (int ks = 0; ks < 4; ks++) {
#pragma unroll
            for (int kg = 0; kg < 4; kg++) {
                const unsigned off = (unsigned)(kg * 16 + (lane & 15)) * 144u +
                                     (unsigned)ks * 32u + kb;
                unsigned th[4];
                ldsm4(th, KS + off);
                unsigned bh0[2] = {th[0], th[2]}, bh1[2] = {th[1], th[3]};
                mma16816h(sf[2 * kg],     qf[ks], bh0);
                mma16816h(sf[2 * kg + 1], qf[ks], bh1);
            }
        }

        const int jb = c * 64 + (lane & 3) * 2;
        const float NEG = -1e30f;
#pragma unroll
        for (int j8 = 0; j8 < 8; j8++) {
            const int j0 = jb + j8 * 8;
            if (j0 < rbase     || j0 > rbase + 256) sf[j8][0] = NEG;
            if (j0 + 1 < rbase || j0 + 1 > rbase + 256) sf[j8][1] = NEG;
            if (j0 < rbase + 8 || j0 > rbase + 264) sf[j8][2] = NEG;
            if (j0 + 1 < rbase + 8 || j0 + 1 > rbase + 264) sf[j8][3] = NEG;
        }
        float mx0 = NEG, mx1 = NEG;
#pragma unroll
        for (int j8 = 0; j8 < 8; j8++) {
            mx0 = fmaxf(mx0, fmaxf(sf[j8][0], sf[j8][1]));
            mx1 = fmaxf(mx1, fmaxf(sf[j8][2], sf[j8][3]));
        }
        mx0 = fmaxf(mx0, __shfl_xor_sync(0xffffffffu, mx0, 1));
        mx0 = fmaxf(mx0, __shfl_xor_sync(0xffffffffu, mx0, 2));
        mx1 = fmaxf(mx1, __shfl_xor_sync(0xffffffffu, mx1, 1));
        mx1 = fmaxf(mx1, __shfl_xor_sync(0xffffffffu, mx1, 2));
        const float mn0 = fmaxf(m0, mx0), mn1 = fmaxf(m1, mx1);
        const float a0 = fexp(m0 - mn0), a1 = fexp(m1 - mn1);
        m0 = mn0; m1 = mn1;
        float s0 = 0.f, s1 = 0.f;
#pragma unroll
        for (int j8 = 0; j8 < 8; j8++) {
            sf[j8][0] = fexp(sf[j8][0] - mn0);
            sf[j8][1] = fexp(sf[j8][1] - mn0);
            sf[j8][2] = fexp(sf[j8][2] - mn1);
            sf[j8][3] = fexp(sf[j8][3] - mn1);
            s0 += sf[j8][0] + sf[j8][1];
            s1 += sf[j8][2] + sf[j8][3];
        }
        s0 += __shfl_xor_sync(0xffffffffu, s0, 1);
        s0 += __shfl_xor_sync(0xffffffffu, s0, 2);
        s1 += __shfl_xor_sync(0xffffffffu, s1, 1);
        s1 += __shfl_xor_sync(0xffffffffu, s1, 2);
        l0 = l0 * a0 + s0;
        l1 = l1 * a1 + s1;
#pragma unroll
        for (int j = 0; j < 8; j++) {
            oacc[j][0] *= a0; oacc[j][1] *= a0;
            oacc[j][2] *= a1; oacc[j][3] *= a1;
        }

#pragma unroll
        for (int kg = 0; kg < 4; kg++) {
            unsigned pa[4];
            pa[0] = pack_h16(sf[2 * kg][0],     sf[2 * kg][1]);
            pa[1] = pack_h16(sf[2 * kg][2],     sf[2 * kg][3]);
            pa[2] = pack_h16(sf[2 * kg + 1][0], sf[2 * kg + 1][1]);
            pa[3] = pack_h16(sf[2 * kg + 1][2], sf[2 * kg + 1][3]);
            const unsigned vrow =
                (unsigned)(kg * 16 + ((lane >> 3) & 1) * 8 + (lane & 7)) * 144u;
#pragma unroll
            for (int dh = 0; dh < 4; dh++) {
                const unsigned voff =
                    vrow + (unsigned)dh * 32u + (unsigned)(lane >> 4) * 16u;
                unsigned vh4[4];
                ldsm4t(vh4, VS + voff);
                unsigned vb0[2] = {vh4[0], vh4[1]}, vb1[2] = {vh4[2], vh4[3]};
                mma16816h(oacc[2 * dh],     pa, vb0);
                mma16816h(oacc[2 * dh + 1], pa, vb1);
            }
        }
    }

    const float inv0 = 1.f / l0, inv1 = 1.f / l1;
    const size_t grow0 =
        (size_t)(b * S_LEN + n * 256 + t128 * 128 + w * 16 + (lane >> 2));
    const int colb = h * 64 + (lane & 3) * 2;
#pragma unroll
    for (int j8 = 0; j8 < 8; j8++) {
        const unsigned u0 = pack_h16(oacc[j8][0] * inv0, oacc[j8][1] * inv0);
        const unsigned u1 = pack_h16(oacc[j8][2] * inv1, oacc[j8][3] * inv1);
        const size_t i0 = grow0 * 2048 + colb + j8 * 8;
        const size_t i1 = i0 + 8 * 2048;
        *(unsigned*)(oatt + i0) = u0;
        *(unsigned*)(oatt + i1) = u1;
    }
}

// ---------------- launch ----------------
extern "C" void kernel_launch(void* const* d_in, const int* in_sizes, int n_in,
                              void* d_out, int out_size) {
    const float* hs = (const float*)d_in[0];
    const float* Wq = (const float*)d_in[1];
    const float* Wk = (const float*)d_in[2];
    const float* Wv = (const float*)d_in[3];
    const float* Wo = (const float*)d_in[4];
    float* out = (float*)d_out;

    float *q, *k, *v;
    __half *hs16, *wq16, *wk16, *wv16, *wo16, *att16, *qa16, *ka16, *va16;
    cudaGetSymbolAddress((void**)&q, g_q);
    cudaGetSymbolAddress((void**)&k, g_k);
    cudaGetSymbolAddress((void**)&v, g_v);
    cudaGetSymbolAddress((void**)&hs16, g_hs16);
    cudaGetSymbolAddress((void**)&wq16, g_wq16);
    cudaGetSymbolAddress((void**)&wk16, g_wk16);
    cudaGetSymbolAddress((void**)&wv16, g_wv16);
    cudaGetSymbolAddress((void**)&wo16, g_wo16);
    cudaGetSymbolAddress((void**)&att16, g_att16);
    cudaGetSymbolAddress((void**)&qa16, g_qa16);
    cudaGetSymbolAddress((void**)&ka16, g_ka16);
    cudaGetSymbolAddress((void**)&va16, g_va16);

    cudaFuncSetAttribute(gemm_f16,
                         cudaFuncAttributeMaxDynamicSharedMemorySize, 73728);
    cudaFuncSetAttribute(attn_tc,
                         cudaFuncAttributeMaxDynamicSharedMemorySize, 36864);

    // launches 0-2, then gemmQ at #4 overall (ncu capture slot)
    cvt16_kernel<<<(M_ROWS * 2048 / 4 + 255) / 256, 256>>>(hs, hs16, M_ROWS * 2048 / 4);
    cvt16_kernel<<<(2048 * 2048 / 4 + 255) / 256, 256>>>(Wq, wq16, 2048 * 2048 / 4);
    cvt16_kernel<<<(512 * 2048 / 4 + 255) / 256, 256>>>(Wk, wk16, 512 * 2048 / 4);
    gemm_f16<<<dim3(2048 / 256, M_ROWS / 128), 256, 73728>>>(
        hs16, wq16, q, M_ROWS, 2048, 2048);
    gemm_f16<<<dim3(512 / 256, M_ROWS / 128), 256, 73728>>>(
        hs16, wk16, k, M_ROWS, 512, 2048);
    cvt16_kernel<<<(512 * 2048 / 4 + 255) / 256, 256>>>(Wv, wv16, 512 * 2048 / 4);
    gemm_f16<<<dim3(512 / 256, M_ROWS / 128), 256, 73728>>>(
        hs16, wv16, v, M_ROWS, 512, 2048);

    // RoPE -> fp16 Q/K; V -> fp16
    rope16_kernel<<<(M_ROWS * 40 * 32 + 255) / 256, 256>>>(q, k, qa16, ka16);
    cvt16_kernel<<<(M_ROWS * 512 / 4 + 255) / 256, 256>>>(v, va16, M_ROWS * 512 / 4);

    // fp16 tensor-core attention
    attn_tc<<<dim3(2, 32, 32), 256, 36864>>>(qa16, ka16, va16, att16);

    // Output projection
    cvt16_kernel<<<(2048 * 2048 / 4 + 255) / 256, 256>>>(Wo, wo16, 2048 * 2048 / 4);
    gemm_f16<<<dim3(2048 / 256, M_ROWS / 128), 256, 73728>>>(
        att16, wo16, out, M_ROWS, 2048, 2048);
}